// round 1
// baseline (speedup 1.0000x reference)
#include <cuda_runtime.h>

#define FULLMASK 0xffffffffu

#define KB 8
#define KH 8
#define KR 128
#define KC 128
#define KDQ 16
#define KMS 16

// scratch: score[B,H,R,C] (4 MB)
__device__ float g_score[KB * KH * KR * KC];

// ---------------------------------------------------------------------------
// Kernel 1: per (b,h): dps = gelu(q ks^T/4); w_self = softmax(dps);
// dpa = relu(q ka^T/4); score = (w_self @ dpa)/4
// grid = 64 blocks, 256 threads; dynamic smem 98816 B
// ---------------------------------------------------------------------------
__global__ __launch_bounds__(256) void k1_score(const float* __restrict__ q,
                                                const float* __restrict__ ks,
                                                const float* __restrict__ ka) {
    extern __shared__ float sm[];
    float* ksT  = sm;            // [16][132]
    float* kaT  = sm + 2112;     // [16][132]
    float* qrow = sm + 4224;     // [128*16]
    float* pbuf = sm + 6272;     // [8][128]
    float* dpa  = sm + 7296;     // [128][136]

    const int bh  = blockIdx.x;
    const int tid = threadIdx.x;
    const float* qb  = q  + bh * 2048;
    const float* ksb = ks + bh * 2048;
    const float* kab = ka + bh * 2048;

    for (int i = tid; i < 2048; i += 256) {
        int srow = i >> 4, e = i & 15;
        ksT[e * 132 + srow] = ksb[i];
        kaT[e * 132 + srow] = kab[i];
        qrow[i] = qb[i];
    }
    __syncthreads();

    const int w = tid >> 5, l = tid & 31;

    // Phase A: dpa[r][c] = relu(dot(q[r], ka[c]) * 0.25)
    for (int k = 0; k < 16; ++k) {
        int r = w * 16 + k;
        float qr[16];
#pragma unroll
        for (int j = 0; j < 4; ++j) {
            float4 v4 = *(const float4*)&qrow[r * 16 + 4 * j];
            qr[4 * j + 0] = v4.x; qr[4 * j + 1] = v4.y;
            qr[4 * j + 2] = v4.z; qr[4 * j + 3] = v4.w;
        }
        float a0 = 0.f, a1 = 0.f, a2 = 0.f, a3 = 0.f;
#pragma unroll
        for (int e = 0; e < 16; ++e) {
            float4 kk = *(const float4*)&kaT[e * 132 + 4 * l];
            a0 = fmaf(qr[e], kk.x, a0); a1 = fmaf(qr[e], kk.y, a1);
            a2 = fmaf(qr[e], kk.z, a2); a3 = fmaf(qr[e], kk.w, a3);
        }
        float4 o;
        o.x = fmaxf(a0 * 0.25f, 0.f); o.y = fmaxf(a1 * 0.25f, 0.f);
        o.z = fmaxf(a2 * 0.25f, 0.f); o.w = fmaxf(a3 * 0.25f, 0.f);
        *(float4*)&dpa[r * 136 + 4 * l] = o;
    }
    __syncthreads();

    // Phase B: dps row -> gelu -> softmax -> score row
    for (int k = 0; k < 16; ++k) {
        int r = w * 16 + k;
        float qr[16];
#pragma unroll
        for (int j = 0; j < 4; ++j) {
            float4 v4 = *(const float4*)&qrow[r * 16 + 4 * j];
            qr[4 * j + 0] = v4.x; qr[4 * j + 1] = v4.y;
            qr[4 * j + 2] = v4.z; qr[4 * j + 3] = v4.w;
        }
        float a0 = 0.f, a1 = 0.f, a2 = 0.f, a3 = 0.f;
#pragma unroll
        for (int e = 0; e < 16; ++e) {
            float4 kk = *(const float4*)&ksT[e * 132 + 4 * l];
            a0 = fmaf(qr[e], kk.x, a0); a1 = fmaf(qr[e], kk.y, a1);
            a2 = fmaf(qr[e], kk.z, a2); a3 = fmaf(qr[e], kk.w, a3);
        }
        // exact GELU on qk/4
        float x0 = a0 * 0.25f, x1 = a1 * 0.25f, x2 = a2 * 0.25f, x3 = a3 * 0.25f;
        a0 = x0 * normcdff(x0); a1 = x1 * normcdff(x1);
        a2 = x2 * normcdff(x2); a3 = x3 * normcdff(x3);
        // softmax over 128 (4 per lane)
        float mx = fmaxf(fmaxf(a0, a1), fmaxf(a2, a3));
#pragma unroll
        for (int o = 16; o; o >>= 1) mx = fmaxf(mx, __shfl_xor_sync(FULLMASK, mx, o));
        float p0 = __expf(a0 - mx), p1 = __expf(a1 - mx);
        float p2 = __expf(a2 - mx), p3 = __expf(a3 - mx);
        float ssum = p0 + p1 + p2 + p3;
#pragma unroll
        for (int o = 16; o; o >>= 1) ssum += __shfl_xor_sync(FULLMASK, ssum, o);
        float inv = 1.f / ssum;
        float4 pv = make_float4(p0 * inv, p1 * inv, p2 * inv, p3 * inv);
        *(float4*)&pbuf[w * 128 + 4 * l] = pv;
        __syncwarp();
        // score row = p @ dpa, scaled by 0.25
        float c0 = 0.f, c1 = 0.f, c2 = 0.f, c3 = 0.f;
#pragma unroll 4
        for (int s2 = 0; s2 < 128; ++s2) {
            float pvv = pbuf[w * 128 + s2];
            float4 dv = *(const float4*)&dpa[s2 * 136 + 4 * l];
            c0 = fmaf(pvv, dv.x, c0); c1 = fmaf(pvv, dv.y, c1);
            c2 = fmaf(pvv, dv.z, c2); c3 = fmaf(pvv, dv.w, c3);
        }
        float4 so = make_float4(c0 * 0.25f, c1 * 0.25f, c2 * 0.25f, c3 * 0.25f);
        *(float4*)&g_score[(bh * 128 + r) * 128 + 4 * l] = so;
        __syncwarp();
    }
}

// ---------------------------------------------------------------------------
// Kernel 2: per (b,r): fused mix1 / depth-attention / LN / edge / mixed-attn.
// grid = 1024 blocks, 256 threads; dynamic smem 49988 B
// ---------------------------------------------------------------------------
__global__ __launch_bounds__(256) void k2_main(
    const float* __restrict__ cost_mat,
    const float* __restrict__ mix1_w, const float* __restrict__ mix1_b,
    const float* __restrict__ Waa,
    const float* __restrict__ mix2_w, const float* __restrict__ mix2_b,
    const float* __restrict__ edge_w, const float* __restrict__ edge_b,
    const float* __restrict__ ln_g,  const float* __restrict__ ln_b,
    const float* __restrict__ v, float* __restrict__ out) {
    extern __shared__ float sm[];
    float* ms1T     = sm;           // [16][132]
    float* tmat     = sm + 2112;    // [128][17]
    float* aeT      = sm + 4288;    // [16][132]
    float* red      = sm + 6400;    // [8][32][20]
    float* waa      = sm + 11520;   // [16][16]
    float* w1a      = sm + 11776;   // [16]
    float* w1b      = sm + 11792;   // [16]
    float* b1s      = sm + 11808;   // [16]
    float* w2s      = sm + 11824;   // [16]
    float* ews      = sm + 11840;   // [16]
    float* costrow  = sm + 11856;   // [128]
    float* mixedrow = sm + 11984;   // [128]
    float* edge_acc = sm + 12112;   // [128]
    float* lng      = sm + 12240;   // [128]
    float* lnb      = sm + 12368;   // [128]
    float* b2s      = sm + 12496;   // [1]

    const int tid = threadIdx.x;
    const int br = blockIdx.x;
    const int b = br >> 7, r = br & 127;
    const int w = tid >> 5, l = tid & 31;

    if (tid < 128) {
        costrow[tid]  = cost_mat[br * 128 + tid];
        lng[tid]      = ln_g[tid];
        lnb[tid]      = ln_b[tid];
        edge_acc[tid] = 0.f;
    }

    for (int h = 0; h < KH; ++h) {
        waa[tid < 256 ? tid : 0] = Waa[h * 256 + (tid < 256 ? tid : 0)];
        if (tid < 16) {
            w1a[tid] = mix1_w[h * 32 + tid];
            w1b[tid] = mix1_w[h * 32 + 16 + tid];
            b1s[tid] = mix1_b[h * 16 + tid];
            w2s[tid] = mix2_w[h * 16 + tid];
            ews[tid] = edge_w[h * 16 + tid];
        }
        if (tid == 0) b2s[0] = mix2_b[h];
        __syncthreads();

        // ---- P1: ms1, t = ms1 @ Waa, mixed = ms1 @ w2 + b2 ----
        {
            int c = tid & 127, half = tid >> 7;
            float sc = g_score[((b * KH + h) * KR + r) * KC + c];
            float co = costrow[c];
            float m[16];
#pragma unroll
            for (int e = 0; e < 16; ++e)
                m[e] = fmaxf(fmaf(sc, w1a[e], fmaf(co, w1b[e], b1s[e])), 0.f);
            int e0 = half * 8;
#pragma unroll
            for (int e = 0; e < 8; ++e) ms1T[(e0 + e) * 132 + c] = m[e0 + e];
#pragma unroll
            for (int e = 0; e < 8; ++e) {
                float t = 0.f;
#pragma unroll
                for (int f = 0; f < 16; ++f) t = fmaf(m[f], waa[f * 16 + e0 + e], t);
                tmat[c * 17 + e0 + e] = t;
            }
            if (half == 0) {
                float mx = b2s[0];
#pragma unroll
                for (int f = 0; f < 16; ++f) mx = fmaf(m[f], w2s[f], mx);
                mixedrow[c] = mx;
            }
        }
        __syncthreads();

        // ---- P2: per-row dd = t @ ms1^T, softmax, ae = dw @ ms1 ----
        for (int k = 0; k < 16; ++k) {
            int c = w * 16 + k;
            float tr[16];
#pragma unroll
            for (int e = 0; e < 16; ++e) tr[e] = tmat[c * 17 + e];
            float a0 = 0.f, a1 = 0.f, a2 = 0.f, a3 = 0.f;
#pragma unroll
            for (int e = 0; e < 16; ++e) {
                float4 mm = *(const float4*)&ms1T[e * 132 + 4 * l];
                a0 = fmaf(tr[e], mm.x, a0); a1 = fmaf(tr[e], mm.y, a1);
                a2 = fmaf(tr[e], mm.z, a2); a3 = fmaf(tr[e], mm.w, a3);
            }
            float mx = fmaxf(fmaxf(a0, a1), fmaxf(a2, a3));
#pragma unroll
            for (int o = 16; o; o >>= 1) mx = fmaxf(mx, __shfl_xor_sync(FULLMASK, mx, o));
            float p0 = __expf(a0 - mx), p1 = __expf(a1 - mx);
            float p2 = __expf(a2 - mx), p3 = __expf(a3 - mx);
            float ssum = p0 + p1 + p2 + p3;
#pragma unroll
            for (int o = 16; o; o >>= 1) ssum += __shfl_xor_sync(FULLMASK, ssum, o);
            float inv = 1.f / ssum;
            float pa[16];
#pragma unroll
            for (int e = 0; e < 16; ++e) {
                float4 mm = *(const float4*)&ms1T[e * 132 + 4 * l];
                pa[e] = fmaf(p0, mm.x, fmaf(p1, mm.y, fmaf(p2, mm.z, p3 * mm.w)));
            }
            float* rbase = &red[(w * 32 + l) * 20];
            *(float4*)&rbase[0]  = make_float4(pa[0],  pa[1],  pa[2],  pa[3]);
            *(float4*)&rbase[4]  = make_float4(pa[4],  pa[5],  pa[6],  pa[7]);
            *(float4*)&rbase[8]  = make_float4(pa[8],  pa[9],  pa[10], pa[11]);
            *(float4*)&rbase[12] = make_float4(pa[12], pa[13], pa[14], pa[15]);
            __syncwarp();
            if (l < 16) {
                float t = 0.f;
#pragma unroll
                for (int j = 0; j < 32; ++j) t += red[(w * 32 + j) * 20 + l];
                aeT[l * 132 + c] = t * inv;   // residual (+ms1) added in LN
            }
            __syncwarp();
        }
        __syncthreads();

        // ---- P3: LayerNorm over C per feature e; warp w handles e=w, w+8 ----
#pragma unroll
        for (int ei = 0; ei < 2; ++ei) {
            int e = w + ei * 8;
            float x0 = aeT[e * 132 + l]      + ms1T[e * 132 + l];
            float x1 = aeT[e * 132 + l + 32] + ms1T[e * 132 + l + 32];
            float x2 = aeT[e * 132 + l + 64] + ms1T[e * 132 + l + 64];
            float x3 = aeT[e * 132 + l + 96] + ms1T[e * 132 + l + 96];
            float s1 = x0 + x1 + x2 + x3;
            float sq = x0 * x0 + x1 * x1 + x2 * x2 + x3 * x3;
#pragma unroll
            for (int o = 16; o; o >>= 1) {
                s1 += __shfl_xor_sync(FULLMASK, s1, o);
                sq += __shfl_xor_sync(FULLMASK, sq, o);
            }
            float mean = s1 * (1.f / 128.f);
            float var  = sq * (1.f / 128.f) - mean * mean;
            float rs = rsqrtf(var + 1e-5f);
            aeT[e * 132 + l]      = (x0 - mean) * rs * lng[l]      + lnb[l];
            aeT[e * 132 + l + 32] = (x1 - mean) * rs * lng[l + 32] + lnb[l + 32];
            aeT[e * 132 + l + 64] = (x2 - mean) * rs * lng[l + 64] + lnb[l + 64];
            aeT[e * 132 + l + 96] = (x3 - mean) * rs * lng[l + 96] + lnb[l + 96];
        }
        __syncthreads();

        // ---- P4: edge accumulation (warps 0-3) || mixed softmax-attn (warps 4-7)
        if (tid < 128) {
            int c = tid;
            float acc = edge_acc[c];
#pragma unroll
            for (int e = 0; e < 16; ++e) acc = fmaf(aeT[e * 132 + c], ews[e], acc);
            edge_acc[c] = acc;
        } else {
            int ww = w - 4;
            float m0 = mixedrow[l],      m1 = mixedrow[l + 32];
            float m2 = mixedrow[l + 64], m3 = mixedrow[l + 96];
            float mx = fmaxf(fmaxf(m0, m1), fmaxf(m2, m3));
#pragma unroll
            for (int o = 16; o; o >>= 1) mx = fmaxf(mx, __shfl_xor_sync(FULLMASK, mx, o));
            float p0 = __expf(m0 - mx), p1 = __expf(m1 - mx);
            float p2 = __expf(m2 - mx), p3 = __expf(m3 - mx);
            float ssum = p0 + p1 + p2 + p3;
#pragma unroll
            for (int o = 16; o; o >>= 1) ssum += __shfl_xor_sync(FULLMASK, ssum, o);
            float inv = 1.f / ssum;
            const float* vb = v + (b * KH + h) * KC * KDQ;
#pragma unroll
            for (int d = 0; d < 4; ++d) {
                int dq = ww * 4 + d;
                float a = p0 * vb[l * 16 + dq] + p1 * vb[(l + 32) * 16 + dq]
                        + p2 * vb[(l + 64) * 16 + dq] + p3 * vb[(l + 96) * 16 + dq];
#pragma unroll
                for (int o = 16; o; o >>= 1) a += __shfl_xor_sync(FULLMASK, a, o);
                if (l == 0)
                    out[(b * KR + r) * (KH * KDQ) + h * KDQ + dq] = a * inv;
            }
        }
        __syncthreads();
    }

    if (tid < 128)
        out[KB * KR * KH * KDQ + br * 128 + tid] = edge_acc[tid] + edge_b[0];
}

extern "C" void kernel_launch(void* const* d_in, const int* in_sizes, int n_in,
                              void* d_out, int out_size) {
    const float* q    = (const float*)d_in[0];
    const float* k_s  = (const float*)d_in[1];
    const float* k_a  = (const float*)d_in[2];
    const float* v    = (const float*)d_in[3];
    const float* cost = (const float*)d_in[4];
    const float* m1w  = (const float*)d_in[5];
    const float* m1b  = (const float*)d_in[6];
    const float* waa  = (const float*)d_in[7];
    const float* m2w  = (const float*)d_in[8];
    const float* m2b  = (const float*)d_in[9];
    const float* ew   = (const float*)d_in[10];
    const float* eb   = (const float*)d_in[11];
    const float* lng  = (const float*)d_in[12];
    const float* lnb  = (const float*)d_in[13];
    float* out = (float*)d_out;

    cudaFuncSetAttribute(k1_score, cudaFuncAttributeMaxDynamicSharedMemorySize, 98816);
    cudaFuncSetAttribute(k2_main,  cudaFuncAttributeMaxDynamicSharedMemorySize, 49988);

    k1_score<<<KB * KH, 256, 98816>>>(q, k_s, k_a);
    k2_main<<<KB * KR, 256, 49988>>>(cost, m1w, m1b, waa, m2w, m2b, ew, eb,
                                     lng, lnb, v, out);
}

// round 2
// speedup vs baseline: 1.3303x; 1.3303x over previous
#include <cuda_runtime.h>

#define FULLMASK 0xffffffffu

#define KB 8
#define KH 8
#define KR 128
#define KC 128
#define KDQ 16
#define KMS 16

// scratch: score[B,H,R,C] (4 MB)
__device__ float g_score[KB * KH * KR * KC];

// ---- packed f32x2 helpers (Blackwell) ----
__device__ __forceinline__ unsigned long long pk2(float x, float y) {
    unsigned long long r;
    asm("mov.b64 %0, {%1, %2};" : "=l"(r) : "f"(x), "f"(y));
    return r;
}
__device__ __forceinline__ float2 upk2(unsigned long long v) {
    float2 r;
    asm("mov.b64 {%0, %1}, %2;" : "=f"(r.x), "=f"(r.y) : "l"(v));
    return r;
}
__device__ __forceinline__ unsigned long long fma2(unsigned long long a,
                                                   unsigned long long b,
                                                   unsigned long long c) {
    unsigned long long d;
    asm("fma.rn.f32x2 %0, %1, %2, %3;" : "=l"(d) : "l"(a), "l"(b), "l"(c));
    return d;
}
__device__ __forceinline__ unsigned long long mul2(unsigned long long a,
                                                   unsigned long long b) {
    unsigned long long d;
    asm("mul.rn.f32x2 %0, %1, %2;" : "=l"(d) : "l"(a), "l"(b));
    return d;
}

// ---------------------------------------------------------------------------
// Kernel 1: per (b,h): dps = gelu(q ks^T/4); w_self = softmax(dps);
// dpa = relu(q ka^T/4); score = (w_self @ dpa)/4
// grid = 64 blocks, 256 threads; dynamic smem 98816 B
// ---------------------------------------------------------------------------
__global__ __launch_bounds__(256) void k1_score(const float* __restrict__ q,
                                                const float* __restrict__ ks,
                                                const float* __restrict__ ka) {
    extern __shared__ float sm[];
    float* ksT  = sm;            // [16][132]
    float* kaT  = sm + 2112;     // [16][132]
    float* qrow = sm + 4224;     // [128*16]
    float* pbuf = sm + 6272;     // [8][128]
    float* dpa  = sm + 7296;     // [128][136]

    const int bh  = blockIdx.x;
    const int tid = threadIdx.x;
    const float* qb  = q  + bh * 2048;
    const float* ksb = ks + bh * 2048;
    const float* kab = ka + bh * 2048;

    for (int i = tid; i < 2048; i += 256) {
        int srow = i >> 4, e = i & 15;
        ksT[e * 132 + srow] = ksb[i];
        kaT[e * 132 + srow] = kab[i];
        qrow[i] = qb[i];
    }
    __syncthreads();

    const int w = tid >> 5, l = tid & 31;

    // Phase A: dpa[r][c] = relu(dot(q[r], ka[c]) * 0.25)
    for (int k = 0; k < 16; ++k) {
        int r = w * 16 + k;
        float qr[16];
#pragma unroll
        for (int j = 0; j < 4; ++j) {
            float4 v4 = *(const float4*)&qrow[r * 16 + 4 * j];
            qr[4 * j + 0] = v4.x; qr[4 * j + 1] = v4.y;
            qr[4 * j + 2] = v4.z; qr[4 * j + 3] = v4.w;
        }
        float a0 = 0.f, a1 = 0.f, a2 = 0.f, a3 = 0.f;
#pragma unroll
        for (int e = 0; e < 16; ++e) {
            float4 kk = *(const float4*)&kaT[e * 132 + 4 * l];
            a0 = fmaf(qr[e], kk.x, a0); a1 = fmaf(qr[e], kk.y, a1);
            a2 = fmaf(qr[e], kk.z, a2); a3 = fmaf(qr[e], kk.w, a3);
        }
        float4 o;
        o.x = fmaxf(a0 * 0.25f, 0.f); o.y = fmaxf(a1 * 0.25f, 0.f);
        o.z = fmaxf(a2 * 0.25f, 0.f); o.w = fmaxf(a3 * 0.25f, 0.f);
        *(float4*)&dpa[r * 136 + 4 * l] = o;
    }
    __syncthreads();

    // Phase B: dps row -> gelu -> softmax -> score row
    for (int k = 0; k < 16; ++k) {
        int r = w * 16 + k;
        float qr[16];
#pragma unroll
        for (int j = 0; j < 4; ++j) {
            float4 v4 = *(const float4*)&qrow[r * 16 + 4 * j];
            qr[4 * j + 0] = v4.x; qr[4 * j + 1] = v4.y;
            qr[4 * j + 2] = v4.z; qr[4 * j + 3] = v4.w;
        }
        float a0 = 0.f, a1 = 0.f, a2 = 0.f, a3 = 0.f;
#pragma unroll
        for (int e = 0; e < 16; ++e) {
            float4 kk = *(const float4*)&ksT[e * 132 + 4 * l];
            a0 = fmaf(qr[e], kk.x, a0); a1 = fmaf(qr[e], kk.y, a1);
            a2 = fmaf(qr[e], kk.z, a2); a3 = fmaf(qr[e], kk.w, a3);
        }
        // exact GELU on qk/4
        float x0 = a0 * 0.25f, x1 = a1 * 0.25f, x2 = a2 * 0.25f, x3 = a3 * 0.25f;
        a0 = x0 * normcdff(x0); a1 = x1 * normcdff(x1);
        a2 = x2 * normcdff(x2); a3 = x3 * normcdff(x3);
        // softmax over 128 (4 per lane)
        float mx = fmaxf(fmaxf(a0, a1), fmaxf(a2, a3));
#pragma unroll
        for (int o = 16; o; o >>= 1) mx = fmaxf(mx, __shfl_xor_sync(FULLMASK, mx, o));
        float p0 = __expf(a0 - mx), p1 = __expf(a1 - mx);
        float p2 = __expf(a2 - mx), p3 = __expf(a3 - mx);
        float ssum = p0 + p1 + p2 + p3;
#pragma unroll
        for (int o = 16; o; o >>= 1) ssum += __shfl_xor_sync(FULLMASK, ssum, o);
        float inv = 1.f / ssum;
        float4 pv = make_float4(p0 * inv, p1 * inv, p2 * inv, p3 * inv);
        *(float4*)&pbuf[w * 128 + 4 * l] = pv;
        __syncwarp();
        // score row = p @ dpa, scaled by 0.25
        float c0 = 0.f, c1 = 0.f, c2 = 0.f, c3 = 0.f;
#pragma unroll 4
        for (int s2 = 0; s2 < 128; ++s2) {
            float pvv = pbuf[w * 128 + s2];
            float4 dv = *(const float4*)&dpa[s2 * 136 + 4 * l];
            c0 = fmaf(pvv, dv.x, c0); c1 = fmaf(pvv, dv.y, c1);
            c2 = fmaf(pvv, dv.z, c2); c3 = fmaf(pvv, dv.w, c3);
        }
        float4 so = make_float4(c0 * 0.25f, c1 * 0.25f, c2 * 0.25f, c3 * 0.25f);
        *(float4*)&g_score[(bh * 128 + r) * 128 + 4 * l] = so;
        __syncwarp();
    }
}

// ---------------------------------------------------------------------------
// Kernel 2: per (b,r): fused mix1 / depth-attention / LN / edge / mixed-attn.
// grid = 1024 blocks, 256 threads; dynamic smem 29568 B
// ---------------------------------------------------------------------------
__global__ __launch_bounds__(256, 2) void k2_main(
    const float* __restrict__ cost_mat,
    const float* __restrict__ mix1_w, const float* __restrict__ mix1_b,
    const float* __restrict__ Waa,
    const float* __restrict__ mix2_w, const float* __restrict__ mix2_b,
    const float* __restrict__ edge_w, const float* __restrict__ edge_b,
    const float* __restrict__ ln_g,  const float* __restrict__ ln_b,
    const float* __restrict__ v, float* __restrict__ out) {
    extern __shared__ float sm[];
    float* ms1T     = sm;           // [16][132]
    float* tmat     = sm + 2112;    // [128][17]
    float* aeT      = sm + 4288;    // [16][132]
    float* waa      = sm + 6400;    // [16][16]
    float* w1a      = sm + 6656;    // [16]
    float* w1b      = sm + 6672;    // [16]
    float* b1s      = sm + 6688;    // [16]
    float* w2s      = sm + 6704;    // [16]
    float* ews      = sm + 6720;    // [16]
    float* costrow  = sm + 6736;    // [128]
    float* mixedrow = sm + 6864;    // [128]
    float* edge_acc = sm + 6992;    // [128]
    float* lng      = sm + 7120;    // [128]
    float* lnb      = sm + 7248;    // [128]
    float* b2s      = sm + 7376;    // [1]

    const int tid = threadIdx.x;
    const int br = blockIdx.x;
    const int b = br >> 7, r = br & 127;
    const int w = tid >> 5, l = tid & 31;

    if (tid < 128) {
        costrow[tid]  = cost_mat[br * 128 + tid];
        lng[tid]      = ln_g[tid];
        lnb[tid]      = ln_b[tid];
        edge_acc[tid] = 0.f;
    }

    for (int h = 0; h < KH; ++h) {
        waa[tid & 255] = Waa[h * 256 + (tid & 255)];
        if (tid < 16) {
            w1a[tid] = mix1_w[h * 32 + tid];
            w1b[tid] = mix1_w[h * 32 + 16 + tid];
            b1s[tid] = mix1_b[h * 16 + tid];
            w2s[tid] = mix2_w[h * 16 + tid];
            ews[tid] = edge_w[h * 16 + tid];
        }
        if (tid == 0) b2s[0] = mix2_b[h];
        __syncthreads();

        // ---- P1: ms1, t = ms1 @ Waa, mixed = ms1 @ w2 + b2 ----
        {
            int c = tid & 127, half = tid >> 7;
            float sc = g_score[((b * KH + h) * KR + r) * KC + c];
            float co = costrow[c];
            float m[16];
#pragma unroll
            for (int e = 0; e < 16; ++e)
                m[e] = fmaxf(fmaf(sc, w1a[e], fmaf(co, w1b[e], b1s[e])), 0.f);
            int e0 = half * 8;
#pragma unroll
            for (int e = 0; e < 8; ++e) ms1T[(e0 + e) * 132 + c] = m[e0 + e];
#pragma unroll
            for (int e = 0; e < 8; ++e) {
                float t = 0.f;
#pragma unroll
                for (int f = 0; f < 16; ++f) t = fmaf(m[f], waa[f * 16 + e0 + e], t);
                tmat[c * 17 + e0 + e] = t;
            }
            if (half == 0) {
                float mx = b2s[0];
#pragma unroll
                for (int f = 0; f < 16; ++f) mx = fmaf(m[f], w2s[f], mx);
                mixedrow[c] = mx;
            }
        }
        __syncthreads();

        // ---- P2: per-row dd = t @ ms1^T, softmax, ae = dw @ ms1 ----
        // Register-cache ms1 (each lane's 4 columns are fixed for all rows).
        unsigned long long mc01[16], mc23[16];
#pragma unroll
        for (int e = 0; e < 16; ++e) {
            float4 m4 = *(const float4*)&ms1T[e * 132 + 4 * l];
            mc01[e] = pk2(m4.x, m4.y);
            mc23[e] = pk2(m4.z, m4.w);
        }

        for (int k = 0; k < 16; ++k) {
            int c = w * 16 + k;
            unsigned long long a01 = 0ull, a23 = 0ull;
#pragma unroll
            for (int e = 0; e < 16; ++e) {
                float t = tmat[c * 17 + e];
                unsigned long long t2 = pk2(t, t);
                a01 = fma2(t2, mc01[e], a01);
                a23 = fma2(t2, mc23[e], a23);
            }
            float2 f01 = upk2(a01), f23 = upk2(a23);
            float a0 = f01.x, a1 = f01.y, a2 = f23.x, a3 = f23.y;

            float mx = fmaxf(fmaxf(a0, a1), fmaxf(a2, a3));
#pragma unroll
            for (int o = 16; o; o >>= 1) mx = fmaxf(mx, __shfl_xor_sync(FULLMASK, mx, o));
            float p0 = __expf(a0 - mx), p1 = __expf(a1 - mx);
            float p2 = __expf(a2 - mx), p3 = __expf(a3 - mx);
            float ssum = p0 + p1 + p2 + p3;
#pragma unroll
            for (int o = 16; o; o >>= 1) ssum += __shfl_xor_sync(FULLMASK, ssum, o);
            float inv = 1.f / ssum;
            unsigned long long p01 = pk2(p0, p1), p23 = pk2(p2, p3);

            // per-lane partial of ae row c: v[e] = sum over this lane's 4 cols
            float vv[16];
#pragma unroll
            for (int e = 0; e < 16; ++e) {
                unsigned long long s2 = fma2(p23, mc23[e], mul2(p01, mc01[e]));
                float2 sf = upk2(s2);
                vv[e] = sf.x + sf.y;
            }

            // shuffle tree: reduce 16 values across 32 lanes via feature split
            {
                bool hi = (l & 16);
#pragma unroll
                for (int i = 0; i < 8; ++i) {
                    float send = hi ? vv[i] : vv[i + 8];
                    float recv = __shfl_xor_sync(FULLMASK, send, 16);
                    vv[i] = (hi ? vv[i + 8] : vv[i]) + recv;
                }
                hi = (l & 8);
#pragma unroll
                for (int i = 0; i < 4; ++i) {
                    float send = hi ? vv[i] : vv[i + 4];
                    float recv = __shfl_xor_sync(FULLMASK, send, 8);
                    vv[i] = (hi ? vv[i + 4] : vv[i]) + recv;
                }
                hi = (l & 4);
#pragma unroll
                for (int i = 0; i < 2; ++i) {
                    float send = hi ? vv[i] : vv[i + 2];
                    float recv = __shfl_xor_sync(FULLMASK, send, 4);
                    vv[i] = (hi ? vv[i + 2] : vv[i]) + recv;
                }
                hi = (l & 2);
                {
                    float send = hi ? vv[0] : vv[1];
                    float recv = __shfl_xor_sync(FULLMASK, send, 2);
                    vv[0] = (hi ? vv[1] : vv[0]) + recv;
                }
                vv[0] += __shfl_xor_sync(FULLMASK, vv[0], 1);
            }
            int f = (l >> 1) & 15;
            if (!(l & 1)) aeT[f * 132 + c] = vv[0] * inv;  // residual added in P3
        }
        __syncthreads();

        // ---- P3: LayerNorm over C per feature e; warp w handles e=w, w+8 ----
#pragma unroll
        for (int ei = 0; ei < 2; ++ei) {
            int e = w + ei * 8;
            float x0 = aeT[e * 132 + l]      + ms1T[e * 132 + l];
            float x1 = aeT[e * 132 + l + 32] + ms1T[e * 132 + l + 32];
            float x2 = aeT[e * 132 + l + 64] + ms1T[e * 132 + l + 64];
            float x3 = aeT[e * 132 + l + 96] + ms1T[e * 132 + l + 96];
            float s1 = x0 + x1 + x2 + x3;
            float sq = x0 * x0 + x1 * x1 + x2 * x2 + x3 * x3;
#pragma unroll
            for (int o = 16; o; o >>= 1) {
                s1 += __shfl_xor_sync(FULLMASK, s1, o);
                sq += __shfl_xor_sync(FULLMASK, sq, o);
            }
            float mean = s1 * (1.f / 128.f);
            float var  = sq * (1.f / 128.f) - mean * mean;
            float rs = rsqrtf(var + 1e-5f);
            aeT[e * 132 + l]      = (x0 - mean) * rs * lng[l]      + lnb[l];
            aeT[e * 132 + l + 32] = (x1 - mean) * rs * lng[l + 32] + lnb[l + 32];
            aeT[e * 132 + l + 64] = (x2 - mean) * rs * lng[l + 64] + lnb[l + 64];
            aeT[e * 132 + l + 96] = (x3 - mean) * rs * lng[l + 96] + lnb[l + 96];
        }
        __syncthreads();

        // ---- P4: edge accumulation (warps 0-3) || mixed softmax-attn (warps 4-7)
        if (tid < 128) {
            int c = tid;
            float acc = edge_acc[c];
#pragma unroll
            for (int e = 0; e < 16; ++e) acc = fmaf(aeT[e * 132 + c], ews[e], acc);
            edge_acc[c] = acc;
        } else {
            int ww = w - 4;
            float m0 = mixedrow[l],      m1 = mixedrow[l + 32];
            float m2 = mixedrow[l + 64], m3 = mixedrow[l + 96];
            float mx = fmaxf(fmaxf(m0, m1), fmaxf(m2, m3));
#pragma unroll
            for (int o = 16; o; o >>= 1) mx = fmaxf(mx, __shfl_xor_sync(FULLMASK, mx, o));
            float p0 = __expf(m0 - mx), p1 = __expf(m1 - mx);
            float p2 = __expf(m2 - mx), p3 = __expf(m3 - mx);
            float ssum = p0 + p1 + p2 + p3;
#pragma unroll
            for (int o = 16; o; o >>= 1) ssum += __shfl_xor_sync(FULLMASK, ssum, o);
            float inv = 1.f / ssum;
            const float* vb = v + (b * KH + h) * KC * KDQ;
#pragma unroll
            for (int d = 0; d < 4; ++d) {
                int dq = ww * 4 + d;
                float a = p0 * vb[l * 16 + dq] + p1 * vb[(l + 32) * 16 + dq]
                        + p2 * vb[(l + 64) * 16 + dq] + p3 * vb[(l + 96) * 16 + dq];
#pragma unroll
                for (int o = 16; o; o >>= 1) a += __shfl_xor_sync(FULLMASK, a, o);
                if (l == 0)
                    out[(b * KR + r) * (KH * KDQ) + h * KDQ + dq] = a * inv;
            }
        }
        __syncthreads();
    }

    if (tid < 128)
        out[KB * KR * KH * KDQ + br * 128 + tid] = edge_acc[tid] + edge_b[0];
}

extern "C" void kernel_launch(void* const* d_in, const int* in_sizes, int n_in,
                              void* d_out, int out_size) {
    const float* q    = (const float*)d_in[0];
    const float* k_s  = (const float*)d_in[1];
    const float* k_a  = (const float*)d_in[2];
    const float* v    = (const float*)d_in[3];
    const float* cost = (const float*)d_in[4];
    const float* m1w  = (const float*)d_in[5];
    const float* m1b  = (const float*)d_in[6];
    const float* waa  = (const float*)d_in[7];
    const float* m2w  = (const float*)d_in[8];
    const float* m2b  = (const float*)d_in[9];
    const float* ew   = (const float*)d_in[10];
    const float* eb   = (const float*)d_in[11];
    const float* lng  = (const float*)d_in[12];
    const float* lnb  = (const float*)d_in[13];
    float* out = (float*)d_out;

    cudaFuncSetAttribute(k1_score, cudaFuncAttributeMaxDynamicSharedMemorySize, 98816);
    cudaFuncSetAttribute(k2_main,  cudaFuncAttributeMaxDynamicSharedMemorySize, 29568);

    k1_score<<<KB * KH, 256, 98816>>>(q, k_s, k_a);
    k2_main<<<KB * KR, 256, 29568>>>(cost, m1w, m1b, waa, m2w, m2b, ew, eb,
                                     lng, lnb, v, out);
}

// round 3
// speedup vs baseline: 2.2002x; 1.6539x over previous
#include <cuda_runtime.h>

#define FULLMASK 0xffffffffu

#define KB 8
#define KH 8
#define KR 128
#define KC 128
#define KDQ 16
#define KMS 16

// scratch: score[B,H,R,C] (4 MB)
__device__ float g_score[KB * KH * KR * KC];

// ---- packed f32x2 helpers (Blackwell) ----
__device__ __forceinline__ unsigned long long pk2(float x, float y) {
    unsigned long long r;
    asm("mov.b64 %0, {%1, %2};" : "=l"(r) : "f"(x), "f"(y));
    return r;
}
__device__ __forceinline__ float2 upk2(unsigned long long v) {
    float2 r;
    asm("mov.b64 {%0, %1}, %2;" : "=f"(r.x), "=f"(r.y) : "l"(v));
    return r;
}
__device__ __forceinline__ unsigned long long fma2(unsigned long long a,
                                                   unsigned long long b,
                                                   unsigned long long c) {
    unsigned long long d;
    asm("fma.rn.f32x2 %0, %1, %2, %3;" : "=l"(d) : "l"(a), "l"(b), "l"(c));
    return d;
}
__device__ __forceinline__ unsigned long long mul2(unsigned long long a,
                                                   unsigned long long b) {
    unsigned long long d;
    asm("mul.rn.f32x2 %0, %1, %2;" : "=l"(d) : "l"(a), "l"(b));
    return d;
}
__device__ __forceinline__ void gbar(int g) {
    asm volatile("bar.sync %0, 128;" :: "r"(g + 1) : "memory");
}

// ---------------------------------------------------------------------------
// Kernel 1: per (b,h,quarter): dps = gelu(q ks^T/4); w_self = softmax(dps);
// dpa = relu(q ka^T/4); score = (w_self @ dpa)/4
// grid = 256 blocks, 256 threads; dynamic smem 98816 B
// ---------------------------------------------------------------------------
__global__ __launch_bounds__(256) void k1_score(const float* __restrict__ q,
                                                const float* __restrict__ ks,
                                                const float* __restrict__ ka) {
    extern __shared__ float sm[];
    float* ksT  = sm;            // [16][132]
    float* kaT  = sm + 2112;     // [16][132]
    float* qrow = sm + 4224;     // [128*16]
    float* pbuf = sm + 6272;     // [8][128]
    float* dpa  = sm + 7296;     // [128][136]

    const int bh      = blockIdx.x >> 2;
    const int quarter = blockIdx.x & 3;
    const int tid = threadIdx.x;
    const float* qb  = q  + bh * 2048;
    const float* ksb = ks + bh * 2048;
    const float* kab = ka + bh * 2048;

    for (int i = tid; i < 2048; i += 256) {
        int srow = i >> 4, e = i & 15;
        ksT[e * 132 + srow] = ksb[i];
        kaT[e * 132 + srow] = kab[i];
        qrow[i] = qb[i];
    }
    __syncthreads();

    const int w = tid >> 5, l = tid & 31;

    // Phase A: full dpa[r][c] = relu(dot(q[r], ka[c]) * 0.25)
    for (int k = 0; k < 16; ++k) {
        int r = w * 16 + k;
        float qr[16];
#pragma unroll
        for (int j = 0; j < 4; ++j) {
            float4 v4 = *(const float4*)&qrow[r * 16 + 4 * j];
            qr[4 * j + 0] = v4.x; qr[4 * j + 1] = v4.y;
            qr[4 * j + 2] = v4.z; qr[4 * j + 3] = v4.w;
        }
        float a0 = 0.f, a1 = 0.f, a2 = 0.f, a3 = 0.f;
#pragma unroll
        for (int e = 0; e < 16; ++e) {
            float4 kk = *(const float4*)&kaT[e * 132 + 4 * l];
            a0 = fmaf(qr[e], kk.x, a0); a1 = fmaf(qr[e], kk.y, a1);
            a2 = fmaf(qr[e], kk.z, a2); a3 = fmaf(qr[e], kk.w, a3);
        }
        float4 o;
        o.x = fmaxf(a0 * 0.25f, 0.f); o.y = fmaxf(a1 * 0.25f, 0.f);
        o.z = fmaxf(a2 * 0.25f, 0.f); o.w = fmaxf(a3 * 0.25f, 0.f);
        *(float4*)&dpa[r * 136 + 4 * l] = o;
    }
    __syncthreads();

    // Phase B: this block handles rows [quarter*32, quarter*32+32), 4 per warp
    for (int k = 0; k < 4; ++k) {
        int r = quarter * 32 + w * 4 + k;
        float qr[16];
#pragma unroll
        for (int j = 0; j < 4; ++j) {
            float4 v4 = *(const float4*)&qrow[r * 16 + 4 * j];
            qr[4 * j + 0] = v4.x; qr[4 * j + 1] = v4.y;
            qr[4 * j + 2] = v4.z; qr[4 * j + 3] = v4.w;
        }
        float a0 = 0.f, a1 = 0.f, a2 = 0.f, a3 = 0.f;
#pragma unroll
        for (int e = 0; e < 16; ++e) {
            float4 kk = *(const float4*)&ksT[e * 132 + 4 * l];
            a0 = fmaf(qr[e], kk.x, a0); a1 = fmaf(qr[e], kk.y, a1);
            a2 = fmaf(qr[e], kk.z, a2); a3 = fmaf(qr[e], kk.w, a3);
        }
        // exact GELU on qk/4
        float x0 = a0 * 0.25f, x1 = a1 * 0.25f, x2 = a2 * 0.25f, x3 = a3 * 0.25f;
        a0 = x0 * normcdff(x0); a1 = x1 * normcdff(x1);
        a2 = x2 * normcdff(x2); a3 = x3 * normcdff(x3);
        // softmax over 128 (4 per lane)
        float mx = fmaxf(fmaxf(a0, a1), fmaxf(a2, a3));
#pragma unroll
        for (int o = 16; o; o >>= 1) mx = fmaxf(mx, __shfl_xor_sync(FULLMASK, mx, o));
        float p0 = __expf(a0 - mx), p1 = __expf(a1 - mx);
        float p2 = __expf(a2 - mx), p3 = __expf(a3 - mx);
        float ssum = p0 + p1 + p2 + p3;
#pragma unroll
        for (int o = 16; o; o >>= 1) ssum += __shfl_xor_sync(FULLMASK, ssum, o);
        float inv = 1.f / ssum;
        float4 pv = make_float4(p0 * inv, p1 * inv, p2 * inv, p3 * inv);
        *(float4*)&pbuf[w * 128 + 4 * l] = pv;
        __syncwarp();
        // score row = p @ dpa, scaled by 0.25
        float c0 = 0.f, c1 = 0.f, c2 = 0.f, c3 = 0.f;
#pragma unroll 4
        for (int s2 = 0; s2 < 128; ++s2) {
            float pvv = pbuf[w * 128 + s2];
            float4 dv = *(const float4*)&dpa[s2 * 136 + 4 * l];
            c0 = fmaf(pvv, dv.x, c0); c1 = fmaf(pvv, dv.y, c1);
            c2 = fmaf(pvv, dv.z, c2); c3 = fmaf(pvv, dv.w, c3);
        }
        float4 so = make_float4(c0 * 0.25f, c1 * 0.25f, c2 * 0.25f, c3 * 0.25f);
        *(float4*)&g_score[(bh * 128 + r) * 128 + 4 * l] = so;
        __syncwarp();
    }
}

// ---------------------------------------------------------------------------
// Kernel 2: per (b,r). Two warp-groups of 128 threads; group g handles heads
// h = 4g..4g+3. One thread per dd-row: single-pass bound-normalized softmax,
// everything in registers, no cross-lane reductions in the hot loop.
// grid = 1024 blocks, 256 threads; dynamic smem 51872 B
// ---------------------------------------------------------------------------
__global__ __launch_bounds__(256, 3) void k2_main(
    const float* __restrict__ cost_mat,
    const float* __restrict__ mix1_w, const float* __restrict__ mix1_b,
    const float* __restrict__ Waa,
    const float* __restrict__ mix2_w, const float* __restrict__ mix2_b,
    const float* __restrict__ edge_w, const float* __restrict__ edge_b,
    const float* __restrict__ ln_g,  const float* __restrict__ ln_b,
    const float* __restrict__ v, float* __restrict__ out) {
    extern __shared__ float sm[];
    float* waa_all = sm;            // [8][256]
    float* w1a_all = sm + 2048;     // [8][16]
    float* w1b_all = sm + 2176;     // [8][16]
    float* b1s_all = sm + 2304;     // [8][16]
    float* w2s_all = sm + 2432;     // [8][16]
    float* ews_all = sm + 2560;     // [8][16]
    float* b2_all  = sm + 2688;     // [8]
    float* costrow = sm + 2696;     // [128]
    float* lng     = sm + 2824;     // [128]
    float* lnb     = sm + 2952;     // [128]
    // per-group region: base 3080 + g*4944
    const int tid = threadIdx.x;
    const int g  = tid >> 7;        // warp group (0,1)
    const int c  = tid & 127;       // row owned by this thread
    const int gw = (tid >> 5) & 3;  // warp within group
    const int l  = tid & 31;

    float* ms1      = sm + 3080 + g * 4944;  // [128][20]
    float* aeT      = ms1 + 2560;            // [16][132]
    float* mixedrow = aeT + 2112;            // [128]
    float* edge     = mixedrow + 128;        // [128]
    float* Msm      = edge + 128;            // [4]

    const int br = blockIdx.x;
    const int b = br >> 7, r = br & 127;

    // ---- preload all weights / per-row constants ----
    for (int i = tid; i < 2048; i += 256) waa_all[i] = Waa[i];
    if (tid < 128) {
        int h0 = tid >> 4, e0 = tid & 15;
        w1a_all[tid] = mix1_w[h0 * 32 + e0];
        w1b_all[tid] = mix1_w[h0 * 32 + 16 + e0];
        b1s_all[tid] = mix1_b[tid];
        w2s_all[tid] = mix2_w[tid];
        ews_all[tid] = edge_w[tid];
        costrow[tid] = cost_mat[br * 128 + tid];
        lng[tid] = ln_g[tid];
        lnb[tid] = ln_b[tid];
    }
    if (tid < 8) b2_all[tid] = mix2_b[tid];
    edge[c] = 0.f;      // each group's 128 threads init their own edge buffer
    __syncthreads();

    for (int hh = 0; hh < 4; ++hh) {
        const int h = g * 4 + hh;

        // ---- P1: ms1 row c, t-row (regs), mixed score, tile-max ----
        float sc = g_score[((b * KH + h) * KR + r) * KC + c];
        float co = costrow[c];
        float m[16];
#pragma unroll
        for (int e = 0; e < 16; ++e)
            m[e] = fmaxf(fmaf(sc, w1a_all[h * 16 + e],
                         fmaf(co, w1b_all[h * 16 + e], b1s_all[h * 16 + e])), 0.f);
#pragma unroll
        for (int j = 0; j < 4; ++j)
            *(float4*)&ms1[c * 20 + 4 * j] =
                make_float4(m[4 * j], m[4 * j + 1], m[4 * j + 2], m[4 * j + 3]);
        {   // mixed = ms1 . w2 + b2
            float mx = b2_all[h];
#pragma unroll
            for (int f = 0; f < 16; ++f) mx = fmaf(m[f], w2s_all[h * 16 + f], mx);
            mixedrow[c] = mx;
        }
        // t[c][x] = sum_e m[e] * Waa[e][x], packed in pairs
        unsigned long long t2[8];
        const unsigned long long* waa2 =
            (const unsigned long long*)(waa_all + h * 256);
        {
            unsigned long long m02 = pk2(m[0], m[0]);
#pragma unroll
            for (int j = 0; j < 8; ++j) t2[j] = mul2(m02, waa2[j]);
#pragma unroll
            for (int f = 1; f < 16; ++f) {
                unsigned long long mf2 = pk2(m[f], m[f]);
#pragma unroll
                for (int j = 0; j < 8; ++j) t2[j] = fma2(mf2, waa2[f * 8 + j], t2[j]);
            }
        }
        // tile max of ms1 (ms1 >= 0): warp-reduce row maxes
        {
            float rm = m[0];
#pragma unroll
            for (int e = 1; e < 16; ++e) rm = fmaxf(rm, m[e]);
#pragma unroll
            for (int o = 16; o; o >>= 1) rm = fmaxf(rm, __shfl_xor_sync(FULLMASK, rm, o));
            if (l == 0) Msm[gw] = rm;
        }
        // sum of relu(t) for the softmax upper bound
        float srt = 0.f;
#pragma unroll
        for (int j = 0; j < 8; ++j) {
            float2 tf = upk2(t2[j]);
            srt += fmaxf(tf.x, 0.f) + fmaxf(tf.y, 0.f);
        }
        gbar(g);
        float M = fmaxf(fmaxf(Msm[0], Msm[1]), fmaxf(Msm[2], Msm[3]));
        float m_ub = M * srt;   // dd[c][d] <= m_ub for all d (ms1 in [0,M])

        // ---- P2: one-pass softmax(dd) @ ms1, all in registers ----
        unsigned long long vv2[8];
#pragma unroll
        for (int j = 0; j < 8; ++j) vv2[j] = 0ull;
        float s = 0.f;
#pragma unroll 2
        for (int d = 0; d < 128; ++d) {
            const float* mrow = &ms1[d * 20];     // broadcast across lanes
            ulonglong2 u0 = *(const ulonglong2*)&mrow[0];
            ulonglong2 u1 = *(const ulonglong2*)&mrow[4];
            ulonglong2 u2 = *(const ulonglong2*)&mrow[8];
            ulonglong2 u3 = *(const ulonglong2*)&mrow[12];
            unsigned long long da = mul2(t2[0], u0.x);
            unsigned long long db = mul2(t2[1], u0.y);
            da = fma2(t2[2], u1.x, da); db = fma2(t2[3], u1.y, db);
            da = fma2(t2[4], u2.x, da); db = fma2(t2[5], u2.y, db);
            da = fma2(t2[6], u3.x, da); db = fma2(t2[7], u3.y, db);
            float2 fa = upk2(da), fb = upk2(db);
            float dd = (fa.x + fa.y) + (fb.x + fb.y);
            float p = __expf(dd - m_ub);
            s += p;
            unsigned long long p2 = pk2(p, p);
            vv2[0] = fma2(p2, u0.x, vv2[0]); vv2[1] = fma2(p2, u0.y, vv2[1]);
            vv2[2] = fma2(p2, u1.x, vv2[2]); vv2[3] = fma2(p2, u1.y, vv2[3]);
            vv2[4] = fma2(p2, u2.x, vv2[4]); vv2[5] = fma2(p2, u2.y, vv2[5]);
            vv2[6] = fma2(p2, u3.x, vv2[6]); vv2[7] = fma2(p2, u3.y, vv2[7]);
        }
        {
            float inv = 1.f / s;
#pragma unroll
            for (int j = 0; j < 8; ++j) {
                float2 vf = upk2(vv2[j]);
                aeT[(2 * j) * 132 + c]     = vf.x * inv;
                aeT[(2 * j + 1) * 132 + c] = vf.y * inv;
            }
        }
        gbar(g);

        // ---- P3: LayerNorm over C; warp gw handles features 4gw..4gw+3 ----
#pragma unroll
        for (int ei = 0; ei < 4; ++ei) {
            int e = gw * 4 + ei;
            float x0 = aeT[e * 132 + l]      + ms1[l * 20 + e];
            float x1 = aeT[e * 132 + l + 32] + ms1[(l + 32) * 20 + e];
            float x2 = aeT[e * 132 + l + 64] + ms1[(l + 64) * 20 + e];
            float x3 = aeT[e * 132 + l + 96] + ms1[(l + 96) * 20 + e];
            float s1 = x0 + x1 + x2 + x3;
            float sq = x0 * x0 + x1 * x1 + x2 * x2 + x3 * x3;
#pragma unroll
            for (int o = 16; o; o >>= 1) {
                s1 += __shfl_xor_sync(FULLMASK, s1, o);
                sq += __shfl_xor_sync(FULLMASK, sq, o);
            }
            float mean = s1 * (1.f / 128.f);
            float var  = sq * (1.f / 128.f) - mean * mean;
            float rs = rsqrtf(var + 1e-5f);
            aeT[e * 132 + l]      = (x0 - mean) * rs * lng[l]      + lnb[l];
            aeT[e * 132 + l + 32] = (x1 - mean) * rs * lng[l + 32] + lnb[l + 32];
            aeT[e * 132 + l + 64] = (x2 - mean) * rs * lng[l + 64] + lnb[l + 64];
            aeT[e * 132 + l + 96] = (x3 - mean) * rs * lng[l + 96] + lnb[l + 96];
        }
        gbar(g);

        // ---- P4: edge accumulation + mixed softmax attention ----
        {
            float acc = edge[c];
#pragma unroll
            for (int e = 0; e < 16; ++e)
                acc = fmaf(aeT[e * 132 + c], ews_all[h * 16 + e], acc);
            edge[c] = acc;
        }
        {
            float m0 = mixedrow[l],      m1 = mixedrow[l + 32];
            float m2 = mixedrow[l + 64], m3 = mixedrow[l + 96];
            float mx = fmaxf(fmaxf(m0, m1), fmaxf(m2, m3));
#pragma unroll
            for (int o = 16; o; o >>= 1) mx = fmaxf(mx, __shfl_xor_sync(FULLMASK, mx, o));
            float p0 = __expf(m0 - mx), p1 = __expf(m1 - mx);
            float p2 = __expf(m2 - mx), p3 = __expf(m3 - mx);
            float ssum = p0 + p1 + p2 + p3;
#pragma unroll
            for (int o = 16; o; o >>= 1) ssum += __shfl_xor_sync(FULLMASK, ssum, o);
            float inv = 1.f / ssum;
            const float* vb = v + (b * KH + h) * KC * KDQ;
#pragma unroll
            for (int d0 = 0; d0 < 4; ++d0) {
                int dq = gw * 4 + d0;
                float a = p0 * vb[l * 16 + dq] + p1 * vb[(l + 32) * 16 + dq]
                        + p2 * vb[(l + 64) * 16 + dq] + p3 * vb[(l + 96) * 16 + dq];
#pragma unroll
                for (int o = 16; o; o >>= 1) a += __shfl_xor_sync(FULLMASK, a, o);
                if (l == 0)
                    out[(b * KR + r) * (KH * KDQ) + h * KDQ + dq] = a * inv;
            }
        }
        gbar(g);   // ms1/mixedrow reused next h
    }

    __syncthreads();
    if (tid < 128) {
        const float* e0 = sm + 3080 + 2560 + 2112 + 128;
        const float* e1 = sm + 3080 + 4944 + 2560 + 2112 + 128;
        out[KB * KR * KH * KDQ + br * 128 + tid] = e0[tid] + e1[tid] + edge_b[0];
    }
}

extern "C" void kernel_launch(void* const* d_in, const int* in_sizes, int n_in,
                              void* d_out, int out_size) {
    const float* q    = (const float*)d_in[0];
    const float* k_s  = (const float*)d_in[1];
    const float* k_a  = (const float*)d_in[2];
    const float* v    = (const float*)d_in[3];
    const float* cost = (const float*)d_in[4];
    const float* m1w  = (const float*)d_in[5];
    const float* m1b  = (const float*)d_in[6];
    const float* waa  = (const float*)d_in[7];
    const float* m2w  = (const float*)d_in[8];
    const float* m2b  = (const float*)d_in[9];
    const float* ew   = (const float*)d_in[10];
    const float* eb   = (const float*)d_in[11];
    const float* lng  = (const float*)d_in[12];
    const float* lnb  = (const float*)d_in[13];
    float* out = (float*)d_out;

    cudaFuncSetAttribute(k1_score, cudaFuncAttributeMaxDynamicSharedMemorySize, 98816);
    cudaFuncSetAttribute(k2_main,  cudaFuncAttributeMaxDynamicSharedMemorySize, 51872);

    k1_score<<<KB * KH * 4, 256, 98816>>>(q, k_s, k_a);
    k2_main<<<KB * KR, 256, 51872>>>(cost, m1w, m1b, waa, m2w, m2b, ew, eb,
                                     lng, lnb, v, out);
}

// round 4
// speedup vs baseline: 2.2024x; 1.0010x over previous
#include <cuda_runtime.h>

#define FULLMASK 0xffffffffu

#define KB 8
#define KH 8
#define KR 128
#define KC 128
#define KDQ 16
#define KMS 16

#define L2E 1.4426950408889634f

// scratch: score[B,H,R,C] (4 MB)
__device__ float g_score[KB * KH * KR * KC];

// ---- packed f32x2 helpers (Blackwell) ----
__device__ __forceinline__ unsigned long long pk2(float x, float y) {
    unsigned long long r;
    asm("mov.b64 %0, {%1, %2};" : "=l"(r) : "f"(x), "f"(y));
    return r;
}
__device__ __forceinline__ float2 upk2(unsigned long long v) {
    float2 r;
    asm("mov.b64 {%0, %1}, %2;" : "=f"(r.x), "=f"(r.y) : "l"(v));
    return r;
}
__device__ __forceinline__ unsigned long long fma2(unsigned long long a,
                                                   unsigned long long b,
                                                   unsigned long long c) {
    unsigned long long d;
    asm("fma.rn.f32x2 %0, %1, %2, %3;" : "=l"(d) : "l"(a), "l"(b), "l"(c));
    return d;
}
__device__ __forceinline__ unsigned long long mul2(unsigned long long a,
                                                   unsigned long long b) {
    unsigned long long d;
    asm("mul.rn.f32x2 %0, %1, %2;" : "=l"(d) : "l"(a), "l"(b));
    return d;
}
__device__ __forceinline__ unsigned long long add2(unsigned long long a,
                                                   unsigned long long b) {
    unsigned long long d;
    asm("add.rn.f32x2 %0, %1, %2;" : "=l"(d) : "l"(a), "l"(b));
    return d;
}
__device__ __forceinline__ float ex2(float x) {
    float r;
    asm("ex2.approx.f32 %0, %1;" : "=f"(r) : "f"(x));
    return r;
}
__device__ __forceinline__ void gbar(int g) {
    asm volatile("bar.sync %0, 128;" :: "r"(g + 1) : "memory");
}

// ---------------------------------------------------------------------------
// Kernel 1: per (b,h,quarter): dps = gelu(q ks^T/4); w_self = softmax(dps);
// dpa = relu(q ka^T/4); score = (w_self @ dpa)/4
// grid = 256 blocks, 256 threads; dynamic smem 98816 B
// ---------------------------------------------------------------------------
__global__ __launch_bounds__(256) void k1_score(const float* __restrict__ q,
                                                const float* __restrict__ ks,
                                                const float* __restrict__ ka) {
    extern __shared__ float sm[];
    float* ksT  = sm;            // [16][132]
    float* kaT  = sm + 2112;     // [16][132]
    float* qrow = sm + 4224;     // [128*16]
    float* pbuf = sm + 6272;     // [8][128]
    float* dpa  = sm + 7296;     // [128][136]

    const int bh      = blockIdx.x >> 2;
    const int quarter = blockIdx.x & 3;
    const int tid = threadIdx.x;
    const float* qb  = q  + bh * 2048;
    const float* ksb = ks + bh * 2048;
    const float* kab = ka + bh * 2048;

    for (int i = tid; i < 2048; i += 256) {
        int srow = i >> 4, e = i & 15;
        ksT[e * 132 + srow] = ksb[i];
        kaT[e * 132 + srow] = kab[i];
        qrow[i] = qb[i];
    }
    __syncthreads();

    const int w = tid >> 5, l = tid & 31;

    // Phase A: full dpa[r][c] = relu(dot(q[r], ka[c]) * 0.25)
    for (int k = 0; k < 16; ++k) {
        int r = w * 16 + k;
        float qr[16];
#pragma unroll
        for (int j = 0; j < 4; ++j) {
            float4 v4 = *(const float4*)&qrow[r * 16 + 4 * j];
            qr[4 * j + 0] = v4.x; qr[4 * j + 1] = v4.y;
            qr[4 * j + 2] = v4.z; qr[4 * j + 3] = v4.w;
        }
        float a0 = 0.f, a1 = 0.f, a2 = 0.f, a3 = 0.f;
#pragma unroll
        for (int e = 0; e < 16; ++e) {
            float4 kk = *(const float4*)&kaT[e * 132 + 4 * l];
            a0 = fmaf(qr[e], kk.x, a0); a1 = fmaf(qr[e], kk.y, a1);
            a2 = fmaf(qr[e], kk.z, a2); a3 = fmaf(qr[e], kk.w, a3);
        }
        float4 o;
        o.x = fmaxf(a0 * 0.25f, 0.f); o.y = fmaxf(a1 * 0.25f, 0.f);
        o.z = fmaxf(a2 * 0.25f, 0.f); o.w = fmaxf(a3 * 0.25f, 0.f);
        *(float4*)&dpa[r * 136 + 4 * l] = o;
    }
    __syncthreads();

    // Phase B: this block handles rows [quarter*32, quarter*32+32), 4 per warp
    for (int k = 0; k < 4; ++k) {
        int r = quarter * 32 + w * 4 + k;
        float qr[16];
#pragma unroll
        for (int j = 0; j < 4; ++j) {
            float4 v4 = *(const float4*)&qrow[r * 16 + 4 * j];
            qr[4 * j + 0] = v4.x; qr[4 * j + 1] = v4.y;
            qr[4 * j + 2] = v4.z; qr[4 * j + 3] = v4.w;
        }
        float a0 = 0.f, a1 = 0.f, a2 = 0.f, a3 = 0.f;
#pragma unroll
        for (int e = 0; e < 16; ++e) {
            float4 kk = *(const float4*)&ksT[e * 132 + 4 * l];
            a0 = fmaf(qr[e], kk.x, a0); a1 = fmaf(qr[e], kk.y, a1);
            a2 = fmaf(qr[e], kk.z, a2); a3 = fmaf(qr[e], kk.w, a3);
        }
        // exact GELU on qk/4
        float x0 = a0 * 0.25f, x1 = a1 * 0.25f, x2 = a2 * 0.25f, x3 = a3 * 0.25f;
        a0 = x0 * normcdff(x0); a1 = x1 * normcdff(x1);
        a2 = x2 * normcdff(x2); a3 = x3 * normcdff(x3);
        // softmax over 128 (4 per lane)
        float mx = fmaxf(fmaxf(a0, a1), fmaxf(a2, a3));
#pragma unroll
        for (int o = 16; o; o >>= 1) mx = fmaxf(mx, __shfl_xor_sync(FULLMASK, mx, o));
        float p0 = __expf(a0 - mx), p1 = __expf(a1 - mx);
        float p2 = __expf(a2 - mx), p3 = __expf(a3 - mx);
        float ssum = p0 + p1 + p2 + p3;
#pragma unroll
        for (int o = 16; o; o >>= 1) ssum += __shfl_xor_sync(FULLMASK, ssum, o);
        float inv = 1.f / ssum;
        float4 pv = make_float4(p0 * inv, p1 * inv, p2 * inv, p3 * inv);
        *(float4*)&pbuf[w * 128 + 4 * l] = pv;
        __syncwarp();
        // score row = p @ dpa, scaled by 0.25
        float c0 = 0.f, c1 = 0.f, c2 = 0.f, c3 = 0.f;
#pragma unroll 4
        for (int s2 = 0; s2 < 128; ++s2) {
            float pvv = pbuf[w * 128 + s2];
            float4 dv = *(const float4*)&dpa[s2 * 136 + 4 * l];
            c0 = fmaf(pvv, dv.x, c0); c1 = fmaf(pvv, dv.y, c1);
            c2 = fmaf(pvv, dv.z, c2); c3 = fmaf(pvv, dv.w, c3);
        }
        float4 so = make_float4(c0 * 0.25f, c1 * 0.25f, c2 * 0.25f, c3 * 0.25f);
        *(float4*)&g_score[(bh * 128 + r) * 128 + 4 * l] = so;
        __syncwarp();
    }
}

// ---------------------------------------------------------------------------
// Kernel 2: per (b,r). Two warp-groups of 128 threads; group g handles heads
// h = 4g..4g+3. One thread per dd-row; Waa pre-scaled by log2(e) so the
// softmax runs in the exp2 domain with a single EX2 per element.
// grid = 1024 blocks, 256 threads; dynamic smem 51872 B
// ---------------------------------------------------------------------------
__global__ __launch_bounds__(256, 4) void k2_main(
    const float* __restrict__ cost_mat,
    const float* __restrict__ mix1_w, const float* __restrict__ mix1_b,
    const float* __restrict__ Waa,
    const float* __restrict__ mix2_w, const float* __restrict__ mix2_b,
    const float* __restrict__ edge_w, const float* __restrict__ edge_b,
    const float* __restrict__ ln_g,  const float* __restrict__ ln_b,
    const float* __restrict__ v, float* __restrict__ out) {
    extern __shared__ float sm[];
    float* waa_all = sm;            // [8][256]  (pre-scaled by log2 e)
    float* w1a_all = sm + 2048;     // [8][16]
    float* w1b_all = sm + 2176;     // [8][16]
    float* b1s_all = sm + 2304;     // [8][16]
    float* w2s_all = sm + 2432;     // [8][16]
    float* ews_all = sm + 2560;     // [8][16]
    float* b2_all  = sm + 2688;     // [8]
    float* costrow = sm + 2696;     // [128]
    float* lng     = sm + 2824;     // [128]
    float* lnb     = sm + 2952;     // [128]
    const int tid = threadIdx.x;
    const int g  = tid >> 7;        // warp group (0,1)
    const int c  = tid & 127;       // row owned by this thread
    const int gw = (tid >> 5) & 3;  // warp within group
    const int l  = tid & 31;

    float* ms1      = sm + 3080 + g * 4944;  // [128][20]
    float* aeT      = ms1 + 2560;            // [16][132]
    float* mixedrow = aeT + 2112;            // [128]
    float* edge     = mixedrow + 128;        // [128]
    float* Msm      = edge + 128;            // [4]

    const int br = blockIdx.x;
    const int b = br >> 7, r = br & 127;

    // ---- preload all weights / per-row constants ----
    for (int i = tid; i < 2048; i += 256) waa_all[i] = Waa[i] * L2E;
    if (tid < 128) {
        int h0 = tid >> 4, e0 = tid & 15;
        w1a_all[tid] = mix1_w[h0 * 32 + e0];
        w1b_all[tid] = mix1_w[h0 * 32 + 16 + e0];
        b1s_all[tid] = mix1_b[tid];
        w2s_all[tid] = mix2_w[tid];
        ews_all[tid] = edge_w[tid];
        costrow[tid] = cost_mat[br * 128 + tid];
        lng[tid] = ln_g[tid];
        lnb[tid] = ln_b[tid];
    }
    if (tid < 8) b2_all[tid] = mix2_b[tid];
    edge[c] = 0.f;
    __syncthreads();

    for (int hh = 0; hh < 4; ++hh) {
        const int h = g * 4 + hh;

        // ---- P1: ms1 row c, t-row (regs, log2-scaled), mixed score, tile max
        float sc = g_score[((b * KH + h) * KR + r) * KC + c];
        float co = costrow[c];
        float m[16];
#pragma unroll
        for (int e = 0; e < 16; ++e)
            m[e] = fmaxf(fmaf(sc, w1a_all[h * 16 + e],
                         fmaf(co, w1b_all[h * 16 + e], b1s_all[h * 16 + e])), 0.f);
#pragma unroll
        for (int j = 0; j < 4; ++j)
            *(float4*)&ms1[c * 20 + 4 * j] =
                make_float4(m[4 * j], m[4 * j + 1], m[4 * j + 2], m[4 * j + 3]);
        {   // mixed = ms1 . w2 + b2
            float mx = b2_all[h];
#pragma unroll
            for (int f = 0; f < 16; ++f) mx = fmaf(m[f], w2s_all[h * 16 + f], mx);
            mixedrow[c] = mx;
        }
        // tile max of ms1 (ms1 >= 0): warp-reduce row maxes
        {
            float rm = m[0];
#pragma unroll
            for (int e = 1; e < 16; ++e) rm = fmaxf(rm, m[e]);
#pragma unroll
            for (int o = 16; o; o >>= 1) rm = fmaxf(rm, __shfl_xor_sync(FULLMASK, rm, o));
            if (l == 0) Msm[gw] = rm;
        }
        // t[c][x] = sum_e m[e] * Waa_scaled[e][x], packed in pairs
        unsigned long long t2[8];
        {
            const ulonglong2* waa4 = (const ulonglong2*)(waa_all + h * 256);
            unsigned long long m02 = pk2(m[0], m[0]);
#pragma unroll
            for (int j = 0; j < 4; ++j) {
                ulonglong2 wv = waa4[j];
                t2[2 * j]     = mul2(m02, wv.x);
                t2[2 * j + 1] = mul2(m02, wv.y);
            }
#pragma unroll
            for (int f = 1; f < 16; ++f) {
                unsigned long long mf2 = pk2(m[f], m[f]);
#pragma unroll
                for (int j = 0; j < 4; ++j) {
                    ulonglong2 wv = waa4[f * 4 + j];
                    t2[2 * j]     = fma2(mf2, wv.x, t2[2 * j]);
                    t2[2 * j + 1] = fma2(mf2, wv.y, t2[2 * j + 1]);
                }
            }
        }
        // sum of relu(t) for the softmax upper bound (log2 domain)
        float srt = 0.f;
#pragma unroll
        for (int j = 0; j < 8; ++j) {
            float2 tf = upk2(t2[j]);
            srt += fmaxf(tf.x, 0.f) + fmaxf(tf.y, 0.f);
        }
        gbar(g);
        float M = fmaxf(fmaxf(Msm[0], Msm[1]), fmaxf(Msm[2], Msm[3]));
        float m_ub = M * srt;   // dd2[c][d] <= m_ub for all d
        const unsigned long long nmub2 = pk2(-m_ub, 0.f);

        // ---- P2: one-pass softmax(dd) @ ms1, all in registers ----
        unsigned long long vv2[8];
#pragma unroll
        for (int j = 0; j < 8; ++j) vv2[j] = 0ull;
        float s = 0.f;
#pragma unroll 2
        for (int d = 0; d < 128; ++d) {
            const float* mrow = &ms1[d * 20];     // broadcast across lanes
            ulonglong2 u0 = *(const ulonglong2*)&mrow[0];
            ulonglong2 u1 = *(const ulonglong2*)&mrow[4];
            ulonglong2 u2 = *(const ulonglong2*)&mrow[8];
            ulonglong2 u3 = *(const ulonglong2*)&mrow[12];
            unsigned long long da = fma2(t2[0], u0.x, nmub2);
            unsigned long long db = mul2(t2[1], u0.y);
            da = fma2(t2[2], u1.x, da); db = fma2(t2[3], u1.y, db);
            da = fma2(t2[4], u2.x, da); db = fma2(t2[5], u2.y, db);
            da = fma2(t2[6], u3.x, da); db = fma2(t2[7], u3.y, db);
            float2 fs = upk2(add2(da, db));
            float p = ex2(fs.x + fs.y);   // exp2(dd*log2e - m_ub)
            s += p;
            unsigned long long p2 = pk2(p, p);
            vv2[0] = fma2(p2, u0.x, vv2[0]); vv2[1] = fma2(p2, u0.y, vv2[1]);
            vv2[2] = fma2(p2, u1.x, vv2[2]); vv2[3] = fma2(p2, u1.y, vv2[3]);
            vv2[4] = fma2(p2, u2.x, vv2[4]); vv2[5] = fma2(p2, u2.y, vv2[5]);
            vv2[6] = fma2(p2, u3.x, vv2[6]); vv2[7] = fma2(p2, u3.y, vv2[7]);
        }
        {
            float inv = 1.f / s;
            unsigned long long inv2 = pk2(inv, inv);
#pragma unroll
            for (int j = 0; j < 8; ++j) {
                float2 vf = upk2(mul2(vv2[j], inv2));
                aeT[(2 * j) * 132 + c]     = vf.x;
                aeT[(2 * j + 1) * 132 + c] = vf.y;
            }
        }
        gbar(g);

        // ---- P3: LayerNorm over C; warp gw handles features 4gw..4gw+3 ----
#pragma unroll
        for (int ei = 0; ei < 4; ++ei) {
            int e = gw * 4 + ei;
            float x0 = aeT[e * 132 + l]      + ms1[l * 20 + e];
            float x1 = aeT[e * 132 + l + 32] + ms1[(l + 32) * 20 + e];
            float x2 = aeT[e * 132 + l + 64] + ms1[(l + 64) * 20 + e];
            float x3 = aeT[e * 132 + l + 96] + ms1[(l + 96) * 20 + e];
            float s1 = x0 + x1 + x2 + x3;
            float sq = x0 * x0 + x1 * x1 + x2 * x2 + x3 * x3;
#pragma unroll
            for (int o = 16; o; o >>= 1) {
                s1 += __shfl_xor_sync(FULLMASK, s1, o);
                sq += __shfl_xor_sync(FULLMASK, sq, o);
            }
            float mean = s1 * (1.f / 128.f);
            float var  = sq * (1.f / 128.f) - mean * mean;
            float rs = rsqrtf(var + 1e-5f);
            aeT[e * 132 + l]      = (x0 - mean) * rs * lng[l]      + lnb[l];
            aeT[e * 132 + l + 32] = (x1 - mean) * rs * lng[l + 32] + lnb[l + 32];
            aeT[e * 132 + l + 64] = (x2 - mean) * rs * lng[l + 64] + lnb[l + 64];
            aeT[e * 132 + l + 96] = (x3 - mean) * rs * lng[l + 96] + lnb[l + 96];
        }
        gbar(g);

        // ---- P4: edge accumulation + mixed softmax attention ----
        {
            float acc = edge[c];
#pragma unroll
            for (int e = 0; e < 16; ++e)
                acc = fmaf(aeT[e * 132 + c], ews_all[h * 16 + e], acc);
            edge[c] = acc;
        }
        {
            float m0 = mixedrow[l],      m1 = mixedrow[l + 32];
            float m2 = mixedrow[l + 64], m3 = mixedrow[l + 96];
            float mx = fmaxf(fmaxf(m0, m1), fmaxf(m2, m3));
#pragma unroll
            for (int o = 16; o; o >>= 1) mx = fmaxf(mx, __shfl_xor_sync(FULLMASK, mx, o));
            float p0 = __expf(m0 - mx), p1 = __expf(m1 - mx);
            float p2 = __expf(m2 - mx), p3 = __expf(m3 - mx);
            float ssum = p0 + p1 + p2 + p3;
#pragma unroll
            for (int o = 16; o; o >>= 1) ssum += __shfl_xor_sync(FULLMASK, ssum, o);
            float inv = 1.f / ssum;
            const float* vb = v + (b * KH + h) * KC * KDQ;
#pragma unroll
            for (int d0 = 0; d0 < 4; ++d0) {
                int dq = gw * 4 + d0;
                float a = p0 * vb[l * 16 + dq] + p1 * vb[(l + 32) * 16 + dq]
                        + p2 * vb[(l + 64) * 16 + dq] + p3 * vb[(l + 96) * 16 + dq];
#pragma unroll
                for (int o = 16; o; o >>= 1) a += __shfl_xor_sync(FULLMASK, a, o);
                if (l == 0)
                    out[(b * KR + r) * (KH * KDQ) + h * KDQ + dq] = a * inv;
            }
        }
        gbar(g);   // ms1/mixedrow reused next h
    }

    __syncthreads();
    if (tid < 128) {
        const float* e0 = sm + 3080 + 2560 + 2112 + 128;
        const float* e1 = sm + 3080 + 4944 + 2560 + 2112 + 128;
        out[KB * KR * KH * KDQ + br * 128 + tid] = e0[tid] + e1[tid] + edge_b[0];
    }
}

extern "C" void kernel_launch(void* const* d_in, const int* in_sizes, int n_in,
                              void* d_out, int out_size) {
    const float* q    = (const float*)d_in[0];
    const float* k_s  = (const float*)d_in[1];
    const float* k_a  = (const float*)d_in[2];
    const float* v    = (const float*)d_in[3];
    const float* cost = (const float*)d_in[4];
    const float* m1w  = (const float*)d_in[5];
    const float* m1b  = (const float*)d_in[6];
    const float* waa  = (const float*)d_in[7];
    const float* m2w  = (const float*)d_in[8];
    const float* m2b  = (const float*)d_in[9];
    const float* ew   = (const float*)d_in[10];
    const float* eb   = (const float*)d_in[11];
    const float* lng  = (const float*)d_in[12];
    const float* lnb  = (const float*)d_in[13];
    float* out = (float*)d_out;

    cudaFuncSetAttribute(k1_score, cudaFuncAttributeMaxDynamicSharedMemorySize, 98816);
    cudaFuncSetAttribute(k2_main,  cudaFuncAttributeMaxDynamicSharedMemorySize, 51872);

    k1_score<<<KB * KH * 4, 256, 98816>>>(q, k_s, k_a);
    k2_main<<<KB * KR, 256, 51872>>>(cost, m1w, m1b, waa, m2w, m2b, ew, eb,
                                     lng, lnb, v, out);
}

// round 5
// speedup vs baseline: 2.2127x; 1.0047x over previous
#include <cuda_runtime.h>

#define FULLMASK 0xffffffffu

#define KB 8
#define KH 8
#define KR 128
#define KC 128
#define KDQ 16
#define KMS 16

#define L2E 1.4426950408889634f

// scratch: score[B,H,R,C] (4 MB)
__device__ float g_score[KB * KH * KR * KC];

// ---- packed f32x2 helpers (Blackwell) ----
__device__ __forceinline__ unsigned long long pk2(float x, float y) {
    unsigned long long r;
    asm("mov.b64 %0, {%1, %2};" : "=l"(r) : "f"(x), "f"(y));
    return r;
}
__device__ __forceinline__ float2 upk2(unsigned long long v) {
    float2 r;
    asm("mov.b64 {%0, %1}, %2;" : "=f"(r.x), "=f"(r.y) : "l"(v));
    return r;
}
__device__ __forceinline__ unsigned long long fma2(unsigned long long a,
                                                   unsigned long long b,
                                                   unsigned long long c) {
    unsigned long long d;
    asm("fma.rn.f32x2 %0, %1, %2, %3;" : "=l"(d) : "l"(a), "l"(b), "l"(c));
    return d;
}
__device__ __forceinline__ unsigned long long mul2(unsigned long long a,
                                                   unsigned long long b) {
    unsigned long long d;
    asm("mul.rn.f32x2 %0, %1, %2;" : "=l"(d) : "l"(a), "l"(b));
    return d;
}
__device__ __forceinline__ unsigned long long add2(unsigned long long a,
                                                   unsigned long long b) {
    unsigned long long d;
    asm("add.rn.f32x2 %0, %1, %2;" : "=l"(d) : "l"(a), "l"(b));
    return d;
}
__device__ __forceinline__ float ex2(float x) {
    float r;
    asm("ex2.approx.f32 %0, %1;" : "=f"(r) : "f"(x));
    return r;
}
__device__ __forceinline__ void gbar(int g) {
    asm volatile("bar.sync %0, 128;" :: "r"(g + 1) : "memory");
}

// ---------------------------------------------------------------------------
// Kernel 1: per (b,h,quarter): dps = gelu(q ks^T/4); w_self = softmax(dps);
// dpa = relu(q ka^T/4); score = (w_self @ dpa)/4
// grid = 256 blocks, 256 threads; dynamic smem 98816 B
// ---------------------------------------------------------------------------
__global__ __launch_bounds__(256) void k1_score(const float* __restrict__ q,
                                                const float* __restrict__ ks,
                                                const float* __restrict__ ka) {
    extern __shared__ float sm[];
    float* ksT  = sm;            // [16][132]
    float* kaT  = sm + 2112;     // [16][132]
    float* qrow = sm + 4224;     // [128*16]
    float* pbuf = sm + 6272;     // [8][128]
    float* dpa  = sm + 7296;     // [128][136]

    const int bh      = blockIdx.x >> 2;
    const int quarter = blockIdx.x & 3;
    const int tid = threadIdx.x;
    const float* qb  = q  + bh * 2048;
    const float* ksb = ks + bh * 2048;
    const float* kab = ka + bh * 2048;

    for (int i = tid; i < 2048; i += 256) {
        int srow = i >> 4, e = i & 15;
        ksT[e * 132 + srow] = ksb[i];
        kaT[e * 132 + srow] = kab[i];
        qrow[i] = qb[i];
    }
    __syncthreads();

    const int w = tid >> 5, l = tid & 31;

    // Phase A: full dpa[r][c] = relu(dot(q[r], ka[c]) * 0.25)
    for (int k = 0; k < 16; ++k) {
        int r = w * 16 + k;
        float qr[16];
#pragma unroll
        for (int j = 0; j < 4; ++j) {
            float4 v4 = *(const float4*)&qrow[r * 16 + 4 * j];
            qr[4 * j + 0] = v4.x; qr[4 * j + 1] = v4.y;
            qr[4 * j + 2] = v4.z; qr[4 * j + 3] = v4.w;
        }
        float a0 = 0.f, a1 = 0.f, a2 = 0.f, a3 = 0.f;
#pragma unroll
        for (int e = 0; e < 16; ++e) {
            float4 kk = *(const float4*)&kaT[e * 132 + 4 * l];
            a0 = fmaf(qr[e], kk.x, a0); a1 = fmaf(qr[e], kk.y, a1);
            a2 = fmaf(qr[e], kk.z, a2); a3 = fmaf(qr[e], kk.w, a3);
        }
        float4 o;
        o.x = fmaxf(a0 * 0.25f, 0.f); o.y = fmaxf(a1 * 0.25f, 0.f);
        o.z = fmaxf(a2 * 0.25f, 0.f); o.w = fmaxf(a3 * 0.25f, 0.f);
        *(float4*)&dpa[r * 136 + 4 * l] = o;
    }
    __syncthreads();

    // Phase B: this block handles rows [quarter*32, quarter*32+32), 4 per warp
    for (int k = 0; k < 4; ++k) {
        int r = quarter * 32 + w * 4 + k;
        float qr[16];
#pragma unroll
        for (int j = 0; j < 4; ++j) {
            float4 v4 = *(const float4*)&qrow[r * 16 + 4 * j];
            qr[4 * j + 0] = v4.x; qr[4 * j + 1] = v4.y;
            qr[4 * j + 2] = v4.z; qr[4 * j + 3] = v4.w;
        }
        float a0 = 0.f, a1 = 0.f, a2 = 0.f, a3 = 0.f;
#pragma unroll
        for (int e = 0; e < 16; ++e) {
            float4 kk = *(const float4*)&ksT[e * 132 + 4 * l];
            a0 = fmaf(qr[e], kk.x, a0); a1 = fmaf(qr[e], kk.y, a1);
            a2 = fmaf(qr[e], kk.z, a2); a3 = fmaf(qr[e], kk.w, a3);
        }
        // exact GELU on qk/4
        float x0 = a0 * 0.25f, x1 = a1 * 0.25f, x2 = a2 * 0.25f, x3 = a3 * 0.25f;
        a0 = x0 * normcdff(x0); a1 = x1 * normcdff(x1);
        a2 = x2 * normcdff(x2); a3 = x3 * normcdff(x3);
        // softmax over 128 (4 per lane)
        float mx = fmaxf(fmaxf(a0, a1), fmaxf(a2, a3));
#pragma unroll
        for (int o = 16; o; o >>= 1) mx = fmaxf(mx, __shfl_xor_sync(FULLMASK, mx, o));
        float p0 = __expf(a0 - mx), p1 = __expf(a1 - mx);
        float p2 = __expf(a2 - mx), p3 = __expf(a3 - mx);
        float ssum = p0 + p1 + p2 + p3;
#pragma unroll
        for (int o = 16; o; o >>= 1) ssum += __shfl_xor_sync(FULLMASK, ssum, o);
        float inv = 1.f / ssum;
        float4 pv = make_float4(p0 * inv, p1 * inv, p2 * inv, p3 * inv);
        *(float4*)&pbuf[w * 128 + 4 * l] = pv;
        __syncwarp();
        // score row = p @ dpa, scaled by 0.25
        float c0 = 0.f, c1 = 0.f, c2 = 0.f, c3 = 0.f;
#pragma unroll 4
        for (int s2 = 0; s2 < 128; ++s2) {
            float pvv = pbuf[w * 128 + s2];
            float4 dv = *(const float4*)&dpa[s2 * 136 + 4 * l];
            c0 = fmaf(pvv, dv.x, c0); c1 = fmaf(pvv, dv.y, c1);
            c2 = fmaf(pvv, dv.z, c2); c3 = fmaf(pvv, dv.w, c3);
        }
        float4 so = make_float4(c0 * 0.25f, c1 * 0.25f, c2 * 0.25f, c3 * 0.25f);
        *(float4*)&g_score[(bh * 128 + r) * 128 + 4 * l] = so;
        __syncwarp();
    }
}

// ---------------------------------------------------------------------------
// Kernel 2: per (b,r). Two warp-groups of 128 threads; group g handles heads
// h = 4g..4g+3. One thread per dd-row; Waa pre-scaled by log2(e) so the
// softmax runs in the exp2 domain with a single EX2 per element.
// grid = 1024 blocks, 256 threads; dynamic smem 51872 B
// ---------------------------------------------------------------------------
__global__ __launch_bounds__(256, 4) void k2_main(
    const float* __restrict__ cost_mat,
    const float* __restrict__ mix1_w, const float* __restrict__ mix1_b,
    const float* __restrict__ Waa,
    const float* __restrict__ mix2_w, const float* __restrict__ mix2_b,
    const float* __restrict__ edge_w, const float* __restrict__ edge_b,
    const float* __restrict__ ln_g,  const float* __restrict__ ln_b,
    const float* __restrict__ v, float* __restrict__ out) {
    extern __shared__ float sm[];
    float* waa_all = sm;            // [8][256]  (pre-scaled by log2 e)
    float* w1a_all = sm + 2048;     // [8][16]
    float* w1b_all = sm + 2176;     // [8][16]
    float* b1s_all = sm + 2304;     // [8][16]
    float* w2s_all = sm + 2432;     // [8][16]
    float* ews_all = sm + 2560;     // [8][16]
    float* b2_all  = sm + 2688;     // [8]
    float* costrow = sm + 2696;     // [128]
    float* lng     = sm + 2824;     // [128]
    float* lnb     = sm + 2952;     // [128]
    const int tid = threadIdx.x;
    const int g  = tid >> 7;        // warp group (0,1)
    const int c  = tid & 127;       // row owned by this thread
    const int gw = (tid >> 5) & 3;  // warp within group
    const int l  = tid & 31;

    float* ms1      = sm + 3080 + g * 4944;  // [128][20]
    float* aeT      = ms1 + 2560;            // [16][132]
    float* mixedrow = aeT + 2112;            // [128]
    float* edge     = mixedrow + 128;        // [128]
    float* Msm      = edge + 128;            // [4]

    const int br = blockIdx.x;
    const int b = br >> 7, r = br & 127;

    // ---- preload all weights / per-row constants ----
    for (int i = tid; i < 2048; i += 256) waa_all[i] = Waa[i] * L2E;
    if (tid < 128) {
        int h0 = tid >> 4, e0 = tid & 15;
        w1a_all[tid] = mix1_w[h0 * 32 + e0];
        w1b_all[tid] = mix1_w[h0 * 32 + 16 + e0];
        b1s_all[tid] = mix1_b[tid];
        w2s_all[tid] = mix2_w[tid];
        ews_all[tid] = edge_w[tid];
        costrow[tid] = cost_mat[br * 128 + tid];
        lng[tid] = ln_g[tid];
        lnb[tid] = ln_b[tid];
    }
    if (tid < 8) b2_all[tid] = mix2_b[tid];
    edge[c] = 0.f;
    __syncthreads();

    for (int hh = 0; hh < 4; ++hh) {
        const int h = g * 4 + hh;

        // ---- P1: ms1 row c, t-row (regs, log2-scaled), mixed score, tile max
        float sc = g_score[((b * KH + h) * KR + r) * KC + c];
        float co = costrow[c];
        float m[16];
#pragma unroll
        for (int e = 0; e < 16; ++e)
            m[e] = fmaxf(fmaf(sc, w1a_all[h * 16 + e],
                         fmaf(co, w1b_all[h * 16 + e], b1s_all[h * 16 + e])), 0.f);
#pragma unroll
        for (int j = 0; j < 4; ++j)
            *(float4*)&ms1[c * 20 + 4 * j] =
                make_float4(m[4 * j], m[4 * j + 1], m[4 * j + 2], m[4 * j + 3]);
        {   // mixed = ms1 . w2 + b2
            float mx = b2_all[h];
#pragma unroll
            for (int f = 0; f < 16; ++f) mx = fmaf(m[f], w2s_all[h * 16 + f], mx);
            mixedrow[c] = mx;
        }
        // tile max of ms1 (ms1 >= 0): warp-reduce row maxes
        {
            float rm = m[0];
#pragma unroll
            for (int e = 1; e < 16; ++e) rm = fmaxf(rm, m[e]);
#pragma unroll
            for (int o = 16; o; o >>= 1) rm = fmaxf(rm, __shfl_xor_sync(FULLMASK, rm, o));
            if (l == 0) Msm[gw] = rm;
        }
        // t[c][x] = sum_e m[e] * Waa_scaled[e][x], packed in pairs
        unsigned long long t2[8];
        {
            const ulonglong2* waa4 = (const ulonglong2*)(waa_all + h * 256);
            unsigned long long m02 = pk2(m[0], m[0]);
#pragma unroll
            for (int j = 0; j < 4; ++j) {
                ulonglong2 wv = waa4[j];
                t2[2 * j]     = mul2(m02, wv.x);
                t2[2 * j + 1] = mul2(m02, wv.y);
            }
#pragma unroll
            for (int f = 1; f < 16; ++f) {
                unsigned long long mf2 = pk2(m[f], m[f]);
#pragma unroll
                for (int j = 0; j < 4; ++j) {
                    ulonglong2 wv = waa4[f * 4 + j];
                    t2[2 * j]     = fma2(mf2, wv.x, t2[2 * j]);
                    t2[2 * j + 1] = fma2(mf2, wv.y, t2[2 * j + 1]);
                }
            }
        }
        // sum of relu(t) for the softmax upper bound (log2 domain)
        float srt = 0.f;
#pragma unroll
        for (int j = 0; j < 8; ++j) {
            float2 tf = upk2(t2[j]);
            srt += fmaxf(tf.x, 0.f) + fmaxf(tf.y, 0.f);
        }
        gbar(g);
        float M = fmaxf(fmaxf(Msm[0], Msm[1]), fmaxf(Msm[2], Msm[3]));
        float m_ub = M * srt;   // dd2[c][d] <= m_ub for all d
        const unsigned long long nmub2 = pk2(-m_ub, 0.f);

        // ---- P2: one-pass softmax(dd) @ ms1, all in registers ----
        unsigned long long vv2[8];
#pragma unroll
        for (int j = 0; j < 8; ++j) vv2[j] = 0ull;
        float s = 0.f;
#pragma unroll 2
        for (int d = 0; d < 128; ++d) {
            const float* mrow = &ms1[d * 20];     // broadcast across lanes
            ulonglong2 u0 = *(const ulonglong2*)&mrow[0];
            ulonglong2 u1 = *(const ulonglong2*)&mrow[4];
            ulonglong2 u2 = *(const ulonglong2*)&mrow[8];
            ulonglong2 u3 = *(const ulonglong2*)&mrow[12];
            unsigned long long da = fma2(t2[0], u0.x, nmub2);
            unsigned long long db = mul2(t2[1], u0.y);
            da = fma2(t2[2], u1.x, da); db = fma2(t2[3], u1.y, db);
            da = fma2(t2[4], u2.x, da); db = fma2(t2[5], u2.y, db);
            da = fma2(t2[6], u3.x, da); db = fma2(t2[7], u3.y, db);
            float2 fs = upk2(add2(da, db));
            float p = ex2(fs.x + fs.y);   // exp2(dd*log2e - m_ub)
            s += p;
            unsigned long long p2 = pk2(p, p);
            vv2[0] = fma2(p2, u0.x, vv2[0]); vv2[1] = fma2(p2, u0.y, vv2[1]);
            vv2[2] = fma2(p2, u1.x, vv2[2]); vv2[3] = fma2(p2, u1.y, vv2[3]);
            vv2[4] = fma2(p2, u2.x, vv2[4]); vv2[5] = fma2(p2, u2.y, vv2[5]);
            vv2[6] = fma2(p2, u3.x, vv2[6]); vv2[7] = fma2(p2, u3.y, vv2[7]);
        }
        {
            float inv = 1.f / s;
            unsigned long long inv2 = pk2(inv, inv);
#pragma unroll
            for (int j = 0; j < 8; ++j) {
                float2 vf = upk2(mul2(vv2[j], inv2));
                aeT[(2 * j) * 132 + c]     = vf.x;
                aeT[(2 * j + 1) * 132 + c] = vf.y;
            }
        }
        gbar(g);

        // ---- P3: LayerNorm over C; warp gw handles features 4gw..4gw+3 ----
#pragma unroll
        for (int ei = 0; ei < 4; ++ei) {
            int e = gw * 4 + ei;
            float x0 = aeT[e * 132 + l]      + ms1[l * 20 + e];
            float x1 = aeT[e * 132 + l + 32] + ms1[(l + 32) * 20 + e];
            float x2 = aeT[e * 132 + l + 64] + ms1[(l + 64) * 20 + e];
            float x3 = aeT[e * 132 + l + 96] + ms1[(l + 96) * 20 + e];
            float s1 = x0 + x1 + x2 + x3;
            float sq = x0 * x0 + x1 * x1 + x2 * x2 + x3 * x3;
#pragma unroll
            for (int o = 16; o; o >>= 1) {
                s1 += __shfl_xor_sync(FULLMASK, s1, o);
                sq += __shfl_xor_sync(FULLMASK, sq, o);
            }
            float mean = s1 * (1.f / 128.f);
            float var  = sq * (1.f / 128.f) - mean * mean;
            float rs = rsqrtf(var + 1e-5f);
            aeT[e * 132 + l]      = (x0 - mean) * rs * lng[l]      + lnb[l];
            aeT[e * 132 + l + 32] = (x1 - mean) * rs * lng[l + 32] + lnb[l + 32];
            aeT[e * 132 + l + 64] = (x2 - mean) * rs * lng[l + 64] + lnb[l + 64];
            aeT[e * 132 + l + 96] = (x3 - mean) * rs * lng[l + 96] + lnb[l + 96];
        }
        gbar(g);

        // ---- P4: edge accumulation + mixed softmax attention ----
        {
            float acc = edge[c];
#pragma unroll
            for (int e = 0; e < 16; ++e)
                acc = fmaf(aeT[e * 132 + c], ews_all[h * 16 + e], acc);
            edge[c] = acc;
        }
        {
            float m0 = mixedrow[l],      m1 = mixedrow[l + 32];
            float m2 = mixedrow[l + 64], m3 = mixedrow[l + 96];
            float mx = fmaxf(fmaxf(m0, m1), fmaxf(m2, m3));
#pragma unroll
            for (int o = 16; o; o >>= 1) mx = fmaxf(mx, __shfl_xor_sync(FULLMASK, mx, o));
            float p0 = __expf(m0 - mx), p1 = __expf(m1 - mx);
            float p2 = __expf(m2 - mx), p3 = __expf(m3 - mx);
            float ssum = p0 + p1 + p2 + p3;
#pragma unroll
            for (int o = 16; o; o >>= 1) ssum += __shfl_xor_sync(FULLMASK, ssum, o);
            float inv = 1.f / ssum;
            const float* vb = v + (b * KH + h) * KC * KDQ;
#pragma unroll
            for (int d0 = 0; d0 < 4; ++d0) {
                int dq = gw * 4 + d0;
                float a = p0 * vb[l * 16 + dq] + p1 * vb[(l + 32) * 16 + dq]
                        + p2 * vb[(l + 64) * 16 + dq] + p3 * vb[(l + 96) * 16 + dq];
#pragma unroll
                for (int o = 16; o; o >>= 1) a += __shfl_xor_sync(FULLMASK, a, o);
                if (l == 0)
                    out[(b * KR + r) * (KH * KDQ) + h * KDQ + dq] = a * inv;
            }
        }
        gbar(g);   // ms1/mixedrow reused next h
    }

    __syncthreads();
    if (tid < 128) {
        const float* e0 = sm + 3080 + 2560 + 2112 + 128;
        const float* e1 = sm + 3080 + 4944 + 2560 + 2112 + 128;
        out[KB * KR * KH * KDQ + br * 128 + tid] = e0[tid] + e1[tid] + edge_b[0];
    }
}

extern "C" void kernel_launch(void* const* d_in, const int* in_sizes, int n_in,
                              void* d_out, int out_size) {
    const float* q    = (const float*)d_in[0];
    const float* k_s  = (const float*)d_in[1];
    const float* k_a  = (const float*)d_in[2];
    const float* v    = (const float*)d_in[3];
    const float* cost = (const float*)d_in[4];
    const float* m1w  = (const float*)d_in[5];
    const float* m1b  = (const float*)d_in[6];
    const float* waa  = (const float*)d_in[7];
    const float* m2w  = (const float*)d_in[8];
    const float* m2b  = (const float*)d_in[9];
    const float* ew   = (const float*)d_in[10];
    const float* eb   = (const float*)d_in[11];
    const float* lng  = (const float*)d_in[12];
    const float* lnb  = (const float*)d_in[13];
    float* out = (float*)d_out;

    cudaFuncSetAttribute(k1_score, cudaFuncAttributeMaxDynamicSharedMemorySize, 98816);
    cudaFuncSetAttribute(k2_main,  cudaFuncAttributeMaxDynamicSharedMemorySize, 51872);

    k1_score<<<KB * KH * 4, 256, 98816>>>(q, k_s, k_a);
    k2_main<<<KB * KR, 256, 51872>>>(cost, m1w, m1b, waa, m2w, m2b, ew, eb,
                                     lng, lnb, v, out);
}

// round 7
// speedup vs baseline: 2.6928x; 1.2169x over previous
#include <cuda_runtime.h>
#include <cstdint>

#define FULLMASK 0xffffffffu
#define KB 8
#define KH 8
#define KR 128
#define KC 128
#define KDQ 16
#define L2E 1.4426950408889634f

__device__ float g_score[KB * KH * KR * KC];

__device__ __forceinline__ unsigned long long pk2(float x, float y) {
    unsigned long long r;
    asm("mov.b64 %0, {%1, %2};" : "=l"(r) : "f"(x), "f"(y));
    return r;
}
__device__ __forceinline__ float2 upk2(unsigned long long v) {
    float2 r;
    asm("mov.b64 {%0, %1}, %2;" : "=f"(r.x), "=f"(r.y) : "l"(v));
    return r;
}
__device__ __forceinline__ unsigned long long fma2(unsigned long long a,
                                                   unsigned long long b,
                                                   unsigned long long c) {
    unsigned long long d;
    asm("fma.rn.f32x2 %0, %1, %2, %3;" : "=l"(d) : "l"(a), "l"(b), "l"(c));
    return d;
}
__device__ __forceinline__ unsigned long long mul2(unsigned long long a,
                                                   unsigned long long b) {
    unsigned long long d;
    asm("mul.rn.f32x2 %0, %1, %2;" : "=l"(d) : "l"(a), "l"(b));
    return d;
}
__device__ __forceinline__ float ex2(float x) {
    float r;
    asm("ex2.approx.f32 %0, %1;" : "=f"(r) : "f"(x));
    return r;
}
// round fp32 -> tf32 (b32 with low mantissa cleared, round-to-nearest)
__device__ __forceinline__ uint32_t tf32r(float f) {
    uint32_t u;
    asm("cvt.rna.tf32.f32 %0, %1;" : "=r"(u) : "f"(f));
    return u;
}
// D += A(16x8) * B(8x8), tf32, fp32 accum (warp-collective)
__device__ __forceinline__ void mma8(float& c0, float& c1, float& c2, float& c3,
                                     uint32_t a0, uint32_t a1, uint32_t a2,
                                     uint32_t a3, uint32_t b0, uint32_t b1) {
    asm volatile(
        "mma.sync.aligned.m16n8k8.row.col.f32.tf32.tf32.f32 "
        "{%0,%1,%2,%3}, {%4,%5,%6,%7}, {%8,%9}, {%0,%1,%2,%3};"
        : "+f"(c0), "+f"(c1), "+f"(c2), "+f"(c3)
        : "r"(a0), "r"(a1), "r"(a2), "r"(a3), "r"(b0), "r"(b1));
}

// ---------------------------------------------------------------------------
// Kernel 1 (unchanged, proven): grid 256, 256 thr, smem 98816
// ---------------------------------------------------------------------------
__global__ __launch_bounds__(256) void k1_score(const float* __restrict__ q,
                                                const float* __restrict__ ks,
                                                const float* __restrict__ ka) {
    extern __shared__ float sm[];
    float* ksT  = sm;
    float* kaT  = sm + 2112;
    float* qrow = sm + 4224;
    float* pbuf = sm + 6272;
    float* dpa  = sm + 7296;

    const int bh      = blockIdx.x >> 2;
    const int quarter = blockIdx.x & 3;
    const int tid = threadIdx.x;
    const float* qb  = q  + bh * 2048;
    const float* ksb = ks + bh * 2048;
    const float* kab = ka + bh * 2048;

    for (int i = tid; i < 2048; i += 256) {
        int srow = i >> 4, e = i & 15;
        ksT[e * 132 + srow] = ksb[i];
        kaT[e * 132 + srow] = kab[i];
        qrow[i] = qb[i];
    }
    __syncthreads();

    const int w = tid >> 5, l = tid & 31;

    for (int k = 0; k < 16; ++k) {
        int r = w * 16 + k;
        float qr[16];
#pragma unroll
        for (int j = 0; j < 4; ++j) {
            float4 v4 = *(const float4*)&qrow[r * 16 + 4 * j];
            qr[4*j] = v4.x; qr[4*j+1] = v4.y; qr[4*j+2] = v4.z; qr[4*j+3] = v4.w;
        }
        float a0 = 0.f, a1 = 0.f, a2 = 0.f, a3 = 0.f;
#pragma unroll
        for (int e = 0; e < 16; ++e) {
            float4 kk = *(const float4*)&kaT[e * 132 + 4 * l];
            a0 = fmaf(qr[e], kk.x, a0); a1 = fmaf(qr[e], kk.y, a1);
            a2 = fmaf(qr[e], kk.z, a2); a3 = fmaf(qr[e], kk.w, a3);
        }
        float4 o;
        o.x = fmaxf(a0 * 0.25f, 0.f); o.y = fmaxf(a1 * 0.25f, 0.f);
        o.z = fmaxf(a2 * 0.25f, 0.f); o.w = fmaxf(a3 * 0.25f, 0.f);
        *(float4*)&dpa[r * 136 + 4 * l] = o;
    }
    __syncthreads();

    for (int k = 0; k < 4; ++k) {
        int r = quarter * 32 + w * 4 + k;
        float qr[16];
#pragma unroll
        for (int j = 0; j < 4; ++j) {
            float4 v4 = *(const float4*)&qrow[r * 16 + 4 * j];
            qr[4*j] = v4.x; qr[4*j+1] = v4.y; qr[4*j+2] = v4.z; qr[4*j+3] = v4.w;
        }
        float a0 = 0.f, a1 = 0.f, a2 = 0.f, a3 = 0.f;
#pragma unroll
        for (int e = 0; e < 16; ++e) {
            float4 kk = *(const float4*)&ksT[e * 132 + 4 * l];
            a0 = fmaf(qr[e], kk.x, a0); a1 = fmaf(qr[e], kk.y, a1);
            a2 = fmaf(qr[e], kk.z, a2); a3 = fmaf(qr[e], kk.w, a3);
        }
        float x0 = a0 * 0.25f, x1 = a1 * 0.25f, x2 = a2 * 0.25f, x3 = a3 * 0.25f;
        a0 = x0 * normcdff(x0); a1 = x1 * normcdff(x1);
        a2 = x2 * normcdff(x2); a3 = x3 * normcdff(x3);
        float mx = fmaxf(fmaxf(a0, a1), fmaxf(a2, a3));
#pragma unroll
        for (int o = 16; o; o >>= 1) mx = fmaxf(mx, __shfl_xor_sync(FULLMASK, mx, o));
        float p0 = __expf(a0 - mx), p1 = __expf(a1 - mx);
        float p2 = __expf(a2 - mx), p3 = __expf(a3 - mx);
        float ssum = p0 + p1 + p2 + p3;
#pragma unroll
        for (int o = 16; o; o >>= 1) ssum += __shfl_xor_sync(FULLMASK, ssum, o);
        float inv = 1.f / ssum;
        *(float4*)&pbuf[w * 128 + 4 * l] = make_float4(p0*inv, p1*inv, p2*inv, p3*inv);
        __syncwarp();
        float c0 = 0.f, c1 = 0.f, c2 = 0.f, c3 = 0.f;
#pragma unroll 4
        for (int s2 = 0; s2 < 128; ++s2) {
            float pvv = pbuf[w * 128 + s2];
            float4 dv = *(const float4*)&dpa[s2 * 136 + 4 * l];
            c0 = fmaf(pvv, dv.x, c0); c1 = fmaf(pvv, dv.y, c1);
            c2 = fmaf(pvv, dv.z, c2); c3 = fmaf(pvv, dv.w, c3);
        }
        *(float4*)&g_score[(bh * 128 + r) * 128 + 4 * l] =
            make_float4(c0*0.25f, c1*0.25f, c2*0.25f, c3*0.25f);
        __syncwarp();
    }
}

// ---------------------------------------------------------------------------
// Kernel 2: per (b,r); depth-attention GEMMs on mma.sync tf32 tensor cores.
// 8 warps; warp w owns dd rows 16w..16w+15. grid 1024, 256 thr, smem 86080.
// ---------------------------------------------------------------------------
__global__ __launch_bounds__(256) void k2_main(
    const float* __restrict__ cost_mat,
    const float* __restrict__ mix1_w, const float* __restrict__ mix1_b,
    const float* __restrict__ Waa,
    const float* __restrict__ mix2_w, const float* __restrict__ mix2_b,
    const float* __restrict__ edge_w, const float* __restrict__ edge_b,
    const float* __restrict__ ln_g,  const float* __restrict__ ln_b,
    const float* __restrict__ v, float* __restrict__ out) {
    extern __shared__ float sm[];
    float* waa_all  = sm;            // [8][256]  L2E-scaled
    float* w1a_all  = sm + 2048;
    float* w1b_all  = sm + 2176;
    float* b1s_all  = sm + 2304;
    float* w2s_all  = sm + 2432;
    float* ews_all  = sm + 2560;
    float* b2_all   = sm + 2688;     // [8]
    float* costrow  = sm + 2696;
    float* lng      = sm + 2824;
    float* lnb      = sm + 2952;
    float* mixedrow = sm + 3080;
    float* edge     = sm + 3208;
    float* Msm      = sm + 3336;     // [8]
    float* srt_sm   = sm + 3344;     // [128]
    float* ms1      = sm + 3472;     // [128][20] exact fp32
    float* tsm      = sm + 6032;     // [128][20] tf32-rounded
    float* ms1T     = sm + 8592;     // [16][132] tf32-rounded
    float* aeT      = sm + 10704;    // [16][132]
    float* dwb_all  = sm + 12816;    // 8 x [16][68]

    const int tid = threadIdx.x;
    const int w = tid >> 5, l = tid & 31;
    const int c = tid & 127;
    const int half = tid >> 7;
    const int g = l >> 2, tq = l & 3;
    const int Rw = w * 16;
    float* dwb = dwb_all + w * 1088;

    const int br = blockIdx.x;
    const int b = br >> 7, r = br & 127;

    for (int i = tid; i < 2048; i += 256) waa_all[i] = Waa[i] * L2E;
    if (tid < 128) {
        int h0 = tid >> 4, e0 = tid & 15;
        w1a_all[tid] = mix1_w[h0 * 32 + e0];
        w1b_all[tid] = mix1_w[h0 * 32 + 16 + e0];
        b1s_all[tid] = mix1_b[tid];
        w2s_all[tid] = mix2_w[tid];
        ews_all[tid] = edge_w[tid];
        costrow[tid] = cost_mat[br * 128 + tid];
        lng[tid] = ln_g[tid];
        lnb[tid] = ln_b[tid];
        edge[tid] = 0.f;
    }
    if (tid < 8) b2_all[tid] = mix2_b[tid];
    __syncthreads();

    for (int h = 0; h < KH; ++h) {
        // ---- P1: ms1 row c; tiles; t; mixed; bound ----
        float sc = g_score[((b * KH + h) * KR + r) * KC + c];
        float co = costrow[c];
        float m[16];
#pragma unroll
        for (int e = 0; e < 16; ++e)
            m[e] = fmaxf(fmaf(sc, w1a_all[h*16+e],
                         fmaf(co, w1b_all[h*16+e], b1s_all[h*16+e])), 0.f);
        {
            float rm = m[0];
#pragma unroll
            for (int e = 1; e < 16; ++e) rm = fmaxf(rm, m[e]);
#pragma unroll
            for (int o = 16; o; o >>= 1) rm = fmaxf(rm, __shfl_xor_sync(FULLMASK, rm, o));
            if (l == 0) Msm[w] = rm;
        }
        if (half == 0) {
            // exact ms1 tile (dd-B source + LN residual)
#pragma unroll
            for (int j = 0; j < 4; ++j)
                *(float4*)&ms1[c * 20 + 4 * j] =
                    make_float4(m[4*j], m[4*j+1], m[4*j+2], m[4*j+3]);
            // t = ms1 @ (Waa * L2E)
            unsigned long long t2[8];
            const ulonglong2* waa4 = (const ulonglong2*)(waa_all + h * 256);
            unsigned long long m02 = pk2(m[0], m[0]);
#pragma unroll
            for (int j = 0; j < 4; ++j) {
                ulonglong2 wv = waa4[j];
                t2[2*j] = mul2(m02, wv.x); t2[2*j+1] = mul2(m02, wv.y);
            }
#pragma unroll
            for (int f = 1; f < 16; ++f) {
                unsigned long long mf2 = pk2(m[f], m[f]);
#pragma unroll
                for (int j = 0; j < 4; ++j) {
                    ulonglong2 wv = waa4[f * 4 + j];
                    t2[2*j]   = fma2(mf2, wv.x, t2[2*j]);
                    t2[2*j+1] = fma2(mf2, wv.y, t2[2*j+1]);
                }
            }
            // round t to tf32; srt from rounded values (keeps bound valid)
            float srt = 0.f;
            float tr[16];
#pragma unroll
            for (int j = 0; j < 8; ++j) {
                float2 tv = upk2(t2[j]);
                float f0 = __uint_as_float(tf32r(tv.x));
                float f1 = __uint_as_float(tf32r(tv.y));
                srt += fmaxf(f0, 0.f) + fmaxf(f1, 0.f);
                tr[2*j] = f0; tr[2*j+1] = f1;
            }
#pragma unroll
            for (int j = 0; j < 4; ++j)
                *(float4*)&tsm[c * 20 + 4 * j] =
                    make_float4(tr[4*j], tr[4*j+1], tr[4*j+2], tr[4*j+3]);
            srt_sm[c] = srt;
        } else {
            // transposed tf32 ms1 (ae-B source)
#pragma unroll
            for (int e = 0; e < 16; ++e)
                ms1T[e * 132 + c] = __uint_as_float(tf32r(m[e]));
            float mx = b2_all[h];
#pragma unroll
            for (int f = 0; f < 16; ++f) mx = fmaf(m[f], w2s_all[h*16+f], mx);
            mixedrow[c] = mx;
        }
        __syncthreads();

        const float Mmax =
            fmaxf(fmaxf(fmaxf(Msm[0], Msm[1]), fmaxf(Msm[2], Msm[3])),
                  fmaxf(fmaxf(Msm[4], Msm[5]), fmaxf(Msm[6], Msm[7])));

        // ---- P2: dd = t @ ms1^T (mma), softmax, ae = dw @ ms1 (mma) ----
        uint32_t at[8];
#pragma unroll
        for (int k2 = 0; k2 < 2; ++k2) {
            at[k2*4+0] = __float_as_uint(tsm[(Rw+g)  *20 + k2*8 + tq]);
            at[k2*4+1] = __float_as_uint(tsm[(Rw+g+8)*20 + k2*8 + tq]);
            at[k2*4+2] = __float_as_uint(tsm[(Rw+g)  *20 + k2*8 + tq + 4]);
            at[k2*4+3] = __float_as_uint(tsm[(Rw+g+8)*20 + k2*8 + tq + 4]);
        }
        const float mub0 = Mmax * srt_sm[Rw + g];
        const float mub1 = Mmax * srt_sm[Rw + g + 8];
        float sg0 = 0.f, sg1 = 0.f;
        float ae[8];
#pragma unroll
        for (int i = 0; i < 8; ++i) ae[i] = 0.f;

#pragma unroll
        for (int chunk = 0; chunk < 2; ++chunk) {
#pragma unroll
            for (int jj = 0; jj < 8; ++jj) {
                int j = chunk * 8 + jj;
                float c0 = -mub0, c1 = -mub0, c2 = -mub1, c3 = -mub1;
#pragma unroll
                for (int k2 = 0; k2 < 2; ++k2) {
                    int base = (8*j + g) * 20 + k2*8 + tq;
                    uint32_t b0 = tf32r(ms1[base]);
                    uint32_t b1 = tf32r(ms1[base + 4]);
                    mma8(c0, c1, c2, c3, at[k2*4], at[k2*4+1], at[k2*4+2],
                         at[k2*4+3], b0, b1);
                }
                float p0 = ex2(c0), p1 = ex2(c1), p2 = ex2(c2), p3 = ex2(c3);
                sg0 += p0 + p1; sg1 += p2 + p3;
                *(float2*)&dwb[g      *68 + jj*8 + 2*tq] = make_float2(p0, p1);
                *(float2*)&dwb[(g + 8)*68 + jj*8 + 2*tq] = make_float2(p2, p3);
            }
            __syncwarp();
#pragma unroll
            for (int kk = 0; kk < 8; ++kk) {
                uint32_t a0 = __float_as_uint(dwb[g      *68 + kk*8 + tq]);
                uint32_t a1 = __float_as_uint(dwb[(g + 8)*68 + kk*8 + tq]);
                uint32_t a2 = __float_as_uint(dwb[g      *68 + kk*8 + tq + 4]);
                uint32_t a3 = __float_as_uint(dwb[(g + 8)*68 + kk*8 + tq + 4]);
                int dbase = chunk * 64 + kk * 8;
#pragma unroll
                for (int nt = 0; nt < 2; ++nt) {
                    uint32_t b0 = __float_as_uint(ms1T[(8*nt+g)*132 + dbase + tq]);
                    uint32_t b1 = __float_as_uint(ms1T[(8*nt+g)*132 + dbase + tq + 4]);
                    mma8(ae[nt*4], ae[nt*4+1], ae[nt*4+2], ae[nt*4+3],
                         a0, a1, a2, a3, b0, b1);
                }
            }
            __syncwarp();
        }
        // row sums (quad reduce) and normalized aeT stores
        sg0 += __shfl_xor_sync(FULLMASK, sg0, 1);
        sg0 += __shfl_xor_sync(FULLMASK, sg0, 2);
        sg1 += __shfl_xor_sync(FULLMASK, sg1, 1);
        sg1 += __shfl_xor_sync(FULLMASK, sg1, 2);
        const float inv0 = 1.f / sg0, inv1 = 1.f / sg1;
#pragma unroll
        for (int nt = 0; nt < 2; ++nt) {
            aeT[(8*nt + 2*tq)    *132 + Rw + g]     = ae[nt*4]   * inv0;
            aeT[(8*nt + 2*tq + 1)*132 + Rw + g]     = ae[nt*4+1] * inv0;
            aeT[(8*nt + 2*tq)    *132 + Rw + g + 8] = ae[nt*4+2] * inv1;
            aeT[(8*nt + 2*tq + 1)*132 + Rw + g + 8] = ae[nt*4+3] * inv1;
        }
        __syncthreads();

        // ---- P3: LayerNorm over C; warp w handles features w, w+8 ----
#pragma unroll
        for (int ei = 0; ei < 2; ++ei) {
            int e = w + ei * 8;
            float x0 = aeT[e * 132 + l]      + ms1[l * 20 + e];
            float x1 = aeT[e * 132 + l + 32] + ms1[(l + 32) * 20 + e];
            float x2 = aeT[e * 132 + l + 64] + ms1[(l + 64) * 20 + e];
            float x3 = aeT[e * 132 + l + 96] + ms1[(l + 96) * 20 + e];
            float s1 = x0 + x1 + x2 + x3;
            float sq = x0 * x0 + x1 * x1 + x2 * x2 + x3 * x3;
#pragma unroll
            for (int o = 16; o; o >>= 1) {
                s1 += __shfl_xor_sync(FULLMASK, s1, o);
                sq += __shfl_xor_sync(FULLMASK, sq, o);
            }
            float mean = s1 * (1.f / 128.f);
            float var  = sq * (1.f / 128.f) - mean * mean;
            float rs = rsqrtf(var + 1e-5f);
            aeT[e * 132 + l]      = (x0 - mean) * rs * lng[l]      + lnb[l];
            aeT[e * 132 + l + 32] = (x1 - mean) * rs * lng[l + 32] + lnb[l + 32];
            aeT[e * 132 + l + 64] = (x2 - mean) * rs * lng[l + 64] + lnb[l + 64];
            aeT[e * 132 + l + 96] = (x3 - mean) * rs * lng[l + 96] + lnb[l + 96];
        }
        __syncthreads();

        // ---- P4: edge (half 0) + mixed softmax attention (half 1) ----
        if (half == 0) {
            float acc = edge[c];
#pragma unroll
            for (int e = 0; e < 16; ++e)
                acc = fmaf(aeT[e * 132 + c], ews_all[h * 16 + e], acc);
            edge[c] = acc;
        } else {
            int ww = w - 4;
            float m0 = mixedrow[l],      m1 = mixedrow[l + 32];
            float m2 = mixedrow[l + 64], m3 = mixedrow[l + 96];
            float mx = fmaxf(fmaxf(m0, m1), fmaxf(m2, m3));
#pragma unroll
            for (int o = 16; o; o >>= 1) mx = fmaxf(mx, __shfl_xor_sync(FULLMASK, mx, o));
            float p0 = __expf(m0 - mx), p1 = __expf(m1 - mx);
            float p2 = __expf(m2 - mx), p3 = __expf(m3 - mx);
            float ssum = p0 + p1 + p2 + p3;
#pragma unroll
            for (int o = 16; o; o >>= 1) ssum += __shfl_xor_sync(FULLMASK, ssum, o);
            float inv = 1.f / ssum;
            const float* vb = v + (b * KH + h) * KC * KDQ;
#pragma unroll
            for (int d0 = 0; d0 < 4; ++d0) {
                int dq = ww * 4 + d0;
                float a = p0 * vb[l * 16 + dq] + p1 * vb[(l + 32) * 16 + dq]
                        + p2 * vb[(l + 64) * 16 + dq] + p3 * vb[(l + 96) * 16 + dq];
#pragma unroll
                for (int o = 16; o; o >>= 1) a += __shfl_xor_sync(FULLMASK, a, o);
                if (l == 0)
                    out[(b * KR + r) * (KH * KDQ) + h * KDQ + dq] = a * inv;
            }
        }
        __syncthreads();
    }

    if (tid < 128)
        out[KB * KR * KH * KDQ + br * 128 + tid] = edge[tid] + edge_b[0];
}

extern "C" void kernel_launch(void* const* d_in, const int* in_sizes, int n_in,
                              void* d_out, int out_size) {
    const float* q    = (const float*)d_in[0];
    const float* k_s  = (const float*)d_in[1];
    const float* k_a  = (const float*)d_in[2];
    const float* v    = (const float*)d_in[3];
    const float* cost = (const float*)d_in[4];
    const float* m1w  = (const float*)d_in[5];
    const float* m1b  = (const float*)d_in[6];
    const float* waa  = (const float*)d_in[7];
    const float* m2w  = (const float*)d_in[8];
    const float* m2b  = (const float*)d_in[9];
    const float* ew   = (const float*)d_in[10];
    const float* eb   = (const float*)d_in[11];
    const float* lng  = (const float*)d_in[12];
    const float* lnb  = (const float*)d_in[13];
    float* out = (float*)d_out;

    cudaFuncSetAttribute(k1_score, cudaFuncAttributeMaxDynamicSharedMemorySize, 98816);
    cudaFuncSetAttribute(k2_main,  cudaFuncAttributeMaxDynamicSharedMemorySize, 86080);

    k1_score<<<KB * KH * 4, 256, 98816>>>(q, k_s, k_a);
    k2_main<<<KB * KR, 256, 86080>>>(cost, m1w, m1b, waa, m2w, m2b, ew, eb,
                                     lng, lnb, v, out);
}

// round 8
// speedup vs baseline: 3.0269x; 1.1241x over previous
#include <cuda_runtime.h>
#include <cstdint>

#define FULLMASK 0xffffffffu
#define KB 8
#define KH 8
#define KR 128
#define KC 128
#define KDQ 16
#define L2E 1.4426950408889634f

__device__ float g_score[KB * KH * KR * KC];

__device__ __forceinline__ unsigned long long pk2(float x, float y) {
    unsigned long long r;
    asm("mov.b64 %0, {%1, %2};" : "=l"(r) : "f"(x), "f"(y));
    return r;
}
__device__ __forceinline__ float2 upk2(unsigned long long v) {
    float2 r;
    asm("mov.b64 {%0, %1}, %2;" : "=f"(r.x), "=f"(r.y) : "l"(v));
    return r;
}
__device__ __forceinline__ unsigned long long fma2(unsigned long long a,
                                                   unsigned long long b,
                                                   unsigned long long c) {
    unsigned long long d;
    asm("fma.rn.f32x2 %0, %1, %2, %3;" : "=l"(d) : "l"(a), "l"(b), "l"(c));
    return d;
}
__device__ __forceinline__ unsigned long long mul2(unsigned long long a,
                                                   unsigned long long b) {
    unsigned long long d;
    asm("mul.rn.f32x2 %0, %1, %2;" : "=l"(d) : "l"(a), "l"(b));
    return d;
}
__device__ __forceinline__ float ex2(float x) {
    float r;
    asm("ex2.approx.f32 %0, %1;" : "=f"(r) : "f"(x));
    return r;
}
__device__ __forceinline__ uint32_t tf32r(float f) {
    uint32_t u;
    asm("cvt.rna.tf32.f32 %0, %1;" : "=r"(u) : "f"(f));
    return u;
}
__device__ __forceinline__ void mma8(float& c0, float& c1, float& c2, float& c3,
                                     uint32_t a0, uint32_t a1, uint32_t a2,
                                     uint32_t a3, uint32_t b0, uint32_t b1) {
    asm volatile(
        "mma.sync.aligned.m16n8k8.row.col.f32.tf32.tf32.f32 "
        "{%0,%1,%2,%3}, {%4,%5,%6,%7}, {%8,%9}, {%0,%1,%2,%3};"
        : "+f"(c0), "+f"(c1), "+f"(c2), "+f"(c3)
        : "r"(a0), "r"(a1), "r"(a2), "r"(a3), "r"(b0), "r"(b1));
}

// ---------------------------------------------------------------------------
// Kernel 1 (unchanged, proven): grid 256, 256 thr, smem 98816
// ---------------------------------------------------------------------------
__global__ __launch_bounds__(256) void k1_score(const float* __restrict__ q,
                                                const float* __restrict__ ks,
                                                const float* __restrict__ ka) {
    extern __shared__ float sm[];
    float* ksT  = sm;
    float* kaT  = sm + 2112;
    float* qrow = sm + 4224;
    float* pbuf = sm + 6272;
    float* dpa  = sm + 7296;

    const int bh      = blockIdx.x >> 2;
    const int quarter = blockIdx.x & 3;
    const int tid = threadIdx.x;
    const float* qb  = q  + bh * 2048;
    const float* ksb = ks + bh * 2048;
    const float* kab = ka + bh * 2048;

    for (int i = tid; i < 2048; i += 256) {
        int srow = i >> 4, e = i & 15;
        ksT[e * 132 + srow] = ksb[i];
        kaT[e * 132 + srow] = kab[i];
        qrow[i] = qb[i];
    }
    __syncthreads();

    const int w = tid >> 5, l = tid & 31;

    for (int k = 0; k < 16; ++k) {
        int r = w * 16 + k;
        float qr[16];
#pragma unroll
        for (int j = 0; j < 4; ++j) {
            float4 v4 = *(const float4*)&qrow[r * 16 + 4 * j];
            qr[4*j] = v4.x; qr[4*j+1] = v4.y; qr[4*j+2] = v4.z; qr[4*j+3] = v4.w;
        }
        float a0 = 0.f, a1 = 0.f, a2 = 0.f, a3 = 0.f;
#pragma unroll
        for (int e = 0; e < 16; ++e) {
            float4 kk = *(const float4*)&kaT[e * 132 + 4 * l];
            a0 = fmaf(qr[e], kk.x, a0); a1 = fmaf(qr[e], kk.y, a1);
            a2 = fmaf(qr[e], kk.z, a2); a3 = fmaf(qr[e], kk.w, a3);
        }
        float4 o;
        o.x = fmaxf(a0 * 0.25f, 0.f); o.y = fmaxf(a1 * 0.25f, 0.f);
        o.z = fmaxf(a2 * 0.25f, 0.f); o.w = fmaxf(a3 * 0.25f, 0.f);
        *(float4*)&dpa[r * 136 + 4 * l] = o;
    }
    __syncthreads();

    for (int k = 0; k < 4; ++k) {
        int r = quarter * 32 + w * 4 + k;
        float qr[16];
#pragma unroll
        for (int j = 0; j < 4; ++j) {
            float4 v4 = *(const float4*)&qrow[r * 16 + 4 * j];
            qr[4*j] = v4.x; qr[4*j+1] = v4.y; qr[4*j+2] = v4.z; qr[4*j+3] = v4.w;
        }
        float a0 = 0.f, a1 = 0.f, a2 = 0.f, a3 = 0.f;
#pragma unroll
        for (int e = 0; e < 16; ++e) {
            float4 kk = *(const float4*)&ksT[e * 132 + 4 * l];
            a0 = fmaf(qr[e], kk.x, a0); a1 = fmaf(qr[e], kk.y, a1);
            a2 = fmaf(qr[e], kk.z, a2); a3 = fmaf(qr[e], kk.w, a3);
        }
        float x0 = a0 * 0.25f, x1 = a1 * 0.25f, x2 = a2 * 0.25f, x3 = a3 * 0.25f;
        a0 = x0 * normcdff(x0); a1 = x1 * normcdff(x1);
        a2 = x2 * normcdff(x2); a3 = x3 * normcdff(x3);
        float mx = fmaxf(fmaxf(a0, a1), fmaxf(a2, a3));
#pragma unroll
        for (int o = 16; o; o >>= 1) mx = fmaxf(mx, __shfl_xor_sync(FULLMASK, mx, o));
        float p0 = __expf(a0 - mx), p1 = __expf(a1 - mx);
        float p2 = __expf(a2 - mx), p3 = __expf(a3 - mx);
        float ssum = p0 + p1 + p2 + p3;
#pragma unroll
        for (int o = 16; o; o >>= 1) ssum += __shfl_xor_sync(FULLMASK, ssum, o);
        float inv = 1.f / ssum;
        *(float4*)&pbuf[w * 128 + 4 * l] = make_float4(p0*inv, p1*inv, p2*inv, p3*inv);
        __syncwarp();
        float c0 = 0.f, c1 = 0.f, c2 = 0.f, c3 = 0.f;
#pragma unroll 4
        for (int s2 = 0; s2 < 128; ++s2) {
            float pvv = pbuf[w * 128 + s2];
            float4 dv = *(const float4*)&dpa[s2 * 136 + 4 * l];
            c0 = fmaf(pvv, dv.x, c0); c1 = fmaf(pvv, dv.y, c1);
            c2 = fmaf(pvv, dv.z, c2); c3 = fmaf(pvv, dv.w, c3);
        }
        *(float4*)&g_score[(bh * 128 + r) * 128 + 4 * l] =
            make_float4(c0*0.25f, c1*0.25f, c2*0.25f, c3*0.25f);
        __syncwarp();
    }
}

// ---------------------------------------------------------------------------
// Kernel 2: per (b,r); fused dd->softmax->ae on mma.sync tf32, with
// in-register C->A fragment conversion (no SMEM staging).
// grid 1024, 256 thr; dynamic smem 61504 B -> 3 CTAs/SM.
// ---------------------------------------------------------------------------
__global__ __launch_bounds__(256, 3) void k2_main(
    const float* __restrict__ cost_mat,
    const float* __restrict__ mix1_w, const float* __restrict__ mix1_b,
    const float* __restrict__ Waa,
    const float* __restrict__ mix2_w, const float* __restrict__ mix2_b,
    const float* __restrict__ edge_w, const float* __restrict__ edge_b,
    const float* __restrict__ ln_g,  const float* __restrict__ ln_b,
    const float* __restrict__ v, float* __restrict__ out) {
    extern __shared__ float sm[];
    float* waa_all  = sm;            // [8][256]  L2E-scaled
    float* w1a_all  = sm + 2048;
    float* w1b_all  = sm + 2176;
    float* b1s_all  = sm + 2304;
    float* w2s_all  = sm + 2432;
    float* ews_all  = sm + 2560;
    float* b2_all   = sm + 2688;     // [8]
    float* costrow  = sm + 2696;
    float* lng      = sm + 2824;
    float* lnb      = sm + 2952;
    float* mixedrow = sm + 3080;
    float* edge     = sm + 3208;
    float* Msm      = sm + 3336;     // [8]
    float* srt_sm   = sm + 3344;     // [128]
    float* ms1      = sm + 3472;     // [128][20] exact fp32 (LN residual)
    float* ms1r     = sm + 6032;     // [128][20] tf32-rounded (dd B)
    float* tsm      = sm + 8592;     // [128][20] tf32-rounded t (dd A)
    float* ms1T     = sm + 11152;    // [16][132] tf32-rounded (ae B)
    float* aeT      = sm + 13264;    // [16][132]

    const int tid = threadIdx.x;
    const int w = tid >> 5, l = tid & 31;
    const int c = tid & 127;
    const int half = tid >> 7;
    const int g = l >> 2, tq = l & 3;
    const int qbase = l & ~3;
    const int Rw = w * 16;

    const int br = blockIdx.x;
    const int b = br >> 7, r = br & 127;

    for (int i = tid; i < 2048; i += 256) waa_all[i] = Waa[i] * L2E;
    if (tid < 128) {
        int h0 = tid >> 4, e0 = tid & 15;
        w1a_all[tid] = mix1_w[h0 * 32 + e0];
        w1b_all[tid] = mix1_w[h0 * 32 + 16 + e0];
        b1s_all[tid] = mix1_b[tid];
        w2s_all[tid] = mix2_w[tid];
        ews_all[tid] = edge_w[tid];
        costrow[tid] = cost_mat[br * 128 + tid];
        lng[tid] = ln_g[tid];
        lnb[tid] = ln_b[tid];
        edge[tid] = 0.f;
    }
    if (tid < 8) b2_all[tid] = mix2_b[tid];
    __syncthreads();

    for (int h = 0; h < KH; ++h) {
        // ---- P1: ms1 row c; tiles; t; mixed; bound ----
        float sc = g_score[((b * KH + h) * KR + r) * KC + c];
        float co = costrow[c];
        float m[16];
#pragma unroll
        for (int e = 0; e < 16; ++e)
            m[e] = fmaxf(fmaf(sc, w1a_all[h*16+e],
                         fmaf(co, w1b_all[h*16+e], b1s_all[h*16+e])), 0.f);
        {
            float rm = m[0];
#pragma unroll
            for (int e = 1; e < 16; ++e) rm = fmaxf(rm, m[e]);
#pragma unroll
            for (int o = 16; o; o >>= 1) rm = fmaxf(rm, __shfl_xor_sync(FULLMASK, rm, o));
            if (l == 0) Msm[w] = rm;
        }
        if (half == 0) {
            // exact ms1 (LN residual) + rounded ms1r (dd B source)
#pragma unroll
            for (int j = 0; j < 4; ++j) {
                *(float4*)&ms1[c * 20 + 4 * j] =
                    make_float4(m[4*j], m[4*j+1], m[4*j+2], m[4*j+3]);
                float4 mr;
                mr.x = __uint_as_float(tf32r(m[4*j]));
                mr.y = __uint_as_float(tf32r(m[4*j+1]));
                mr.z = __uint_as_float(tf32r(m[4*j+2]));
                mr.w = __uint_as_float(tf32r(m[4*j+3]));
                *(float4*)&ms1r[c * 20 + 4 * j] = mr;
            }
            // t = ms1 @ (Waa * L2E)
            unsigned long long t2[8];
            const ulonglong2* waa4 = (const ulonglong2*)(waa_all + h * 256);
            unsigned long long m02 = pk2(m[0], m[0]);
#pragma unroll
            for (int j = 0; j < 4; ++j) {
                ulonglong2 wv = waa4[j];
                t2[2*j] = mul2(m02, wv.x); t2[2*j+1] = mul2(m02, wv.y);
            }
#pragma unroll
            for (int f = 1; f < 16; ++f) {
                unsigned long long mf2 = pk2(m[f], m[f]);
#pragma unroll
                for (int j = 0; j < 4; ++j) {
                    ulonglong2 wv = waa4[f * 4 + j];
                    t2[2*j]   = fma2(mf2, wv.x, t2[2*j]);
                    t2[2*j+1] = fma2(mf2, wv.y, t2[2*j+1]);
                }
            }
            float srt = 0.f;
            float tr[16];
#pragma unroll
            for (int j = 0; j < 8; ++j) {
                float2 tv = upk2(t2[j]);
                float f0 = __uint_as_float(tf32r(tv.x));
                float f1 = __uint_as_float(tf32r(tv.y));
                srt += fmaxf(f0, 0.f) + fmaxf(f1, 0.f);
                tr[2*j] = f0; tr[2*j+1] = f1;
            }
#pragma unroll
            for (int j = 0; j < 4; ++j)
                *(float4*)&tsm[c * 20 + 4 * j] =
                    make_float4(tr[4*j], tr[4*j+1], tr[4*j+2], tr[4*j+3]);
            srt_sm[c] = srt;
        } else {
            // transposed tf32 ms1 (ae B source) + mixed score
#pragma unroll
            for (int e = 0; e < 16; ++e)
                ms1T[e * 132 + c] = __uint_as_float(tf32r(m[e]));
            float mx = b2_all[h];
#pragma unroll
            for (int f = 0; f < 16; ++f) mx = fmaf(m[f], w2s_all[h*16+f], mx);
            mixedrow[c] = mx;
        }
        __syncthreads();

        const float Mmax =
            fmaxf(fmaxf(fmaxf(Msm[0], Msm[1]), fmaxf(Msm[2], Msm[3])),
                  fmaxf(fmaxf(Msm[4], Msm[5]), fmaxf(Msm[6], Msm[7])));

        // ---- P2: fused dd-mma -> ex2 -> shuffle-convert -> ae-mma ----
        uint32_t at[8];
#pragma unroll
        for (int k2 = 0; k2 < 2; ++k2) {
            at[k2*4+0] = __float_as_uint(tsm[(Rw+g)  *20 + k2*8 + tq]);
            at[k2*4+1] = __float_as_uint(tsm[(Rw+g+8)*20 + k2*8 + tq]);
            at[k2*4+2] = __float_as_uint(tsm[(Rw+g)  *20 + k2*8 + tq + 4]);
            at[k2*4+3] = __float_as_uint(tsm[(Rw+g+8)*20 + k2*8 + tq + 4]);
        }
        const float mub0 = Mmax * srt_sm[Rw + g];
        const float mub1 = Mmax * srt_sm[Rw + g + 8];
        const int s0 = qbase + (tq >> 1), s1 = s0 + 2;
        const bool odd = tq & 1;
        float sg0 = 0.f, sg1 = 0.f;
        float ae[8];
#pragma unroll
        for (int i = 0; i < 8; ++i) ae[i] = 0.f;

#pragma unroll
        for (int j = 0; j < 16; ++j) {
            float c0 = -mub0, c1 = -mub0, c2 = -mub1, c3 = -mub1;
#pragma unroll
            for (int k2 = 0; k2 < 2; ++k2) {
                int base = (8*j + g) * 20 + k2*8 + tq;
                uint32_t b0 = __float_as_uint(ms1r[base]);
                uint32_t b1 = __float_as_uint(ms1r[base + 4]);
                mma8(c0, c1, c2, c3, at[k2*4], at[k2*4+1], at[k2*4+2],
                     at[k2*4+3], b0, b1);
            }
            float p0 = ex2(c0), p1 = ex2(c1), p2 = ex2(c2), p3 = ex2(c3);
            sg0 += p0 + p1; sg1 += p2 + p3;
            // C-layout (cols 2tq,2tq+1) -> A-layout (cols tq, tq+4), intra-quad
            float u0 = __shfl_sync(FULLMASK, p0, s0);
            float u1 = __shfl_sync(FULLMASK, p1, s0);
            float v0 = __shfl_sync(FULLMASK, p0, s1);
            float v1 = __shfl_sync(FULLMASK, p1, s1);
            float u2 = __shfl_sync(FULLMASK, p2, s0);
            float u3 = __shfl_sync(FULLMASK, p3, s0);
            float v2 = __shfl_sync(FULLMASK, p2, s1);
            float v3 = __shfl_sync(FULLMASK, p3, s1);
            uint32_t a0 = __float_as_uint(odd ? u1 : u0);
            uint32_t a1 = __float_as_uint(odd ? u3 : u2);
            uint32_t a2 = __float_as_uint(odd ? v1 : v0);
            uint32_t a3 = __float_as_uint(odd ? v3 : v2);
            const int dbase = 8 * j;
#pragma unroll
            for (int nt = 0; nt < 2; ++nt) {
                uint32_t b0 = __float_as_uint(ms1T[(8*nt+g)*132 + dbase + tq]);
                uint32_t b1 = __float_as_uint(ms1T[(8*nt+g)*132 + dbase + tq + 4]);
                mma8(ae[nt*4], ae[nt*4+1], ae[nt*4+2], ae[nt*4+3],
                     a0, a1, a2, a3, b0, b1);
            }
        }
        // row sums (quad reduce) and normalized aeT stores
        sg0 += __shfl_xor_sync(FULLMASK, sg0, 1);
        sg0 += __shfl_xor_sync(FULLMASK, sg0, 2);
        sg1 += __shfl_xor_sync(FULLMASK, sg1, 1);
        sg1 += __shfl_xor_sync(FULLMASK, sg1, 2);
        const float inv0 = 1.f / sg0, inv1 = 1.f / sg1;
#pragma unroll
        for (int nt = 0; nt < 2; ++nt) {
            aeT[(8*nt + 2*tq)    *132 + Rw + g]     = ae[nt*4]   * inv0;
            aeT[(8*nt + 2*tq + 1)*132 + Rw + g]     = ae[nt*4+1] * inv0;
            aeT[(8*nt + 2*tq)    *132 + Rw + g + 8] = ae[nt*4+2] * inv1;
            aeT[(8*nt + 2*tq + 1)*132 + Rw + g + 8] = ae[nt*4+3] * inv1;
        }
        __syncthreads();

        // ---- P3: LayerNorm over C; warp w handles features w, w+8 ----
#pragma unroll
        for (int ei = 0; ei < 2; ++ei) {
            int e = w + ei * 8;
            float x0 = aeT[e * 132 + l]      + ms1[l * 20 + e];
            float x1 = aeT[e * 132 + l + 32] + ms1[(l + 32) * 20 + e];
            float x2 = aeT[e * 132 + l + 64] + ms1[(l + 64) * 20 + e];
            float x3 = aeT[e * 132 + l + 96] + ms1[(l + 96) * 20 + e];
            float s1v = x0 + x1 + x2 + x3;
            float sq = x0 * x0 + x1 * x1 + x2 * x2 + x3 * x3;
#pragma unroll
            for (int o = 16; o; o >>= 1) {
                s1v += __shfl_xor_sync(FULLMASK, s1v, o);
                sq  += __shfl_xor_sync(FULLMASK, sq, o);
            }
            float mean = s1v * (1.f / 128.f);
            float var  = sq * (1.f / 128.f) - mean * mean;
            float rs = rsqrtf(var + 1e-5f);
            aeT[e * 132 + l]      = (x0 - mean) * rs * lng[l]      + lnb[l];
            aeT[e * 132 + l + 32] = (x1 - mean) * rs * lng[l + 32] + lnb[l + 32];
            aeT[e * 132 + l + 64] = (x2 - mean) * rs * lng[l + 64] + lnb[l + 64];
            aeT[e * 132 + l + 96] = (x3 - mean) * rs * lng[l + 96] + lnb[l + 96];
        }
        __syncthreads();

        // ---- P4: edge (half 0) + mixed softmax attention (half 1) ----
        if (half == 0) {
            float acc = edge[c];
#pragma unroll
            for (int e = 0; e < 16; ++e)
                acc = fmaf(aeT[e * 132 + c], ews_all[h * 16 + e], acc);
            edge[c] = acc;
        } else {
            int ww = w - 4;
            float m0 = mixedrow[l],      m1 = mixedrow[l + 32];
            float m2 = mixedrow[l + 64], m3 = mixedrow[l + 96];
            float mx = fmaxf(fmaxf(m0, m1), fmaxf(m2, m3));
#pragma unroll
            for (int o = 16; o; o >>= 1) mx = fmaxf(mx, __shfl_xor_sync(FULLMASK, mx, o));
            float p0 = __expf(m0 - mx), p1 = __expf(m1 - mx);
            float p2 = __expf(m2 - mx), p3 = __expf(m3 - mx);
            float ssum = p0 + p1 + p2 + p3;
#pragma unroll
            for (int o = 16; o; o >>= 1) ssum += __shfl_xor_sync(FULLMASK, ssum, o);
            float inv = 1.f / ssum;
            const float* vb = v + (b * KH + h) * KC * KDQ;
#pragma unroll
            for (int d0 = 0; d0 < 4; ++d0) {
                int dq = ww * 4 + d0;
                float a = p0 * vb[l * 16 + dq] + p1 * vb[(l + 32) * 16 + dq]
                        + p2 * vb[(l + 64) * 16 + dq] + p3 * vb[(l + 96) * 16 + dq];
#pragma unroll
                for (int o = 16; o; o >>= 1) a += __shfl_xor_sync(FULLMASK, a, o);
                if (l == 0)
                    out[(b * KR + r) * (KH * KDQ) + h * KDQ + dq] = a * inv;
            }
        }
        __syncthreads();
    }

    if (tid < 128)
        out[KB * KR * KH * KDQ + br * 128 + tid] = edge[tid] + edge_b[0];
}

extern "C" void kernel_launch(void* const* d_in, const int* in_sizes, int n_in,
                              void* d_out, int out_size) {
    const float* q    = (const float*)d_in[0];
    const float* k_s  = (const float*)d_in[1];
    const float* k_a  = (const float*)d_in[2];
    const float* v    = (const float*)d_in[3];
    const float* cost = (const float*)d_in[4];
    const float* m1w  = (const float*)d_in[5];
    const float* m1b  = (const float*)d_in[6];
    const float* waa  = (const float*)d_in[7];
    const float* m2w  = (const float*)d_in[8];
    const float* m2b  = (const float*)d_in[9];
    const float* ew   = (const float*)d_in[10];
    const float* eb   = (const float*)d_in[11];
    const float* lng  = (const float*)d_in[12];
    const float* lnb  = (const float*)d_in[13];
    float* out = (float*)d_out;

    cudaFuncSetAttribute(k1_score, cudaFuncAttributeMaxDynamicSharedMemorySize, 98816);
    cudaFuncSetAttribute(k2_main,  cudaFuncAttributeMaxDynamicSharedMemorySize, 61504);

    k1_score<<<KB * KH * 4, 256, 98816>>>(q, k_s, k_a);
    k2_main<<<KB * KR, 256, 61504>>>(cost, m1w, m1b, waa, m2w, m2b, ew, eb,
                                     lng, lnb, v, out);
}

// round 10
// speedup vs baseline: 3.1991x; 1.0569x over previous
#include <cuda_runtime.h>
#include <cstdint>

#define FULLMASK 0xffffffffu
#define KB 8
#define KH 8
#define KR 128
#define KC 128
#define KDQ 16
#define L2E 1.4426950408889634f

__device__ float g_score[KB * KH * KR * KC];

__device__ __forceinline__ unsigned long long pk2(float x, float y) {
    unsigned long long r;
    asm("mov.b64 %0, {%1, %2};" : "=l"(r) : "f"(x), "f"(y));
    return r;
}
__device__ __forceinline__ float2 upk2(unsigned long long v) {
    float2 r;
    asm("mov.b64 {%0, %1}, %2;" : "=f"(r.x), "=f"(r.y) : "l"(v));
    return r;
}
__device__ __forceinline__ unsigned long long fma2(unsigned long long a,
                                                   unsigned long long b,
                                                   unsigned long long c) {
    unsigned long long d;
    asm("fma.rn.f32x2 %0, %1, %2, %3;" : "=l"(d) : "l"(a), "l"(b), "l"(c));
    return d;
}
__device__ __forceinline__ unsigned long long mul2(unsigned long long a,
                                                   unsigned long long b) {
    unsigned long long d;
    asm("mul.rn.f32x2 %0, %1, %2;" : "=l"(d) : "l"(a), "l"(b));
    return d;
}
__device__ __forceinline__ float ex2(float x) {
    float r;
    asm("ex2.approx.f32 %0, %1;" : "=f"(r) : "f"(x));
    return r;
}
__device__ __forceinline__ uint32_t tf32r(float f) {
    uint32_t u;
    asm("cvt.rna.tf32.f32 %0, %1;" : "=r"(u) : "f"(f));
    return u;
}
__device__ __forceinline__ void mma8(float& c0, float& c1, float& c2, float& c3,
                                     uint32_t a0, uint32_t a1, uint32_t a2,
                                     uint32_t a3, uint32_t b0, uint32_t b1) {
    asm volatile(
        "mma.sync.aligned.m16n8k8.row.col.f32.tf32.tf32.f32 "
        "{%0,%1,%2,%3}, {%4,%5,%6,%7}, {%8,%9}, {%0,%1,%2,%3};"
        : "+f"(c0), "+f"(c1), "+f"(c2), "+f"(c3)
        : "r"(a0), "r"(a1), "r"(a2), "r"(a3), "r"(b0), "r"(b1));
}

// ---------------------------------------------------------------------------
// Kernel 1 (unchanged, proven): grid 256, 256 thr, smem 98816
// ---------------------------------------------------------------------------
__global__ __launch_bounds__(256) void k1_score(const float* __restrict__ q,
                                                const float* __restrict__ ks,
                                                const float* __restrict__ ka) {
    extern __shared__ float sm[];
    float* ksT  = sm;
    float* kaT  = sm + 2112;
    float* qrow = sm + 4224;
    float* pbuf = sm + 6272;
    float* dpa  = sm + 7296;

    const int bh      = blockIdx.x >> 2;
    const int quarter = blockIdx.x & 3;
    const int tid = threadIdx.x;
    const float* qb  = q  + bh * 2048;
    const float* ksb = ks + bh * 2048;
    const float* kab = ka + bh * 2048;

    for (int i = tid; i < 2048; i += 256) {
        int srow = i >> 4, e = i & 15;
        ksT[e * 132 + srow] = ksb[i];
        kaT[e * 132 + srow] = kab[i];
        qrow[i] = qb[i];
    }
    __syncthreads();

    const int w = tid >> 5, l = tid & 31;

    for (int k = 0; k < 16; ++k) {
        int r = w * 16 + k;
        float qr[16];
#pragma unroll
        for (int j = 0; j < 4; ++j) {
            float4 v4 = *(const float4*)&qrow[r * 16 + 4 * j];
            qr[4*j] = v4.x; qr[4*j+1] = v4.y; qr[4*j+2] = v4.z; qr[4*j+3] = v4.w;
        }
        float a0 = 0.f, a1 = 0.f, a2 = 0.f, a3 = 0.f;
#pragma unroll
        for (int e = 0; e < 16; ++e) {
            float4 kk = *(const float4*)&kaT[e * 132 + 4 * l];
            a0 = fmaf(qr[e], kk.x, a0); a1 = fmaf(qr[e], kk.y, a1);
            a2 = fmaf(qr[e], kk.z, a2); a3 = fmaf(qr[e], kk.w, a3);
        }
        float4 o;
        o.x = fmaxf(a0 * 0.25f, 0.f); o.y = fmaxf(a1 * 0.25f, 0.f);
        o.z = fmaxf(a2 * 0.25f, 0.f); o.w = fmaxf(a3 * 0.25f, 0.f);
        *(float4*)&dpa[r * 136 + 4 * l] = o;
    }
    __syncthreads();

    for (int k = 0; k < 4; ++k) {
        int r = quarter * 32 + w * 4 + k;
        float qr[16];
#pragma unroll
        for (int j = 0; j < 4; ++j) {
            float4 v4 = *(const float4*)&qrow[r * 16 + 4 * j];
            qr[4*j] = v4.x; qr[4*j+1] = v4.y; qr[4*j+2] = v4.z; qr[4*j+3] = v4.w;
        }
        float a0 = 0.f, a1 = 0.f, a2 = 0.f, a3 = 0.f;
#pragma unroll
        for (int e = 0; e < 16; ++e) {
            float4 kk = *(const float4*)&ksT[e * 132 + 4 * l];
            a0 = fmaf(qr[e], kk.x, a0); a1 = fmaf(qr[e], kk.y, a1);
            a2 = fmaf(qr[e], kk.z, a2); a3 = fmaf(qr[e], kk.w, a3);
        }
        float x0 = a0 * 0.25f, x1 = a1 * 0.25f, x2 = a2 * 0.25f, x3 = a3 * 0.25f;
        a0 = x0 * normcdff(x0); a1 = x1 * normcdff(x1);
        a2 = x2 * normcdff(x2); a3 = x3 * normcdff(x3);
        float mx = fmaxf(fmaxf(a0, a1), fmaxf(a2, a3));
#pragma unroll
        for (int o = 16; o; o >>= 1) mx = fmaxf(mx, __shfl_xor_sync(FULLMASK, mx, o));
        float p0 = __expf(a0 - mx), p1 = __expf(a1 - mx);
        float p2 = __expf(a2 - mx), p3 = __expf(a3 - mx);
        float ssum = p0 + p1 + p2 + p3;
#pragma unroll
        for (int o = 16; o; o >>= 1) ssum += __shfl_xor_sync(FULLMASK, ssum, o);
        float inv = 1.f / ssum;
        *(float4*)&pbuf[w * 128 + 4 * l] = make_float4(p0*inv, p1*inv, p2*inv, p3*inv);
        __syncwarp();
        float c0 = 0.f, c1 = 0.f, c2 = 0.f, c3 = 0.f;
#pragma unroll 4
        for (int s2 = 0; s2 < 128; ++s2) {
            float pvv = pbuf[w * 128 + s2];
            float4 dv = *(const float4*)&dpa[s2 * 136 + 4 * l];
            c0 = fmaf(pvv, dv.x, c0); c1 = fmaf(pvv, dv.y, c1);
            c2 = fmaf(pvv, dv.z, c2); c3 = fmaf(pvv, dv.w, c3);
        }
        *(float4*)&g_score[(bh * 128 + r) * 128 + 4 * l] =
            make_float4(c0*0.25f, c1*0.25f, c2*0.25f, c3*0.25f);
        __syncwarp();
    }
}

// ---------------------------------------------------------------------------
// Kernel 2: fragment-major swizzled tiles + exact fp32 LN residual.
// Waa loaded per-head (saves smem). grid 1024, 256 thr; smem 50496 -> 4 CTAs/SM.
// ---------------------------------------------------------------------------
__global__ __launch_bounds__(256, 4) void k2_main(
    const float* __restrict__ cost_mat,
    const float* __restrict__ mix1_w, const float* __restrict__ mix1_b,
    const float* __restrict__ Waa,
    const float* __restrict__ mix2_w, const float* __restrict__ mix2_b,
    const float* __restrict__ edge_w, const float* __restrict__ edge_b,
    const float* __restrict__ ln_g,  const float* __restrict__ ln_b,
    const float* __restrict__ v, float* __restrict__ out) {
    extern __shared__ float sm[];
    float* waa      = sm;            // [256] current head, L2E-scaled
    float* w1a_all  = sm + 256;
    float* w1b_all  = sm + 384;
    float* b1s_all  = sm + 512;
    float* w2s_all  = sm + 640;
    float* ews_all  = sm + 768;
    float* b2_all   = sm + 896;      // [8]
    float* costrow  = sm + 904;
    float* lng      = sm + 1032;
    float* lnb      = sm + 1160;
    float* mixedrow = sm + 1288;
    float* edge     = sm + 1416;
    float* Msm      = sm + 1544;     // [8]
    float* srt_sm   = sm + 1552;     // [128]
    float* ms1      = sm + 1680;     // [128][20] exact fp32 (LN residual)
    float* ms1r_f   = sm + 4240;     // [128][16] tf32 ms1, frag-major+rot
    float* tsm_f    = sm + 6288;     // [128][16] tf32 t, frag-major+rot
    float* ms1T_f   = sm + 8336;     // [16][136] tf32 ms1^T, frag-perm
    float* aeT      = sm + 10512;    // [16][132]

    const int tid = threadIdx.x;
    const int w = tid >> 5, l = tid & 31;
    const int c = tid & 127;
    const int half = tid >> 7;
    const int g = l >> 2, tq = l & 3;
    const int qbase = l & ~3;
    const int Rw = w * 16;
    const int rot4 = 4 * ((tq + (g >> 1)) & 3);   // chunk rotation for loads

    const int br = blockIdx.x;
    const int b = br >> 7, r = br & 127;

    if (tid < 128) {
        int h0 = tid >> 4, e0 = tid & 15;
        w1a_all[tid] = mix1_w[h0 * 32 + e0];
        w1b_all[tid] = mix1_w[h0 * 32 + 16 + e0];
        b1s_all[tid] = mix1_b[tid];
        w2s_all[tid] = mix2_w[tid];
        ews_all[tid] = edge_w[tid];
        costrow[tid] = cost_mat[br * 128 + tid];
        lng[tid] = ln_g[tid];
        lnb[tid] = ln_b[tid];
        edge[tid] = 0.f;
    }
    if (tid < 8) b2_all[tid] = mix2_b[tid];
    __syncthreads();

    for (int h = 0; h < KH; ++h) {
        // per-head Waa reload (L2-resident, 1KB)
        waa[tid] = Waa[h * 256 + tid] * L2E;
        __syncthreads();

        // ---- P1: ms1 row c; fragment tiles; t; mixed; bound ----
        float sc = g_score[((b * KH + h) * KR + r) * KC + c];
        float co = costrow[c];
        float m[16];
#pragma unroll
        for (int e = 0; e < 16; ++e)
            m[e] = fmaxf(fmaf(sc, w1a_all[h*16+e],
                         fmaf(co, w1b_all[h*16+e], b1s_all[h*16+e])), 0.f);
        {
            float rm = m[0];
#pragma unroll
            for (int e = 1; e < 16; ++e) rm = fmaxf(rm, m[e]);
#pragma unroll
            for (int o = 16; o; o >>= 1) rm = fmaxf(rm, __shfl_xor_sync(FULLMASK, rm, o));
            if (l == 0) Msm[w] = rm;
        }
        if (half == 0) {
            // exact ms1 (LN residual) + rotated fragment-major tf32 tile
#pragma unroll
            for (int j = 0; j < 4; ++j)
                *(float4*)&ms1[c * 20 + 4 * j] =
                    make_float4(m[4*j], m[4*j+1], m[4*j+2], m[4*j+3]);
#pragma unroll
            for (int t = 0; t < 4; ++t) {
                float4 ch;
                ch.x = __uint_as_float(tf32r(m[t]));
                ch.y = __uint_as_float(tf32r(m[t + 4]));
                ch.z = __uint_as_float(tf32r(m[t + 8]));
                ch.w = __uint_as_float(tf32r(m[t + 12]));
                *(float4*)&ms1r_f[c * 16 + 4 * ((t + (c >> 1)) & 3)] = ch;
            }
            // t = ms1 @ (Waa * L2E)
            unsigned long long t2[8];
            const ulonglong2* waa4 = (const ulonglong2*)waa;
            unsigned long long m02 = pk2(m[0], m[0]);
#pragma unroll
            for (int j = 0; j < 4; ++j) {
                ulonglong2 wv = waa4[j];
                t2[2*j] = mul2(m02, wv.x); t2[2*j+1] = mul2(m02, wv.y);
            }
#pragma unroll
            for (int f = 1; f < 16; ++f) {
                unsigned long long mf2 = pk2(m[f], m[f]);
#pragma unroll
                for (int j = 0; j < 4; ++j) {
                    ulonglong2 wv = waa4[f * 4 + j];
                    t2[2*j]   = fma2(mf2, wv.x, t2[2*j]);
                    t2[2*j+1] = fma2(mf2, wv.y, t2[2*j+1]);
                }
            }
            float srt = 0.f;
            float tr[16];
#pragma unroll
            for (int j = 0; j < 8; ++j) {
                float2 tv = upk2(t2[j]);
                float f0 = __uint_as_float(tf32r(tv.x));
                float f1 = __uint_as_float(tf32r(tv.y));
                srt += fmaxf(f0, 0.f) + fmaxf(f1, 0.f);
                tr[2*j] = f0; tr[2*j+1] = f1;
            }
#pragma unroll
            for (int t = 0; t < 4; ++t)
                *(float4*)&tsm_f[c * 16 + 4 * ((t + (c >> 1)) & 3)] =
                    make_float4(tr[t], tr[t+4], tr[t+8], tr[t+12]);
            srt_sm[c] = srt;
        } else {
            // ms1T_f: transposed, intra-8 fragment permutation + mixed score
            const int pos = (c >> 3) * 8 + 2 * (c & 3) + ((c >> 2) & 1);
#pragma unroll
            for (int e = 0; e < 16; ++e)
                ms1T_f[e * 136 + pos] = __uint_as_float(tf32r(m[e]));
            float mx = b2_all[h];
#pragma unroll
            for (int f = 0; f < 16; ++f) mx = fmaf(m[f], w2s_all[h*16+f], mx);
            mixedrow[c] = mx;
        }
        __syncthreads();

        const float Mmax =
            fmaxf(fmaxf(fmaxf(Msm[0], Msm[1]), fmaxf(Msm[2], Msm[3])),
                  fmaxf(fmaxf(Msm[4], Msm[5]), fmaxf(Msm[6], Msm[7])));

        // ---- P2: fused dd-mma -> ex2 -> shuffle-convert -> ae-mma ----
        uint32_t at[8];
        {
            float4 tA = *(const float4*)&tsm_f[(Rw + g)     * 16 + rot4];
            float4 tB = *(const float4*)&tsm_f[(Rw + g + 8) * 16 + rot4];
            at[0] = __float_as_uint(tA.x); at[2] = __float_as_uint(tA.y);
            at[4] = __float_as_uint(tA.z); at[6] = __float_as_uint(tA.w);
            at[1] = __float_as_uint(tB.x); at[3] = __float_as_uint(tB.y);
            at[5] = __float_as_uint(tB.z); at[7] = __float_as_uint(tB.w);
        }
        const float mub0 = Mmax * srt_sm[Rw + g];
        const float mub1 = Mmax * srt_sm[Rw + g + 8];
        const int s0 = qbase + (tq >> 1), s1 = s0 + 2;
        const bool odd = tq & 1;
        float sg0 = 0.f, sg1 = 0.f;
        float ae[8];
#pragma unroll
        for (int i = 0; i < 8; ++i) ae[i] = 0.f;

#pragma unroll
        for (int j = 0; j < 16; ++j) {
            float c0 = -mub0, c1 = -mub0, c2 = -mub1, c3 = -mub1;
            {   // one float4 = all four dd-B fragment regs for this j
                float4 bv = *(const float4*)&ms1r_f[(8*j + g) * 16 + rot4];
                mma8(c0, c1, c2, c3, at[0], at[1], at[2], at[3],
                     __float_as_uint(bv.x), __float_as_uint(bv.y));
                mma8(c0, c1, c2, c3, at[4], at[5], at[6], at[7],
                     __float_as_uint(bv.z), __float_as_uint(bv.w));
            }
            float p0 = ex2(c0), p1 = ex2(c1), p2 = ex2(c2), p3 = ex2(c3);
            sg0 += p0 + p1; sg1 += p2 + p3;
            // C-layout (cols 2tq,2tq+1) -> A-layout (cols tq, tq+4), intra-quad
            float u0 = __shfl_sync(FULLMASK, p0, s0);
            float u1 = __shfl_sync(FULLMASK, p1, s0);
            float v0 = __shfl_sync(FULLMASK, p0, s1);
            float v1 = __shfl_sync(FULLMASK, p1, s1);
            float u2 = __shfl_sync(FULLMASK, p2, s0);
            float u3 = __shfl_sync(FULLMASK, p3, s0);
            float v2 = __shfl_sync(FULLMASK, p2, s1);
            float v3 = __shfl_sync(FULLMASK, p3, s1);
            uint32_t a0 = __float_as_uint(odd ? u1 : u0);
            uint32_t a1 = __float_as_uint(odd ? u3 : u2);
            uint32_t a2 = __float_as_uint(odd ? v1 : v0);
            uint32_t a3 = __float_as_uint(odd ? v3 : v2);
#pragma unroll
            for (int nt = 0; nt < 2; ++nt) {
                float2 bv = *(const float2*)&ms1T_f[(8*nt + g) * 136 + j*8 + 2*tq];
                mma8(ae[nt*4], ae[nt*4+1], ae[nt*4+2], ae[nt*4+3],
                     a0, a1, a2, a3,
                     __float_as_uint(bv.x), __float_as_uint(bv.y));
            }
        }
        // row sums (quad reduce) and normalized aeT stores
        sg0 += __shfl_xor_sync(FULLMASK, sg0, 1);
        sg0 += __shfl_xor_sync(FULLMASK, sg0, 2);
        sg1 += __shfl_xor_sync(FULLMASK, sg1, 1);
        sg1 += __shfl_xor_sync(FULLMASK, sg1, 2);
        const float inv0 = 1.f / sg0, inv1 = 1.f / sg1;
#pragma unroll
        for (int nt = 0; nt < 2; ++nt) {
            aeT[(8*nt + 2*tq)    *132 + Rw + g]     = ae[nt*4]   * inv0;
            aeT[(8*nt + 2*tq + 1)*132 + Rw + g]     = ae[nt*4+1] * inv0;
            aeT[(8*nt + 2*tq)    *132 + Rw + g + 8] = ae[nt*4+2] * inv1;
            aeT[(8*nt + 2*tq + 1)*132 + Rw + g + 8] = ae[nt*4+3] * inv1;
        }
        __syncthreads();

        // ---- P3: LayerNorm over C; exact fp32 residual from ms1 ----
#pragma unroll
        for (int ei = 0; ei < 2; ++ei) {
            int e = w + ei * 8;
            float x0 = aeT[e * 132 + l]      + ms1[l * 20 + e];
            float x1 = aeT[e * 132 + l + 32] + ms1[(l + 32) * 20 + e];
            float x2 = aeT[e * 132 + l + 64] + ms1[(l + 64) * 20 + e];
            float x3 = aeT[e * 132 + l + 96] + ms1[(l + 96) * 20 + e];
            float s1v = x0 + x1 + x2 + x3;
            float sq = x0 * x0 + x1 * x1 + x2 * x2 + x3 * x3;
#pragma unroll
            for (int o = 16; o; o >>= 1) {
                s1v += __shfl_xor_sync(FULLMASK, s1v, o);
                sq  += __shfl_xor_sync(FULLMASK, sq, o);
            }
            float mean = s1v * (1.f / 128.f);
            float var  = sq * (1.f / 128.f) - mean * mean;
            float rs = rsqrtf(var + 1e-5f);
            aeT[e * 132 + l]      = (x0 - mean) * rs * lng[l]      + lnb[l];
            aeT[e * 132 + l + 32] = (x1 - mean) * rs * lng[l + 32] + lnb[l + 32];
            aeT[e * 132 + l + 64] = (x2 - mean) * rs * lng[l + 64] + lnb[l + 64];
            aeT[e * 132 + l + 96] = (x3 - mean) * rs * lng[l + 96] + lnb[l + 96];
        }
        __syncthreads();

        // ---- P4: edge (half 0) + mixed softmax attention (half 1) ----
        if (half == 0) {
            float acc = edge[c];
#pragma unroll
            for (int e = 0; e < 16; ++e)
                acc = fmaf(aeT[e * 132 + c], ews_all[h * 16 + e], acc);
            edge[c] = acc;
        } else {
            int ww = w - 4;
            float m0 = mixedrow[l],      m1 = mixedrow[l + 32];
            float m2 = mixedrow[l + 64], m3 = mixedrow[l + 96];
            float mx = fmaxf(fmaxf(m0, m1), fmaxf(m2, m3));
#pragma unroll
            for (int o = 16; o; o >>= 1) mx = fmaxf(mx, __shfl_xor_sync(FULLMASK, mx, o));
            float p0 = __expf(m0 - mx), p1 = __expf(m1 - mx);
            float p2 = __expf(m2 - mx), p3 = __expf(m3 - mx);
            float ssum = p0 + p1 + p2 + p3;
#pragma unroll
            for (int o = 16; o; o >>= 1) ssum += __shfl_xor_sync(FULLMASK, ssum, o);
            float inv = 1.f / ssum;
            const float* vb = v + (b * KH + h) * KC * KDQ;
#pragma unroll
            for (int d0 = 0; d0 < 4; ++d0) {
                int dq = ww * 4 + d0;
                float a = p0 * vb[l * 16 + dq] + p1 * vb[(l + 32) * 16 + dq]
                        + p2 * vb[(l + 64) * 16 + dq] + p3 * vb[(l + 96) * 16 + dq];
#pragma unroll
                for (int o = 16; o; o >>= 1) a += __shfl_xor_sync(FULLMASK, a, o);
                if (l == 0)
                    out[(b * KR + r) * (KH * KDQ) + h * KDQ + dq] = a * inv;
            }
        }
        __syncthreads();
    }

    if (tid < 128)
        out[KB * KR * KH * KDQ + br * 128 + tid] = edge[tid] + edge_b[0];
}

extern "C" void kernel_launch(void* const* d_in, const int* in_sizes, int n_in,
                              void* d_out, int out_size) {
    const float* q    = (const float*)d_in[0];
    const float* k_s  = (const float*)d_in[1];
    const float* k_a  = (const float*)d_in[2];
    const float* v    = (const float*)d_in[3];
    const float* cost = (const float*)d_in[4];
    const float* m1w  = (const float*)d_in[5];
    const float* m1b  = (const float*)d_in[6];
    const float* waa  = (const float*)d_in[7];
    const float* m2w  = (const float*)d_in[8];
    const float* m2b  = (const float*)d_in[9];
    const float* ew   = (const float*)d_in[10];
    const float* eb   = (const float*)d_in[11];
    const float* lng  = (const float*)d_in[12];
    const float* lnb  = (const float*)d_in[13];
    float* out = (float*)d_out;

    cudaFuncSetAttribute(k1_score, cudaFuncAttributeMaxDynamicSharedMemorySize, 98816);
    cudaFuncSetAttribute(k2_main,  cudaFuncAttributeMaxDynamicSharedMemorySize, 50496);

    k1_score<<<KB * KH * 4, 256, 98816>>>(q, k_s, k_a);
    k2_main<<<KB * KR, 256, 50496>>>(cost, m1w, m1b, waa, m2w, m2b, ew, eb,
                                     lng, lnb, v, out);
}

// round 11
// speedup vs baseline: 3.6079x; 1.1278x over previous
#include <cuda_runtime.h>
#include <cstdint>

#define FULLMASK 0xffffffffu
#define KB 8
#define KH 8
#define KR 128
#define KC 128
#define KDQ 16
#define L2E 1.4426950408889634f

__device__ float g_score[KB * KH * KR * KC];

__device__ __forceinline__ unsigned long long pk2(float x, float y) {
    unsigned long long r;
    asm("mov.b64 %0, {%1, %2};" : "=l"(r) : "f"(x), "f"(y));
    return r;
}
__device__ __forceinline__ float2 upk2(unsigned long long v) {
    float2 r;
    asm("mov.b64 {%0, %1}, %2;" : "=f"(r.x), "=f"(r.y) : "l"(v));
    return r;
}
__device__ __forceinline__ unsigned long long fma2(unsigned long long a,
                                                   unsigned long long b,
                                                   unsigned long long c) {
    unsigned long long d;
    asm("fma.rn.f32x2 %0, %1, %2, %3;" : "=l"(d) : "l"(a), "l"(b), "l"(c));
    return d;
}
__device__ __forceinline__ unsigned long long mul2(unsigned long long a,
                                                   unsigned long long b) {
    unsigned long long d;
    asm("mul.rn.f32x2 %0, %1, %2;" : "=l"(d) : "l"(a), "l"(b));
    return d;
}
__device__ __forceinline__ float ex2(float x) {
    float r;
    asm("ex2.approx.f32 %0, %1;" : "=f"(r) : "f"(x));
    return r;
}
__device__ __forceinline__ uint32_t tf32r(float f) {
    uint32_t u;
    asm("cvt.rna.tf32.f32 %0, %1;" : "=r"(u) : "f"(f));
    return u;
}
__device__ __forceinline__ void mma8(float& c0, float& c1, float& c2, float& c3,
                                     uint32_t a0, uint32_t a1, uint32_t a2,
                                     uint32_t a3, uint32_t b0, uint32_t b1) {
    asm volatile(
        "mma.sync.aligned.m16n8k8.row.col.f32.tf32.tf32.f32 "
        "{%0,%1,%2,%3}, {%4,%5,%6,%7}, {%8,%9}, {%0,%1,%2,%3};"
        : "+f"(c0), "+f"(c1), "+f"(c2), "+f"(c3)
        : "r"(a0), "r"(a1), "r"(a2), "r"(a3), "r"(b0), "r"(b1));
}

// ---------------------------------------------------------------------------
// Kernel 1 (unchanged, proven): grid 256, 256 thr, smem 98816
// ---------------------------------------------------------------------------
__global__ __launch_bounds__(256) void k1_score(const float* __restrict__ q,
                                                const float* __restrict__ ks,
                                                const float* __restrict__ ka) {
    extern __shared__ float sm[];
    float* ksT  = sm;
    float* kaT  = sm + 2112;
    float* qrow = sm + 4224;
    float* pbuf = sm + 6272;
    float* dpa  = sm + 7296;

    const int bh      = blockIdx.x >> 2;
    const int quarter = blockIdx.x & 3;
    const int tid = threadIdx.x;
    const float* qb  = q  + bh * 2048;
    const float* ksb = ks + bh * 2048;
    const float* kab = ka + bh * 2048;

    for (int i = tid; i < 2048; i += 256) {
        int srow = i >> 4, e = i & 15;
        ksT[e * 132 + srow] = ksb[i];
        kaT[e * 132 + srow] = kab[i];
        qrow[i] = qb[i];
    }
    __syncthreads();

    const int w = tid >> 5, l = tid & 31;

    for (int k = 0; k < 16; ++k) {
        int r = w * 16 + k;
        float qr[16];
#pragma unroll
        for (int j = 0; j < 4; ++j) {
            float4 v4 = *(const float4*)&qrow[r * 16 + 4 * j];
            qr[4*j] = v4.x; qr[4*j+1] = v4.y; qr[4*j+2] = v4.z; qr[4*j+3] = v4.w;
        }
        float a0 = 0.f, a1 = 0.f, a2 = 0.f, a3 = 0.f;
#pragma unroll
        for (int e = 0; e < 16; ++e) {
            float4 kk = *(const float4*)&kaT[e * 132 + 4 * l];
            a0 = fmaf(qr[e], kk.x, a0); a1 = fmaf(qr[e], kk.y, a1);
            a2 = fmaf(qr[e], kk.z, a2); a3 = fmaf(qr[e], kk.w, a3);
        }
        float4 o;
        o.x = fmaxf(a0 * 0.25f, 0.f); o.y = fmaxf(a1 * 0.25f, 0.f);
        o.z = fmaxf(a2 * 0.25f, 0.f); o.w = fmaxf(a3 * 0.25f, 0.f);
        *(float4*)&dpa[r * 136 + 4 * l] = o;
    }
    __syncthreads();

    for (int k = 0; k < 4; ++k) {
        int r = quarter * 32 + w * 4 + k;
        float qr[16];
#pragma unroll
        for (int j = 0; j < 4; ++j) {
            float4 v4 = *(const float4*)&qrow[r * 16 + 4 * j];
            qr[4*j] = v4.x; qr[4*j+1] = v4.y; qr[4*j+2] = v4.z; qr[4*j+3] = v4.w;
        }
        float a0 = 0.f, a1 = 0.f, a2 = 0.f, a3 = 0.f;
#pragma unroll
        for (int e = 0; e < 16; ++e) {
            float4 kk = *(const float4*)&ksT[e * 132 + 4 * l];
            a0 = fmaf(qr[e], kk.x, a0); a1 = fmaf(qr[e], kk.y, a1);
            a2 = fmaf(qr[e], kk.z, a2); a3 = fmaf(qr[e], kk.w, a3);
        }
        float x0 = a0 * 0.25f, x1 = a1 * 0.25f, x2 = a2 * 0.25f, x3 = a3 * 0.25f;
        a0 = x0 * normcdff(x0); a1 = x1 * normcdff(x1);
        a2 = x2 * normcdff(x2); a3 = x3 * normcdff(x3);
        float mx = fmaxf(fmaxf(a0, a1), fmaxf(a2, a3));
#pragma unroll
        for (int o = 16; o; o >>= 1) mx = fmaxf(mx, __shfl_xor_sync(FULLMASK, mx, o));
        float p0 = __expf(a0 - mx), p1 = __expf(a1 - mx);
        float p2 = __expf(a2 - mx), p3 = __expf(a3 - mx);
        float ssum = p0 + p1 + p2 + p3;
#pragma unroll
        for (int o = 16; o; o >>= 1) ssum += __shfl_xor_sync(FULLMASK, ssum, o);
        float inv = 1.f / ssum;
        *(float4*)&pbuf[w * 128 + 4 * l] = make_float4(p0*inv, p1*inv, p2*inv, p3*inv);
        __syncwarp();
        float c0 = 0.f, c1 = 0.f, c2 = 0.f, c3 = 0.f;
#pragma unroll 4
        for (int s2 = 0; s2 < 128; ++s2) {
            float pvv = pbuf[w * 128 + s2];
            float4 dv = *(const float4*)&dpa[s2 * 136 + 4 * l];
            c0 = fmaf(pvv, dv.x, c0); c1 = fmaf(pvv, dv.y, c1);
            c2 = fmaf(pvv, dv.z, c2); c3 = fmaf(pvv, dv.w, c3);
        }
        *(float4*)&g_score[(bh * 128 + r) * 128 + 4 * l] =
            make_float4(c0*0.25f, c1*0.25f, c2*0.25f, c3*0.25f);
        __syncwarp();
    }
}

// ---------------------------------------------------------------------------
// Kernel 2: K-permuted second GEMM -> C->A conversion is a register rename
// (zero shuffles). grid 1024, 256 thr; smem 50496 -> 4 CTAs/SM.
// ---------------------------------------------------------------------------
__global__ __launch_bounds__(256, 4) void k2_main(
    const float* __restrict__ cost_mat,
    const float* __restrict__ mix1_w, const float* __restrict__ mix1_b,
    const float* __restrict__ Waa,
    const float* __restrict__ mix2_w, const float* __restrict__ mix2_b,
    const float* __restrict__ edge_w, const float* __restrict__ edge_b,
    const float* __restrict__ ln_g,  const float* __restrict__ ln_b,
    const float* __restrict__ v, float* __restrict__ out) {
    extern __shared__ float sm[];
    float* waa      = sm;            // [256] current head, L2E-scaled
    float* w1a_all  = sm + 256;
    float* w1b_all  = sm + 384;
    float* b1s_all  = sm + 512;
    float* w2s_all  = sm + 640;
    float* ews_all  = sm + 768;
    float* b2_all   = sm + 896;      // [8]
    float* costrow  = sm + 904;
    float* lng      = sm + 1032;
    float* lnb      = sm + 1160;
    float* mixedrow = sm + 1288;
    float* edge     = sm + 1416;
    float* Msm      = sm + 1544;     // [8]
    float* srt_sm   = sm + 1552;     // [128]
    float* ms1      = sm + 1680;     // [128][20] exact fp32 (LN residual)
    float* ms1r_f   = sm + 4240;     // [128][16] tf32 ms1, frag-major+rot
    float* tsm_f    = sm + 6288;     // [128][16] tf32 t, frag-major+rot
    float* ms1T_f   = sm + 8336;     // [16][136] tf32 ms1^T, natural order
    float* aeT      = sm + 10512;    // [16][132]

    const int tid = threadIdx.x;
    const int w = tid >> 5, l = tid & 31;
    const int c = tid & 127;
    const int half = tid >> 7;
    const int g = l >> 2, tq = l & 3;
    const int Rw = w * 16;
    const int rot4 = 4 * ((tq + (g >> 1)) & 3);   // chunk rotation for loads

    const int br = blockIdx.x;
    const int b = br >> 7, r = br & 127;

    if (tid < 128) {
        int h0 = tid >> 4, e0 = tid & 15;
        w1a_all[tid] = mix1_w[h0 * 32 + e0];
        w1b_all[tid] = mix1_w[h0 * 32 + 16 + e0];
        b1s_all[tid] = mix1_b[tid];
        w2s_all[tid] = mix2_w[tid];
        ews_all[tid] = edge_w[tid];
        costrow[tid] = cost_mat[br * 128 + tid];
        lng[tid] = ln_g[tid];
        lnb[tid] = ln_b[tid];
        edge[tid] = 0.f;
    }
    if (tid < 8) b2_all[tid] = mix2_b[tid];
    __syncthreads();

    for (int h = 0; h < KH; ++h) {
        // per-head Waa reload (L2-resident, 1KB)
        waa[tid] = Waa[h * 256 + tid] * L2E;
        __syncthreads();

        // ---- P1: ms1 row c; fragment tiles; t; mixed; bound ----
        float sc = g_score[((b * KH + h) * KR + r) * KC + c];
        float co = costrow[c];
        float m[16];
#pragma unroll
        for (int e = 0; e < 16; ++e)
            m[e] = fmaxf(fmaf(sc, w1a_all[h*16+e],
                         fmaf(co, w1b_all[h*16+e], b1s_all[h*16+e])), 0.f);
        {
            float rm = m[0];
#pragma unroll
            for (int e = 1; e < 16; ++e) rm = fmaxf(rm, m[e]);
#pragma unroll
            for (int o = 16; o; o >>= 1) rm = fmaxf(rm, __shfl_xor_sync(FULLMASK, rm, o));
            if (l == 0) Msm[w] = rm;
        }
        if (half == 0) {
            // exact ms1 (LN residual) + rotated fragment-major tf32 tile
#pragma unroll
            for (int j = 0; j < 4; ++j)
                *(float4*)&ms1[c * 20 + 4 * j] =
                    make_float4(m[4*j], m[4*j+1], m[4*j+2], m[4*j+3]);
#pragma unroll
            for (int t = 0; t < 4; ++t) {
                float4 ch;
                ch.x = __uint_as_float(tf32r(m[t]));
                ch.y = __uint_as_float(tf32r(m[t + 4]));
                ch.z = __uint_as_float(tf32r(m[t + 8]));
                ch.w = __uint_as_float(tf32r(m[t + 12]));
                *(float4*)&ms1r_f[c * 16 + 4 * ((t + (c >> 1)) & 3)] = ch;
            }
            // t = ms1 @ (Waa * L2E)
            unsigned long long t2[8];
            const ulonglong2* waa4 = (const ulonglong2*)waa;
            unsigned long long m02 = pk2(m[0], m[0]);
#pragma unroll
            for (int j = 0; j < 4; ++j) {
                ulonglong2 wv = waa4[j];
                t2[2*j] = mul2(m02, wv.x); t2[2*j+1] = mul2(m02, wv.y);
            }
#pragma unroll
            for (int f = 1; f < 16; ++f) {
                unsigned long long mf2 = pk2(m[f], m[f]);
#pragma unroll
                for (int j = 0; j < 4; ++j) {
                    ulonglong2 wv = waa4[f * 4 + j];
                    t2[2*j]   = fma2(mf2, wv.x, t2[2*j]);
                    t2[2*j+1] = fma2(mf2, wv.y, t2[2*j+1]);
                }
            }
            float srt = 0.f;
            float tr[16];
#pragma unroll
            for (int j = 0; j < 8; ++j) {
                float2 tv = upk2(t2[j]);
                float f0 = __uint_as_float(tf32r(tv.x));
                float f1 = __uint_as_float(tf32r(tv.y));
                srt += fmaxf(f0, 0.f) + fmaxf(f1, 0.f);
                tr[2*j] = f0; tr[2*j+1] = f1;
            }
#pragma unroll
            for (int t = 0; t < 4; ++t)
                *(float4*)&tsm_f[c * 16 + 4 * ((t + (c >> 1)) & 3)] =
                    make_float4(tr[t], tr[t+4], tr[t+8], tr[t+12]);
            srt_sm[c] = srt;
        } else {
            // ms1T_f: transposed, NATURAL column order + mixed score
#pragma unroll
            for (int e = 0; e < 16; ++e)
                ms1T_f[e * 136 + c] = __uint_as_float(tf32r(m[e]));
            float mx = b2_all[h];
#pragma unroll
            for (int f = 0; f < 16; ++f) mx = fmaf(m[f], w2s_all[h*16+f], mx);
            mixedrow[c] = mx;
        }
        __syncthreads();

        const float Mmax =
            fmaxf(fmaxf(fmaxf(Msm[0], Msm[1]), fmaxf(Msm[2], Msm[3])),
                  fmaxf(fmaxf(Msm[4], Msm[5]), fmaxf(Msm[6], Msm[7])));

        // ---- P2: fused dd-mma -> ex2 -> rename -> ae-mma (no shuffles) ----
        // ae-mma k-slot tq contracts dd-col 2tq, slot tq+4 contracts col 2tq+1;
        // ms1T_f natural order makes B match, so A = (p0, p2, p1, p3) directly.
        uint32_t at[8];
        {
            float4 tA = *(const float4*)&tsm_f[(Rw + g)     * 16 + rot4];
            float4 tB = *(const float4*)&tsm_f[(Rw + g + 8) * 16 + rot4];
            at[0] = __float_as_uint(tA.x); at[2] = __float_as_uint(tA.y);
            at[4] = __float_as_uint(tA.z); at[6] = __float_as_uint(tA.w);
            at[1] = __float_as_uint(tB.x); at[3] = __float_as_uint(tB.y);
            at[5] = __float_as_uint(tB.z); at[7] = __float_as_uint(tB.w);
        }
        const float mub0 = Mmax * srt_sm[Rw + g];
        const float mub1 = Mmax * srt_sm[Rw + g + 8];
        float sg0 = 0.f, sg1 = 0.f;
        float ae[8];
#pragma unroll
        for (int i = 0; i < 8; ++i) ae[i] = 0.f;

#pragma unroll
        for (int j = 0; j < 16; ++j) {
            float c0 = -mub0, c1 = -mub0, c2 = -mub1, c3 = -mub1;
            {   // one float4 = all four dd-B fragment regs for this j
                float4 bv = *(const float4*)&ms1r_f[(8*j + g) * 16 + rot4];
                mma8(c0, c1, c2, c3, at[0], at[1], at[2], at[3],
                     __float_as_uint(bv.x), __float_as_uint(bv.y));
                mma8(c0, c1, c2, c3, at[4], at[5], at[6], at[7],
                     __float_as_uint(bv.z), __float_as_uint(bv.w));
            }
            float p0 = ex2(c0), p1 = ex2(c1), p2 = ex2(c2), p3 = ex2(c3);
            sg0 += p0 + p1; sg1 += p2 + p3;
            uint32_t a0 = __float_as_uint(p0);
            uint32_t a1 = __float_as_uint(p2);
            uint32_t a2 = __float_as_uint(p1);
            uint32_t a3 = __float_as_uint(p3);
#pragma unroll
            for (int nt = 0; nt < 2; ++nt) {
                float2 bv = *(const float2*)&ms1T_f[(8*nt + g) * 136 + j*8 + 2*tq];
                mma8(ae[nt*4], ae[nt*4+1], ae[nt*4+2], ae[nt*4+3],
                     a0, a1, a2, a3,
                     __float_as_uint(bv.x), __float_as_uint(bv.y));
            }
        }
        // row sums (quad reduce) and normalized aeT stores
        sg0 += __shfl_xor_sync(FULLMASK, sg0, 1);
        sg0 += __shfl_xor_sync(FULLMASK, sg0, 2);
        sg1 += __shfl_xor_sync(FULLMASK, sg1, 1);
        sg1 += __shfl_xor_sync(FULLMASK, sg1, 2);
        const float inv0 = 1.f / sg0, inv1 = 1.f / sg1;
#pragma unroll
        for (int nt = 0; nt < 2; ++nt) {
            aeT[(8*nt + 2*tq)    *132 + Rw + g]     = ae[nt*4]   * inv0;
            aeT[(8*nt + 2*tq + 1)*132 + Rw + g]     = ae[nt*4+1] * inv0;
            aeT[(8*nt + 2*tq)    *132 + Rw + g + 8] = ae[nt*4+2] * inv1;
            aeT[(8*nt + 2*tq + 1)*132 + Rw + g + 8] = ae[nt*4+3] * inv1;
        }
        __syncthreads();

        // ---- P3: LayerNorm over C; exact fp32 residual from ms1 ----
#pragma unroll
        for (int ei = 0; ei < 2; ++ei) {
            int e = w + ei * 8;
            float x0 = aeT[e * 132 + l]      + ms1[l * 20 + e];
            float x1 = aeT[e * 132 + l + 32] + ms1[(l + 32) * 20 + e];
            float x2 = aeT[e * 132 + l + 64] + ms1[(l + 64) * 20 + e];
            float x3 = aeT[e * 132 + l + 96] + ms1[(l + 96) * 20 + e];
            float s1v = x0 + x1 + x2 + x3;
            float sq = x0 * x0 + x1 * x1 + x2 * x2 + x3 * x3;
#pragma unroll
            for (int o = 16; o; o >>= 1) {
                s1v += __shfl_xor_sync(FULLMASK, s1v, o);
                sq  += __shfl_xor_sync(FULLMASK, sq, o);
            }
            float mean = s1v * (1.f / 128.f);
            float var  = sq * (1.f / 128.f) - mean * mean;
            float rs = rsqrtf(var + 1e-5f);
            aeT[e * 132 + l]      = (x0 - mean) * rs * lng[l]      + lnb[l];
            aeT[e * 132 + l + 32] = (x1 - mean) * rs * lng[l + 32] + lnb[l + 32];
            aeT[e * 132 + l + 64] = (x2 - mean) * rs * lng[l + 64] + lnb[l + 64];
            aeT[e * 132 + l + 96] = (x3 - mean) * rs * lng[l + 96] + lnb[l + 96];
        }
        __syncthreads();

        // ---- P4: edge (half 0) + mixed softmax attention (half 1) ----
        if (half == 0) {
            float acc = edge[c];
#pragma unroll
            for (int e = 0; e < 16; ++e)
                acc = fmaf(aeT[e * 132 + c], ews_all[h * 16 + e], acc);
            edge[c] = acc;
        } else {
            int ww = w - 4;
            float m0 = mixedrow[l],      m1 = mixedrow[l + 32];
            float m2 = mixedrow[l + 64], m3 = mixedrow[l + 96];
            float mx = fmaxf(fmaxf(m0, m1), fmaxf(m2, m3));
#pragma unroll
            for (int o = 16; o; o >>= 1) mx = fmaxf(mx, __shfl_xor_sync(FULLMASK, mx, o));
            float p0 = __expf(m0 - mx), p1 = __expf(m1 - mx);
            float p2 = __expf(m2 - mx), p3 = __expf(m3 - mx);
            float ssum = p0 + p1 + p2 + p3;
#pragma unroll
            for (int o = 16; o; o >>= 1) ssum += __shfl_xor_sync(FULLMASK, ssum, o);
            float inv = 1.f / ssum;
            const float* vb = v + (b * KH + h) * KC * KDQ;
#pragma unroll
            for (int d0 = 0; d0 < 4; ++d0) {
                int dq = ww * 4 + d0;
                float a = p0 * vb[l * 16 + dq] + p1 * vb[(l + 32) * 16 + dq]
                        + p2 * vb[(l + 64) * 16 + dq] + p3 * vb[(l + 96) * 16 + dq];
#pragma unroll
                for (int o = 16; o; o >>= 1) a += __shfl_xor_sync(FULLMASK, a, o);
                if (l == 0)
                    out[(b * KR + r) * (KH * KDQ) + h * KDQ + dq] = a * inv;
            }
        }
        __syncthreads();
    }

    if (tid < 128)
        out[KB * KR * KH * KDQ + br * 128 + tid] = edge[tid] + edge_b[0];
}

extern "C" void kernel_launch(void* const* d_in, const int* in_sizes, int n_in,
                              void* d_out, int out_size) {
    const float* q    = (const float*)d_in[0];
    const float* k_s  = (const float*)d_in[1];
    const float* k_a  = (const float*)d_in[2];
    const float* v    = (const float*)d_in[3];
    const float* cost = (const float*)d_in[4];
    const float* m1w  = (const float*)d_in[5];
    const float* m1b  = (const float*)d_in[6];
    const float* waa  = (const float*)d_in[7];
    const float* m2w  = (const float*)d_in[8];
    const float* m2b  = (const float*)d_in[9];
    const float* ew   = (const float*)d_in[10];
    const float* eb   = (const float*)d_in[11];
    const float* lng  = (const float*)d_in[12];
    const float* lnb  = (const float*)d_in[13];
    float* out = (float*)d_out;

    cudaFuncSetAttribute(k1_score, cudaFuncAttributeMaxDynamicSharedMemorySize, 98816);
    cudaFuncSetAttribute(k2_main,  cudaFuncAttributeMaxDynamicSharedMemorySize, 50496);

    k1_score<<<KB * KH * 4, 256, 98816>>>(q, k_s, k_a);
    k2_main<<<KB * KR, 256, 50496>>>(cost, m1w, m1b, waa, m2w, m2b, ew, eb,
                                     lng, lnb, v, out);
}

// round 12
// speedup vs baseline: 3.9442x; 1.0932x over previous
#include <cuda_runtime.h>
#include <cstdint>

#define FULLMASK 0xffffffffu
#define KB 8
#define KH 8
#define KR 128
#define KC 128
#define KDQ 16
#define L2E 1.4426950408889634f

__device__ float g_score[KB * KH * KR * KC];

__device__ __forceinline__ float ex2(float x) {
    float r;
    asm("ex2.approx.f32 %0, %1;" : "=f"(r) : "f"(x));
    return r;
}
__device__ __forceinline__ uint32_t tf32r(float f) {
    uint32_t u;
    asm("cvt.rna.tf32.f32 %0, %1;" : "=r"(u) : "f"(f));
    return u;
}
__device__ __forceinline__ void mma8(float& c0, float& c1, float& c2, float& c3,
                                     uint32_t a0, uint32_t a1, uint32_t a2,
                                     uint32_t a3, uint32_t b0, uint32_t b1) {
    asm volatile(
        "mma.sync.aligned.m16n8k8.row.col.f32.tf32.tf32.f32 "
        "{%0,%1,%2,%3}, {%4,%5,%6,%7}, {%8,%9}, {%0,%1,%2,%3};"
        : "+f"(c0), "+f"(c1), "+f"(c2), "+f"(c3)
        : "r"(a0), "r"(a1), "r"(a2), "r"(a3), "r"(b0), "r"(b1));
}

// ---------------------------------------------------------------------------
// Kernel 1 (unchanged, proven): grid 256, 256 thr, smem 98816
// ---------------------------------------------------------------------------
__global__ __launch_bounds__(256) void k1_score(const float* __restrict__ q,
                                                const float* __restrict__ ks,
                                                const float* __restrict__ ka) {
    extern __shared__ float sm[];
    float* ksT  = sm;
    float* kaT  = sm + 2112;
    float* qrow = sm + 4224;
    float* pbuf = sm + 6272;
    float* dpa  = sm + 7296;

    const int bh      = blockIdx.x >> 2;
    const int quarter = blockIdx.x & 3;
    const int tid = threadIdx.x;
    const float* qb  = q  + bh * 2048;
    const float* ksb = ks + bh * 2048;
    const float* kab = ka + bh * 2048;

    for (int i = tid; i < 2048; i += 256) {
        int srow = i >> 4, e = i & 15;
        ksT[e * 132 + srow] = ksb[i];
        kaT[e * 132 + srow] = kab[i];
        qrow[i] = qb[i];
    }
    __syncthreads();

    const int w = tid >> 5, l = tid & 31;

    for (int k = 0; k < 16; ++k) {
        int r = w * 16 + k;
        float qr[16];
#pragma unroll
        for (int j = 0; j < 4; ++j) {
            float4 v4 = *(const float4*)&qrow[r * 16 + 4 * j];
            qr[4*j] = v4.x; qr[4*j+1] = v4.y; qr[4*j+2] = v4.z; qr[4*j+3] = v4.w;
        }
        float a0 = 0.f, a1 = 0.f, a2 = 0.f, a3 = 0.f;
#pragma unroll
        for (int e = 0; e < 16; ++e) {
            float4 kk = *(const float4*)&kaT[e * 132 + 4 * l];
            a0 = fmaf(qr[e], kk.x, a0); a1 = fmaf(qr[e], kk.y, a1);
            a2 = fmaf(qr[e], kk.z, a2); a3 = fmaf(qr[e], kk.w, a3);
        }
        float4 o;
        o.x = fmaxf(a0 * 0.25f, 0.f); o.y = fmaxf(a1 * 0.25f, 0.f);
        o.z = fmaxf(a2 * 0.25f, 0.f); o.w = fmaxf(a3 * 0.25f, 0.f);
        *(float4*)&dpa[r * 136 + 4 * l] = o;
    }
    __syncthreads();

    for (int k = 0; k < 4; ++k) {
        int r = quarter * 32 + w * 4 + k;
        float qr[16];
#pragma unroll
        for (int j = 0; j < 4; ++j) {
            float4 v4 = *(const float4*)&qrow[r * 16 + 4 * j];
            qr[4*j] = v4.x; qr[4*j+1] = v4.y; qr[4*j+2] = v4.z; qr[4*j+3] = v4.w;
        }
        float a0 = 0.f, a1 = 0.f, a2 = 0.f, a3 = 0.f;
#pragma unroll
        for (int e = 0; e < 16; ++e) {
            float4 kk = *(const float4*)&ksT[e * 132 + 4 * l];
            a0 = fmaf(qr[e], kk.x, a0); a1 = fmaf(qr[e], kk.y, a1);
            a2 = fmaf(qr[e], kk.z, a2); a3 = fmaf(qr[e], kk.w, a3);
        }
        float x0 = a0 * 0.25f, x1 = a1 * 0.25f, x2 = a2 * 0.25f, x3 = a3 * 0.25f;
        a0 = x0 * normcdff(x0); a1 = x1 * normcdff(x1);
        a2 = x2 * normcdff(x2); a3 = x3 * normcdff(x3);
        float mx = fmaxf(fmaxf(a0, a1), fmaxf(a2, a3));
#pragma unroll
        for (int o = 16; o; o >>= 1) mx = fmaxf(mx, __shfl_xor_sync(FULLMASK, mx, o));
        float p0 = __expf(a0 - mx), p1 = __expf(a1 - mx);
        float p2 = __expf(a2 - mx), p3 = __expf(a3 - mx);
        float ssum = p0 + p1 + p2 + p3;
#pragma unroll
        for (int o = 16; o; o >>= 1) ssum += __shfl_xor_sync(FULLMASK, ssum, o);
        float inv = 1.f / ssum;
        *(float4*)&pbuf[w * 128 + 4 * l] = make_float4(p0*inv, p1*inv, p2*inv, p3*inv);
        __syncwarp();
        float c0 = 0.f, c1 = 0.f, c2 = 0.f, c3 = 0.f;
#pragma unroll 4
        for (int s2 = 0; s2 < 128; ++s2) {
            float pvv = pbuf[w * 128 + s2];
            float4 dv = *(const float4*)&dpa[s2 * 136 + 4 * l];
            c0 = fmaf(pvv, dv.x, c0); c1 = fmaf(pvv, dv.y, c1);
            c2 = fmaf(pvv, dv.z, c2); c3 = fmaf(pvv, dv.w, c3);
        }
        *(float4*)&g_score[(bh * 128 + r) * 128 + 4 * l] =
            make_float4(c0*0.25f, c1*0.25f, c2*0.25f, c3*0.25f);
        __syncwarp();
    }
}

// ---------------------------------------------------------------------------
// Kernel 2: all three GEMMs (t = ms1@Waa, dd = t@ms1^T, ae = dw@ms1) on
// tensor cores; t lives only in registers (C->A renames via K-permutation).
// grid 1024, 256 thr; dynamic smem 40000 B -> 4 CTAs/SM.
// ---------------------------------------------------------------------------
__global__ __launch_bounds__(256, 4) void k2_main(
    const float* __restrict__ cost_mat,
    const float* __restrict__ mix1_w, const float* __restrict__ mix1_b,
    const float* __restrict__ Waa,
    const float* __restrict__ mix2_w, const float* __restrict__ mix2_b,
    const float* __restrict__ edge_w, const float* __restrict__ edge_b,
    const float* __restrict__ ln_g,  const float* __restrict__ ln_b,
    const float* __restrict__ v, float* __restrict__ out) {
    extern __shared__ float sm[];
    float* waa      = sm;            // [16][16] current head, L2E-scaled
    float* w1a_all  = sm + 256;
    float* w1b_all  = sm + 384;
    float* b1s_all  = sm + 512;
    float* w2s_all  = sm + 640;
    float* ews_all  = sm + 768;
    float* b2_all   = sm + 896;      // [8]
    float* costrow  = sm + 904;
    float* lng      = sm + 1032;
    float* lnb      = sm + 1160;
    float* mixedrow = sm + 1288;
    float* edge     = sm + 1416;
    float* Msm      = sm + 1544;     // [8]
    float* ms1T_e   = sm + 1552;     // [16][132] exact fp32 (LN residual)
    float* ms1r_f   = sm + 3664;     // [128][16] tf32 ms1, paired-e frag chunks
    float* ms1T_f   = sm + 5712;     // [16][136] tf32 ms1^T, natural order
    float* aeT      = sm + 7888;     // [16][132]

    const int tid = threadIdx.x;
    const int w = tid >> 5, l = tid & 31;
    const int c = tid & 127;
    const int half = tid >> 7;
    const int g = l >> 2, tq = l & 3;
    const int Rw = w * 16;
    const int rot4 = 4 * ((tq + (g >> 1)) & 3);   // chunk rotation for loads

    const int br = blockIdx.x;
    const int b = br >> 7, r = br & 127;

    if (tid < 128) {
        int h0 = tid >> 4, e0 = tid & 15;
        w1a_all[tid] = mix1_w[h0 * 32 + e0];
        w1b_all[tid] = mix1_w[h0 * 32 + 16 + e0];
        b1s_all[tid] = mix1_b[tid];
        w2s_all[tid] = mix2_w[tid];
        ews_all[tid] = edge_w[tid];
        costrow[tid] = cost_mat[br * 128 + tid];
        lng[tid] = ln_g[tid];
        lnb[tid] = ln_b[tid];
        edge[tid] = 0.f;
    }
    if (tid < 8) b2_all[tid] = mix2_b[tid];
    __syncthreads();

    for (int h = 0; h < KH; ++h) {
        // per-head Waa reload (L2-resident, 1KB), pre-scaled by log2(e)
        waa[tid] = Waa[h * 256 + tid] * L2E;
        __syncthreads();

        // ---- P1: ms1 row c -> tiles; mixed; tile max ----
        float sc = g_score[((b * KH + h) * KR + r) * KC + c];
        float co = costrow[c];
        float m[16];
#pragma unroll
        for (int e = 0; e < 16; ++e)
            m[e] = fmaxf(fmaf(sc, w1a_all[h*16+e],
                         fmaf(co, w1b_all[h*16+e], b1s_all[h*16+e])), 0.f);
        {
            float rm = m[0];
#pragma unroll
            for (int e = 1; e < 16; ++e) rm = fmaxf(rm, m[e]);
#pragma unroll
            for (int o = 16; o; o >>= 1) rm = fmaxf(rm, __shfl_xor_sync(FULLMASK, rm, o));
            if (l == 0) Msm[w] = rm;
        }
        if (half == 0) {
            // exact residual tile (transposed, conflict-free)
#pragma unroll
            for (int e = 0; e < 16; ++e) ms1T_e[e * 132 + c] = m[e];
            // fragment tile: chunk t = (m[2t], m[2t+1], m[2t+8], m[2t+9]),
            // rotated by (c>>1)&3 to keep store/load conflict-free
#pragma unroll
            for (int t = 0; t < 4; ++t) {
                float4 ch;
                ch.x = __uint_as_float(tf32r(m[2*t]));
                ch.y = __uint_as_float(tf32r(m[2*t + 1]));
                ch.z = __uint_as_float(tf32r(m[2*t + 8]));
                ch.w = __uint_as_float(tf32r(m[2*t + 9]));
                *(float4*)&ms1r_f[c * 16 + 4 * ((t + (c >> 1)) & 3)] = ch;
            }
        } else {
            // ms1T_f: transposed, natural column order + mixed score
#pragma unroll
            for (int e = 0; e < 16; ++e)
                ms1T_f[e * 136 + c] = __uint_as_float(tf32r(m[e]));
            float mx = b2_all[h];
#pragma unroll
            for (int f = 0; f < 16; ++f) mx = fmaf(m[f], w2s_all[h*16+f], mx);
            mixedrow[c] = mx;
        }
        __syncthreads();

        const float Mmax =
            fmaxf(fmaxf(fmaxf(Msm[0], Msm[1]), fmaxf(Msm[2], Msm[3])),
                  fmaxf(fmaxf(Msm[4], Msm[5]), fmaxf(Msm[6], Msm[7])));

        // ---- P2a: t-GEMM on tensor cores (t stays in registers) ----
        // A = ms1 rows Rw+g / Rw+g+8 (paired-e fragments); B = Waa.
        float4 tA = *(const float4*)&ms1r_f[(Rw + g)     * 16 + rot4];
        float4 tB = *(const float4*)&ms1r_f[(Rw + g + 8) * 16 + rot4];
        float tc0 = 0.f, tc1 = 0.f, tc2 = 0.f, tc3 = 0.f;
        float tc4 = 0.f, tc5 = 0.f, tc6 = 0.f, tc7 = 0.f;
        {
            uint32_t ax = __float_as_uint(tA.x), bx = __float_as_uint(tB.x);
            uint32_t ay = __float_as_uint(tA.y), by = __float_as_uint(tB.y);
            uint32_t az = __float_as_uint(tA.z), bz = __float_as_uint(tB.z);
            uint32_t aw = __float_as_uint(tA.w), bw = __float_as_uint(tB.w);
            // Waa B-fragments (k-slot tq <-> e=2tq etc.)
            uint32_t wb00 = tf32r(waa[(2*tq)   * 16 + g]);
            uint32_t wb01 = tf32r(waa[(2*tq+1) * 16 + g]);
            uint32_t wb10 = tf32r(waa[(8+2*tq) * 16 + g]);
            uint32_t wb11 = tf32r(waa[(9+2*tq) * 16 + g]);
            uint32_t wc00 = tf32r(waa[(2*tq)   * 16 + g + 8]);
            uint32_t wc01 = tf32r(waa[(2*tq+1) * 16 + g + 8]);
            uint32_t wc10 = tf32r(waa[(8+2*tq) * 16 + g + 8]);
            uint32_t wc11 = tf32r(waa[(9+2*tq) * 16 + g + 8]);
            mma8(tc0, tc1, tc2, tc3, ax, bx, ay, by, wb00, wb01);  // k0, x0-7
            mma8(tc0, tc1, tc2, tc3, az, bz, aw, bw, wb10, wb11);  // k1, x0-7
            mma8(tc4, tc5, tc6, tc7, ax, bx, ay, by, wc00, wc01);  // k0, x8-15
            mma8(tc4, tc5, tc6, tc7, az, bz, aw, bw, wc10, wc11);  // k1, x8-15
        }
        // srt per dd-row from t fragments (quad reduce over tq)
        float s_g  = fmaxf(tc0, 0.f) + fmaxf(tc1, 0.f)
                   + fmaxf(tc4, 0.f) + fmaxf(tc5, 0.f);
        float s_g8 = fmaxf(tc2, 0.f) + fmaxf(tc3, 0.f)
                   + fmaxf(tc6, 0.f) + fmaxf(tc7, 0.f);
        s_g  += __shfl_xor_sync(FULLMASK, s_g, 1);
        s_g  += __shfl_xor_sync(FULLMASK, s_g, 2);
        s_g8 += __shfl_xor_sync(FULLMASK, s_g8, 1);
        s_g8 += __shfl_xor_sync(FULLMASK, s_g8, 2);
        const float mub0 = Mmax * s_g;
        const float mub1 = Mmax * s_g8;

        // dd A-fragments = t C-fragments renamed (K-permutation, no data move)
        const uint32_t da0 = __float_as_uint(tc0), da1 = __float_as_uint(tc2);
        const uint32_t da2 = __float_as_uint(tc1), da3 = __float_as_uint(tc3);
        const uint32_t db0 = __float_as_uint(tc4), db1 = __float_as_uint(tc6);
        const uint32_t db2 = __float_as_uint(tc5), db3 = __float_as_uint(tc7);

        // ---- P2b: fused dd-mma -> ex2 -> rename -> ae-mma ----
        float sg0 = 0.f, sg1 = 0.f;
        float ae[8];
#pragma unroll
        for (int i = 0; i < 8; ++i) ae[i] = 0.f;

#pragma unroll
        for (int j = 0; j < 16; ++j) {
            float c0 = -mub0, c1 = -mub0, c2 = -mub1, c3 = -mub1;
            {
                float4 bv = *(const float4*)&ms1r_f[(8*j + g) * 16 + rot4];
                mma8(c0, c1, c2, c3, da0, da1, da2, da3,
                     __float_as_uint(bv.x), __float_as_uint(bv.y));
                mma8(c0, c1, c2, c3, db0, db1, db2, db3,
                     __float_as_uint(bv.z), __float_as_uint(bv.w));
            }
            float p0 = ex2(c0), p1 = ex2(c1), p2 = ex2(c2), p3 = ex2(c3);
            sg0 += p0 + p1; sg1 += p2 + p3;
            uint32_t a0 = __float_as_uint(p0);
            uint32_t a1 = __float_as_uint(p2);
            uint32_t a2 = __float_as_uint(p1);
            uint32_t a3 = __float_as_uint(p3);
#pragma unroll
            for (int nt = 0; nt < 2; ++nt) {
                float2 bv = *(const float2*)&ms1T_f[(8*nt + g) * 136 + j*8 + 2*tq];
                mma8(ae[nt*4], ae[nt*4+1], ae[nt*4+2], ae[nt*4+3],
                     a0, a1, a2, a3,
                     __float_as_uint(bv.x), __float_as_uint(bv.y));
            }
        }
        // row sums (quad reduce) and normalized aeT stores
        sg0 += __shfl_xor_sync(FULLMASK, sg0, 1);
        sg0 += __shfl_xor_sync(FULLMASK, sg0, 2);
        sg1 += __shfl_xor_sync(FULLMASK, sg1, 1);
        sg1 += __shfl_xor_sync(FULLMASK, sg1, 2);
        const float inv0 = 1.f / sg0, inv1 = 1.f / sg1;
#pragma unroll
        for (int nt = 0; nt < 2; ++nt) {
            aeT[(8*nt + 2*tq)    *132 + Rw + g]     = ae[nt*4]   * inv0;
            aeT[(8*nt + 2*tq + 1)*132 + Rw + g]     = ae[nt*4+1] * inv0;
            aeT[(8*nt + 2*tq)    *132 + Rw + g + 8] = ae[nt*4+2] * inv1;
            aeT[(8*nt + 2*tq + 1)*132 + Rw + g + 8] = ae[nt*4+3] * inv1;
        }
        __syncthreads();

        // ---- P3: LayerNorm over C; exact fp32 residual from ms1T_e ----
#pragma unroll
        for (int ei = 0; ei < 2; ++ei) {
            int e = w + ei * 8;
            float x0 = aeT[e * 132 + l]      + ms1T_e[e * 132 + l];
            float x1 = aeT[e * 132 + l + 32] + ms1T_e[e * 132 + l + 32];
            float x2 = aeT[e * 132 + l + 64] + ms1T_e[e * 132 + l + 64];
            float x3 = aeT[e * 132 + l + 96] + ms1T_e[e * 132 + l + 96];
            float s1v = x0 + x1 + x2 + x3;
            float sq = x0 * x0 + x1 * x1 + x2 * x2 + x3 * x3;
#pragma unroll
            for (int o = 16; o; o >>= 1) {
                s1v += __shfl_xor_sync(FULLMASK, s1v, o);
                sq  += __shfl_xor_sync(FULLMASK, sq, o);
            }
            float mean = s1v * (1.f / 128.f);
            float var  = sq * (1.f / 128.f) - mean * mean;
            float rs = rsqrtf(var + 1e-5f);
            aeT[e * 132 + l]      = (x0 - mean) * rs * lng[l]      + lnb[l];
            aeT[e * 132 + l + 32] = (x1 - mean) * rs * lng[l + 32] + lnb[l + 32];
            aeT[e * 132 + l + 64] = (x2 - mean) * rs * lng[l + 64] + lnb[l + 64];
            aeT[e * 132 + l + 96] = (x3 - mean) * rs * lng[l + 96] + lnb[l + 96];
        }
        __syncthreads();

        // ---- P4: edge (half 0) + mixed softmax attention (half 1) ----
        if (half == 0) {
            float acc = edge[c];
#pragma unroll
            for (int e = 0; e < 16; ++e)
                acc = fmaf(aeT[e * 132 + c], ews_all[h * 16 + e], acc);
            edge[c] = acc;
        } else {
            int ww = w - 4;
            float m0 = mixedrow[l],      m1 = mixedrow[l + 32];
            float m2 = mixedrow[l + 64], m3 = mixedrow[l + 96];
            float mx = fmaxf(fmaxf(m0, m1), fmaxf(m2, m3));
#pragma unroll
            for (int o = 16; o; o >>= 1) mx = fmaxf(mx, __shfl_xor_sync(FULLMASK, mx, o));
            float p0 = __expf(m0 - mx), p1 = __expf(m1 - mx);
            float p2 = __expf(m2 - mx), p3 = __expf(m3 - mx);
            float ssum = p0 + p1 + p2 + p3;
#pragma unroll
            for (int o = 16; o; o >>= 1) ssum += __shfl_xor_sync(FULLMASK, ssum, o);
            float inv = 1.f / ssum;
            const float* vb = v + (b * KH + h) * KC * KDQ;
#pragma unroll
            for (int d0 = 0; d0 < 4; ++d0) {
                int dq = ww * 4 + d0;
                float a = p0 * vb[l * 16 + dq] + p1 * vb[(l + 32) * 16 + dq]
                        + p2 * vb[(l + 64) * 16 + dq] + p3 * vb[(l + 96) * 16 + dq];
#pragma unroll
                for (int o = 16; o; o >>= 1) a += __shfl_xor_sync(FULLMASK, a, o);
                if (l == 0)
                    out[(b * KR + r) * (KH * KDQ) + h * KDQ + dq] = a * inv;
            }
        }
        __syncthreads();
    }

    if (tid < 128)
        out[KB * KR * KH * KDQ + br * 128 + tid] = edge[tid] + edge_b[0];
}

extern "C" void kernel_launch(void* const* d_in, const int* in_sizes, int n_in,
                              void* d_out, int out_size) {
    const float* q    = (const float*)d_in[0];
    const float* k_s  = (const float*)d_in[1];
    const float* k_a  = (const float*)d_in[2];
    const float* v    = (const float*)d_in[3];
    const float* cost = (const float*)d_in[4];
    const float* m1w  = (const float*)d_in[5];
    const float* m1b  = (const float*)d_in[6];
    const float* waa  = (const float*)d_in[7];
    const float* m2w  = (const float*)d_in[8];
    const float* m2b  = (const float*)d_in[9];
    const float* ew   = (const float*)d_in[10];
    const float* eb   = (const float*)d_in[11];
    const float* lng  = (const float*)d_in[12];
    const float* lnb  = (const float*)d_in[13];
    float* out = (float*)d_out;

    cudaFuncSetAttribute(k1_score, cudaFuncAttributeMaxDynamicSharedMemorySize, 98816);
    cudaFuncSetAttribute(k2_main,  cudaFuncAttributeMaxDynamicSharedMemorySize, 40000);

    k1_score<<<KB * KH * 4, 256, 98816>>>(q, k_s, k_a);
    k2_main<<<KB * KR, 256, 40000>>>(cost, m1w, m1b, waa, m2w, m2b, ew, eb,
                                     lng, lnb, v, out);
}

// round 13
// speedup vs baseline: 4.1780x; 1.0593x over previous
#include <cuda_runtime.h>
#include <cstdint>

#define FULLMASK 0xffffffffu
#define KB 8
#define KH 8
#define KR 128
#define KC 128
#define KDQ 16
#define L2E 1.4426950408889634f

__device__ float g_score[KB * KH * KR * KC];

__device__ __forceinline__ float ex2(float x) {
    float r;
    asm("ex2.approx.f32 %0, %1;" : "=f"(r) : "f"(x));
    return r;
}
__device__ __forceinline__ uint32_t tf32r(float f) {
    uint32_t u;
    asm("cvt.rna.tf32.f32 %0, %1;" : "=r"(u) : "f"(f));
    return u;
}
__device__ __forceinline__ void mma8(float& c0, float& c1, float& c2, float& c3,
                                     uint32_t a0, uint32_t a1, uint32_t a2,
                                     uint32_t a3, uint32_t b0, uint32_t b1) {
    asm volatile(
        "mma.sync.aligned.m16n8k8.row.col.f32.tf32.tf32.f32 "
        "{%0,%1,%2,%3}, {%4,%5,%6,%7}, {%8,%9}, {%0,%1,%2,%3};"
        : "+f"(c0), "+f"(c1), "+f"(c2), "+f"(c3)
        : "r"(a0), "r"(a1), "r"(a2), "r"(a3), "r"(b0), "r"(b1));
}

// ---------------------------------------------------------------------------
// Kernel 1 (unchanged, proven): grid 256, 256 thr, smem 98816
// ---------------------------------------------------------------------------
__global__ __launch_bounds__(256) void k1_score(const float* __restrict__ q,
                                                const float* __restrict__ ks,
                                                const float* __restrict__ ka) {
    extern __shared__ float sm[];
    float* ksT  = sm;
    float* kaT  = sm + 2112;
    float* qrow = sm + 4224;
    float* pbuf = sm + 6272;
    float* dpa  = sm + 7296;

    const int bh      = blockIdx.x >> 2;
    const int quarter = blockIdx.x & 3;
    const int tid = threadIdx.x;
    const float* qb  = q  + bh * 2048;
    const float* ksb = ks + bh * 2048;
    const float* kab = ka + bh * 2048;

    for (int i = tid; i < 2048; i += 256) {
        int srow = i >> 4, e = i & 15;
        ksT[e * 132 + srow] = ksb[i];
        kaT[e * 132 + srow] = kab[i];
        qrow[i] = qb[i];
    }
    __syncthreads();

    const int w = tid >> 5, l = tid & 31;

    for (int k = 0; k < 16; ++k) {
        int r = w * 16 + k;
        float qr[16];
#pragma unroll
        for (int j = 0; j < 4; ++j) {
            float4 v4 = *(const float4*)&qrow[r * 16 + 4 * j];
            qr[4*j] = v4.x; qr[4*j+1] = v4.y; qr[4*j+2] = v4.z; qr[4*j+3] = v4.w;
        }
        float a0 = 0.f, a1 = 0.f, a2 = 0.f, a3 = 0.f;
#pragma unroll
        for (int e = 0; e < 16; ++e) {
            float4 kk = *(const float4*)&kaT[e * 132 + 4 * l];
            a0 = fmaf(qr[e], kk.x, a0); a1 = fmaf(qr[e], kk.y, a1);
            a2 = fmaf(qr[e], kk.z, a2); a3 = fmaf(qr[e], kk.w, a3);
        }
        float4 o;
        o.x = fmaxf(a0 * 0.25f, 0.f); o.y = fmaxf(a1 * 0.25f, 0.f);
        o.z = fmaxf(a2 * 0.25f, 0.f); o.w = fmaxf(a3 * 0.25f, 0.f);
        *(float4*)&dpa[r * 136 + 4 * l] = o;
    }
    __syncthreads();

    for (int k = 0; k < 4; ++k) {
        int r = quarter * 32 + w * 4 + k;
        float qr[16];
#pragma unroll
        for (int j = 0; j < 4; ++j) {
            float4 v4 = *(const float4*)&qrow[r * 16 + 4 * j];
            qr[4*j] = v4.x; qr[4*j+1] = v4.y; qr[4*j+2] = v4.z; qr[4*j+3] = v4.w;
        }
        float a0 = 0.f, a1 = 0.f, a2 = 0.f, a3 = 0.f;
#pragma unroll
        for (int e = 0; e < 16; ++e) {
            float4 kk = *(const float4*)&ksT[e * 132 + 4 * l];
            a0 = fmaf(qr[e], kk.x, a0); a1 = fmaf(qr[e], kk.y, a1);
            a2 = fmaf(qr[e], kk.z, a2); a3 = fmaf(qr[e], kk.w, a3);
        }
        float x0 = a0 * 0.25f, x1 = a1 * 0.25f, x2 = a2 * 0.25f, x3 = a3 * 0.25f;
        a0 = x0 * normcdff(x0); a1 = x1 * normcdff(x1);
        a2 = x2 * normcdff(x2); a3 = x3 * normcdff(x3);
        float mx = fmaxf(fmaxf(a0, a1), fmaxf(a2, a3));
#pragma unroll
        for (int o = 16; o; o >>= 1) mx = fmaxf(mx, __shfl_xor_sync(FULLMASK, mx, o));
        float p0 = __expf(a0 - mx), p1 = __expf(a1 - mx);
        float p2 = __expf(a2 - mx), p3 = __expf(a3 - mx);
        float ssum = p0 + p1 + p2 + p3;
#pragma unroll
        for (int o = 16; o; o >>= 1) ssum += __shfl_xor_sync(FULLMASK, ssum, o);
        float inv = 1.f / ssum;
        *(float4*)&pbuf[w * 128 + 4 * l] = make_float4(p0*inv, p1*inv, p2*inv, p3*inv);
        __syncwarp();
        float c0 = 0.f, c1 = 0.f, c2 = 0.f, c3 = 0.f;
#pragma unroll 4
        for (int s2 = 0; s2 < 128; ++s2) {
            float pvv = pbuf[w * 128 + s2];
            float4 dv = *(const float4*)&dpa[s2 * 136 + 4 * l];
            c0 = fmaf(pvv, dv.x, c0); c1 = fmaf(pvv, dv.y, c1);
            c2 = fmaf(pvv, dv.z, c2); c3 = fmaf(pvv, dv.w, c3);
        }
        *(float4*)&g_score[(bh * 128 + r) * 128 + 4 * l] =
            make_float4(c0*0.25f, c1*0.25f, c2*0.25f, c3*0.25f);
        __syncwarp();
    }
}

// ---------------------------------------------------------------------------
// Kernel 2: tensor-core t/dd/ae GEMMs; 3 barriers per head; padded waa;
// float4 broadcast weights; LN overlapped with mixed attention.
// grid 1024, 256 thr; dynamic smem 40256 B -> 4 CTAs/SM.
// ---------------------------------------------------------------------------
__global__ __launch_bounds__(256, 4) void k2_main(
    const float* __restrict__ cost_mat,
    const float* __restrict__ mix1_w, const float* __restrict__ mix1_b,
    const float* __restrict__ Waa,
    const float* __restrict__ mix2_w, const float* __restrict__ mix2_b,
    const float* __restrict__ edge_w, const float* __restrict__ edge_b,
    const float* __restrict__ ln_g,  const float* __restrict__ ln_b,
    const float* __restrict__ v, float* __restrict__ out) {
    extern __shared__ float sm[];
    float* waa      = sm;            // [16][20] current head, L2E-scaled, padded
    float* w1a_all  = sm + 320;
    float* w1b_all  = sm + 448;
    float* b1s_all  = sm + 576;
    float* w2s_all  = sm + 704;
    float* ews_all  = sm + 832;
    float* b2_all   = sm + 960;      // [8]
    float* costrow  = sm + 968;
    float* lng      = sm + 1096;
    float* lnb      = sm + 1224;
    float* mixedrow = sm + 1352;
    float* edge     = sm + 1480;
    float* Msm      = sm + 1608;     // [8]
    float* ms1T_e   = sm + 1616;     // [16][132] exact fp32 (LN residual)
    float* ms1r_f   = sm + 3728;     // [128][16] tf32 ms1, paired-e frag chunks
    float* ms1T_f   = sm + 5776;     // [16][136] tf32 ms1^T, natural order
    float* aeT      = sm + 7952;     // [16][132]

    const int tid = threadIdx.x;
    const int w = tid >> 5, l = tid & 31;
    const int c = tid & 127;
    const int half = tid >> 7;
    const int g = l >> 2, tq = l & 3;
    const int Rw = w * 16;
    const int rot4 = 4 * ((tq + (g >> 1)) & 3);

    const int br = blockIdx.x;
    const int b = br >> 7, r = br & 127;

    if (tid < 128) {
        int h0 = tid >> 4, e0 = tid & 15;
        w1a_all[tid] = mix1_w[h0 * 32 + e0];
        w1b_all[tid] = mix1_w[h0 * 32 + 16 + e0];
        b1s_all[tid] = mix1_b[tid];
        w2s_all[tid] = mix2_w[tid];
        ews_all[tid] = edge_w[tid];
        costrow[tid] = cost_mat[br * 128 + tid];
        lng[tid] = ln_g[tid];
        lnb[tid] = ln_b[tid];
        edge[tid] = 0.f;
    }
    if (tid < 8) b2_all[tid] = mix2_b[tid];
    __syncthreads();

    for (int h = 0; h < KH; ++h) {
        // per-head Waa reload into padded [16][20] (conflict-free in P2a)
        waa[(tid >> 4) * 20 + (tid & 15)] = Waa[h * 256 + tid] * L2E;

        // ---- P1: ms1 row c -> tiles; mixed; tile max ----
        float sc = g_score[((b * KH + h) * KR + r) * KC + c];
        float co = costrow[c];
        float m[16];
        {
            const float4* wa4 = (const float4*)&w1a_all[h * 16];
            const float4* wb4 = (const float4*)&w1b_all[h * 16];
            const float4* bi4 = (const float4*)&b1s_all[h * 16];
#pragma unroll
            for (int j = 0; j < 4; ++j) {
                float4 a = wa4[j], bq = wb4[j], bi = bi4[j];
                m[4*j+0] = fmaxf(fmaf(sc, a.x, fmaf(co, bq.x, bi.x)), 0.f);
                m[4*j+1] = fmaxf(fmaf(sc, a.y, fmaf(co, bq.y, bi.y)), 0.f);
                m[4*j+2] = fmaxf(fmaf(sc, a.z, fmaf(co, bq.z, bi.z)), 0.f);
                m[4*j+3] = fmaxf(fmaf(sc, a.w, fmaf(co, bq.w, bi.w)), 0.f);
            }
        }
        {
            float rm = m[0];
#pragma unroll
            for (int e = 1; e < 16; ++e) rm = fmaxf(rm, m[e]);
#pragma unroll
            for (int o = 16; o; o >>= 1) rm = fmaxf(rm, __shfl_xor_sync(FULLMASK, rm, o));
            if (l == 0) Msm[w] = rm;
        }
        if (half == 0) {
            // exact residual tile (transposed, conflict-free)
#pragma unroll
            for (int e = 0; e < 16; ++e) ms1T_e[e * 132 + c] = m[e];
            // fragment tile: chunk t = (m[2t], m[2t+1], m[2t+8], m[2t+9]), rotated
#pragma unroll
            for (int t = 0; t < 4; ++t) {
                float4 ch;
                ch.x = __uint_as_float(tf32r(m[2*t]));
                ch.y = __uint_as_float(tf32r(m[2*t + 1]));
                ch.z = __uint_as_float(tf32r(m[2*t + 8]));
                ch.w = __uint_as_float(tf32r(m[2*t + 9]));
                *(float4*)&ms1r_f[c * 16 + 4 * ((t + (c >> 1)) & 3)] = ch;
            }
        } else {
            // ms1T_f: transposed, natural column order + mixed score
#pragma unroll
            for (int e = 0; e < 16; ++e)
                ms1T_f[e * 136 + c] = __uint_as_float(tf32r(m[e]));
            float mx = b2_all[h];
            const float4* w24 = (const float4*)&w2s_all[h * 16];
#pragma unroll
            for (int j = 0; j < 4; ++j) {
                float4 ww = w24[j];
                mx = fmaf(m[4*j],   ww.x, mx); mx = fmaf(m[4*j+1], ww.y, mx);
                mx = fmaf(m[4*j+2], ww.z, mx); mx = fmaf(m[4*j+3], ww.w, mx);
            }
            mixedrow[c] = mx;
        }
        __syncthreads();   // B1

        const float Mmax =
            fmaxf(fmaxf(fmaxf(Msm[0], Msm[1]), fmaxf(Msm[2], Msm[3])),
                  fmaxf(fmaxf(Msm[4], Msm[5]), fmaxf(Msm[6], Msm[7])));

        // ---- P2a: t-GEMM on tensor cores (t stays in registers) ----
        float4 tA = *(const float4*)&ms1r_f[(Rw + g)     * 16 + rot4];
        float4 tB = *(const float4*)&ms1r_f[(Rw + g + 8) * 16 + rot4];
        float tc0 = 0.f, tc1 = 0.f, tc2 = 0.f, tc3 = 0.f;
        float tc4 = 0.f, tc5 = 0.f, tc6 = 0.f, tc7 = 0.f;
        {
            uint32_t ax = __float_as_uint(tA.x), bx = __float_as_uint(tB.x);
            uint32_t ay = __float_as_uint(tA.y), by = __float_as_uint(tB.y);
            uint32_t az = __float_as_uint(tA.z), bz = __float_as_uint(tB.z);
            uint32_t aw = __float_as_uint(tA.w), bw = __float_as_uint(tB.w);
            uint32_t wb00 = tf32r(waa[(2*tq)   * 20 + g]);
            uint32_t wb01 = tf32r(waa[(2*tq+1) * 20 + g]);
            uint32_t wb10 = tf32r(waa[(8+2*tq) * 20 + g]);
            uint32_t wb11 = tf32r(waa[(9+2*tq) * 20 + g]);
            uint32_t wc00 = tf32r(waa[(2*tq)   * 20 + g + 8]);
            uint32_t wc01 = tf32r(waa[(2*tq+1) * 20 + g + 8]);
            uint32_t wc10 = tf32r(waa[(8+2*tq) * 20 + g + 8]);
            uint32_t wc11 = tf32r(waa[(9+2*tq) * 20 + g + 8]);
            mma8(tc0, tc1, tc2, tc3, ax, bx, ay, by, wb00, wb01);
            mma8(tc0, tc1, tc2, tc3, az, bz, aw, bw, wb10, wb11);
            mma8(tc4, tc5, tc6, tc7, ax, bx, ay, by, wc00, wc01);
            mma8(tc4, tc5, tc6, tc7, az, bz, aw, bw, wc10, wc11);
        }
        float s_g  = fmaxf(tc0, 0.f) + fmaxf(tc1, 0.f)
                   + fmaxf(tc4, 0.f) + fmaxf(tc5, 0.f);
        float s_g8 = fmaxf(tc2, 0.f) + fmaxf(tc3, 0.f)
                   + fmaxf(tc6, 0.f) + fmaxf(tc7, 0.f);
        s_g  += __shfl_xor_sync(FULLMASK, s_g, 1);
        s_g  += __shfl_xor_sync(FULLMASK, s_g, 2);
        s_g8 += __shfl_xor_sync(FULLMASK, s_g8, 1);
        s_g8 += __shfl_xor_sync(FULLMASK, s_g8, 2);
        const float mub0 = Mmax * s_g;
        const float mub1 = Mmax * s_g8;

        const uint32_t da0 = __float_as_uint(tc0), da1 = __float_as_uint(tc2);
        const uint32_t da2 = __float_as_uint(tc1), da3 = __float_as_uint(tc3);
        const uint32_t db0 = __float_as_uint(tc4), db1 = __float_as_uint(tc6);
        const uint32_t db2 = __float_as_uint(tc5), db3 = __float_as_uint(tc7);

        // ---- P2b: fused dd-mma -> ex2 -> rename -> ae-mma ----
        float sg0 = 0.f, sg1 = 0.f;
        float ae[8];
#pragma unroll
        for (int i = 0; i < 8; ++i) ae[i] = 0.f;

#pragma unroll
        for (int j = 0; j < 16; ++j) {
            float c0 = -mub0, c1 = -mub0, c2 = -mub1, c3 = -mub1;
            {
                float4 bv = *(const float4*)&ms1r_f[(8*j + g) * 16 + rot4];
                mma8(c0, c1, c2, c3, da0, da1, da2, da3,
                     __float_as_uint(bv.x), __float_as_uint(bv.y));
                mma8(c0, c1, c2, c3, db0, db1, db2, db3,
                     __float_as_uint(bv.z), __float_as_uint(bv.w));
            }
            float p0 = ex2(c0), p1 = ex2(c1), p2 = ex2(c2), p3 = ex2(c3);
            sg0 += p0 + p1; sg1 += p2 + p3;
            uint32_t a0 = __float_as_uint(p0);
            uint32_t a1 = __float_as_uint(p2);
            uint32_t a2 = __float_as_uint(p1);
            uint32_t a3 = __float_as_uint(p3);
#pragma unroll
            for (int nt = 0; nt < 2; ++nt) {
                float2 bv = *(const float2*)&ms1T_f[(8*nt + g) * 136 + j*8 + 2*tq];
                mma8(ae[nt*4], ae[nt*4+1], ae[nt*4+2], ae[nt*4+3],
                     a0, a1, a2, a3,
                     __float_as_uint(bv.x), __float_as_uint(bv.y));
            }
        }
        sg0 += __shfl_xor_sync(FULLMASK, sg0, 1);
        sg0 += __shfl_xor_sync(FULLMASK, sg0, 2);
        sg1 += __shfl_xor_sync(FULLMASK, sg1, 1);
        sg1 += __shfl_xor_sync(FULLMASK, sg1, 2);
        const float inv0 = 1.f / sg0, inv1 = 1.f / sg1;
#pragma unroll
        for (int nt = 0; nt < 2; ++nt) {
            aeT[(8*nt + 2*tq)    *132 + Rw + g]     = ae[nt*4]   * inv0;
            aeT[(8*nt + 2*tq + 1)*132 + Rw + g]     = ae[nt*4+1] * inv0;
            aeT[(8*nt + 2*tq)    *132 + Rw + g + 8] = ae[nt*4+2] * inv1;
            aeT[(8*nt + 2*tq + 1)*132 + Rw + g + 8] = ae[nt*4+3] * inv1;
        }
        __syncthreads();   // B2

        // ---- P3 (warps 0-3: LN over C, 4 features each)
        // ---- in parallel with mixed softmax attention (warps 4-7) ----
        if (w < 4) {
#pragma unroll
            for (int ei = 0; ei < 4; ++ei) {
                int e = w * 4 + ei;
                float x0 = aeT[e * 132 + l]      + ms1T_e[e * 132 + l];
                float x1 = aeT[e * 132 + l + 32] + ms1T_e[e * 132 + l + 32];
                float x2 = aeT[e * 132 + l + 64] + ms1T_e[e * 132 + l + 64];
                float x3 = aeT[e * 132 + l + 96] + ms1T_e[e * 132 + l + 96];
                float s1v = x0 + x1 + x2 + x3;
                float sq = x0 * x0 + x1 * x1 + x2 * x2 + x3 * x3;
#pragma unroll
                for (int o = 16; o; o >>= 1) {
                    s1v += __shfl_xor_sync(FULLMASK, s1v, o);
                    sq  += __shfl_xor_sync(FULLMASK, sq, o);
                }
                float mean = s1v * (1.f / 128.f);
                float var  = sq * (1.f / 128.f) - mean * mean;
                float rs = rsqrtf(var + 1e-5f);
                aeT[e * 132 + l]      = (x0 - mean) * rs * lng[l]      + lnb[l];
                aeT[e * 132 + l + 32] = (x1 - mean) * rs * lng[l + 32] + lnb[l + 32];
                aeT[e * 132 + l + 64] = (x2 - mean) * rs * lng[l + 64] + lnb[l + 64];
                aeT[e * 132 + l + 96] = (x3 - mean) * rs * lng[l + 96] + lnb[l + 96];
            }
        } else {
            int ww = w - 4;
            float m0 = mixedrow[l],      m1 = mixedrow[l + 32];
            float m2 = mixedrow[l + 64], m3 = mixedrow[l + 96];
            float mx = fmaxf(fmaxf(m0, m1), fmaxf(m2, m3));
#pragma unroll
            for (int o = 16; o; o >>= 1) mx = fmaxf(mx, __shfl_xor_sync(FULLMASK, mx, o));
            float p0 = __expf(m0 - mx), p1 = __expf(m1 - mx);
            float p2 = __expf(m2 - mx), p3 = __expf(m3 - mx);
            float ssum = p0 + p1 + p2 + p3;
#pragma unroll
            for (int o = 16; o; o >>= 1) ssum += __shfl_xor_sync(FULLMASK, ssum, o);
            float inv = 1.f / ssum;
            const float* vb = v + (b * KH + h) * KC * KDQ;
#pragma unroll
            for (int d0 = 0; d0 < 4; ++d0) {
                int dq = ww * 4 + d0;
                float a = p0 * vb[l * 16 + dq] + p1 * vb[(l + 32) * 16 + dq]
                        + p2 * vb[(l + 64) * 16 + dq] + p3 * vb[(l + 96) * 16 + dq];
#pragma unroll
                for (int o = 16; o; o >>= 1) a += __shfl_xor_sync(FULLMASK, a, o);
                if (l == 0)
                    out[(b * KR + r) * (KH * KDQ) + h * KDQ + dq] = a * inv;
            }
        }
        __syncthreads();   // B3

        // ---- edge accumulation (reads aeT; overlaps next-head P1 safely) ----
        if (tid < 128) {
            const float4* ew4 = (const float4*)&ews_all[h * 16];
            float acc = edge[c];
#pragma unroll
            for (int j = 0; j < 4; ++j) {
                float4 ew = ew4[j];
                acc = fmaf(aeT[(4*j)     * 132 + c], ew.x, acc);
                acc = fmaf(aeT[(4*j + 1) * 132 + c], ew.y, acc);
                acc = fmaf(aeT[(4*j + 2) * 132 + c], ew.z, acc);
                acc = fmaf(aeT[(4*j + 3) * 132 + c], ew.w, acc);
            }
            edge[c] = acc;
        }
        // no barrier: next-head P1 writes only ms1*/mixedrow/waa/Msm (not aeT),
        // and aeT is next written after B1 of the next head.
    }

    if (tid < 128)
        out[KB * KR * KH * KDQ + br * 128 + tid] = edge[tid] + edge_b[0];
}

extern "C" void kernel_launch(void* const* d_in, const int* in_sizes, int n_in,
                              void* d_out, int out_size) {
    const float* q    = (const float*)d_in[0];
    const float* k_s  = (const float*)d_in[1];
    const float* k_a  = (const float*)d_in[2];
    const float* v    = (const float*)d_in[3];
    const float* cost = (const float*)d_in[4];
    const float* m1w  = (const float*)d_in[5];
    const float* m1b  = (const float*)d_in[6];
    const float* waa  = (const float*)d_in[7];
    const float* m2w  = (const float*)d_in[8];
    const float* m2b  = (const float*)d_in[9];
    const float* ew   = (const float*)d_in[10];
    const float* eb   = (const float*)d_in[11];
    const float* lng  = (const float*)d_in[12];
    const float* lnb  = (const float*)d_in[13];
    float* out = (float*)d_out;

    cudaFuncSetAttribute(k1_score, cudaFuncAttributeMaxDynamicSharedMemorySize, 98816);
    cudaFuncSetAttribute(k2_main,  cudaFuncAttributeMaxDynamicSharedMemorySize, 40256);

    k1_score<<<KB * KH * 4, 256, 98816>>>(q, k_s, k_a);
    k2_main<<<KB * KR, 256, 40256>>>(cost, m1w, m1b, waa, m2w, m2b, ew, eb,
                                     lng, lnb, v, out);
}

// round 14
// speedup vs baseline: 4.2827x; 1.0251x over previous
#include <cuda_runtime.h>
#include <cstdint>

#define FULLMASK 0xffffffffu
#define KB 8
#define KH 8
#define KR 128
#define KC 128
#define KDQ 16
#define L2E 1.4426950408889634f

__device__ float g_score[KB * KH * KR * KC];

__device__ __forceinline__ float ex2(float x) {
    float r;
    asm("ex2.approx.f32 %0, %1;" : "=f"(r) : "f"(x));
    return r;
}
__device__ __forceinline__ uint32_t tf32r(float f) {
    uint32_t u;
    asm("cvt.rna.tf32.f32 %0, %1;" : "=r"(u) : "f"(f));
    return u;
}
__device__ __forceinline__ void mma8(float& c0, float& c1, float& c2, float& c3,
                                     uint32_t a0, uint32_t a1, uint32_t a2,
                                     uint32_t a3, uint32_t b0, uint32_t b1) {
    asm volatile(
        "mma.sync.aligned.m16n8k8.row.col.f32.tf32.tf32.f32 "
        "{%0,%1,%2,%3}, {%4,%5,%6,%7}, {%8,%9}, {%0,%1,%2,%3};"
        : "+f"(c0), "+f"(c1), "+f"(c2), "+f"(c3)
        : "r"(a0), "r"(a1), "r"(a2), "r"(a3), "r"(b0), "r"(b1));
}
__device__ __forceinline__ void gbar(int grp) {
    asm volatile("bar.sync %0, 128;" :: "r"(grp + 1) : "memory");
}

// ---------------------------------------------------------------------------
// Kernel 1 (unchanged, proven): grid 256, 256 thr, smem 98816
// ---------------------------------------------------------------------------
__global__ __launch_bounds__(256) void k1_score(const float* __restrict__ q,
                                                const float* __restrict__ ks,
                                                const float* __restrict__ ka) {
    extern __shared__ float sm[];
    float* ksT  = sm;
    float* kaT  = sm + 2112;
    float* qrow = sm + 4224;
    float* pbuf = sm + 6272;
    float* dpa  = sm + 7296;

    const int bh      = blockIdx.x >> 2;
    const int quarter = blockIdx.x & 3;
    const int tid = threadIdx.x;
    const float* qb  = q  + bh * 2048;
    const float* ksb = ks + bh * 2048;
    const float* kab = ka + bh * 2048;

    for (int i = tid; i < 2048; i += 256) {
        int srow = i >> 4, e = i & 15;
        ksT[e * 132 + srow] = ksb[i];
        kaT[e * 132 + srow] = kab[i];
        qrow[i] = qb[i];
    }
    __syncthreads();

    const int w = tid >> 5, l = tid & 31;

    for (int k = 0; k < 16; ++k) {
        int r = w * 16 + k;
        float qr[16];
#pragma unroll
        for (int j = 0; j < 4; ++j) {
            float4 v4 = *(const float4*)&qrow[r * 16 + 4 * j];
            qr[4*j] = v4.x; qr[4*j+1] = v4.y; qr[4*j+2] = v4.z; qr[4*j+3] = v4.w;
        }
        float a0 = 0.f, a1 = 0.f, a2 = 0.f, a3 = 0.f;
#pragma unroll
        for (int e = 0; e < 16; ++e) {
            float4 kk = *(const float4*)&kaT[e * 132 + 4 * l];
            a0 = fmaf(qr[e], kk.x, a0); a1 = fmaf(qr[e], kk.y, a1);
            a2 = fmaf(qr[e], kk.z, a2); a3 = fmaf(qr[e], kk.w, a3);
        }
        float4 o;
        o.x = fmaxf(a0 * 0.25f, 0.f); o.y = fmaxf(a1 * 0.25f, 0.f);
        o.z = fmaxf(a2 * 0.25f, 0.f); o.w = fmaxf(a3 * 0.25f, 0.f);
        *(float4*)&dpa[r * 136 + 4 * l] = o;
    }
    __syncthreads();

    for (int k = 0; k < 4; ++k) {
        int r = quarter * 32 + w * 4 + k;
        float qr[16];
#pragma unroll
        for (int j = 0; j < 4; ++j) {
            float4 v4 = *(const float4*)&qrow[r * 16 + 4 * j];
            qr[4*j] = v4.x; qr[4*j+1] = v4.y; qr[4*j+2] = v4.z; qr[4*j+3] = v4.w;
        }
        float a0 = 0.f, a1 = 0.f, a2 = 0.f, a3 = 0.f;
#pragma unroll
        for (int e = 0; e < 16; ++e) {
            float4 kk = *(const float4*)&ksT[e * 132 + 4 * l];
            a0 = fmaf(qr[e], kk.x, a0); a1 = fmaf(qr[e], kk.y, a1);
            a2 = fmaf(qr[e], kk.z, a2); a3 = fmaf(qr[e], kk.w, a3);
        }
        float x0 = a0 * 0.25f, x1 = a1 * 0.25f, x2 = a2 * 0.25f, x3 = a3 * 0.25f;
        a0 = x0 * normcdff(x0); a1 = x1 * normcdff(x1);
        a2 = x2 * normcdff(x2); a3 = x3 * normcdff(x3);
        float mx = fmaxf(fmaxf(a0, a1), fmaxf(a2, a3));
#pragma unroll
        for (int o = 16; o; o >>= 1) mx = fmaxf(mx, __shfl_xor_sync(FULLMASK, mx, o));
        float p0 = __expf(a0 - mx), p1 = __expf(a1 - mx);
        float p2 = __expf(a2 - mx), p3 = __expf(a3 - mx);
        float ssum = p0 + p1 + p2 + p3;
#pragma unroll
        for (int o = 16; o; o >>= 1) ssum += __shfl_xor_sync(FULLMASK, ssum, o);
        float inv = 1.f / ssum;
        *(float4*)&pbuf[w * 128 + 4 * l] = make_float4(p0*inv, p1*inv, p2*inv, p3*inv);
        __syncwarp();
        float c0 = 0.f, c1 = 0.f, c2 = 0.f, c3 = 0.f;
#pragma unroll 4
        for (int s2 = 0; s2 < 128; ++s2) {
            float pvv = pbuf[w * 128 + s2];
            float4 dv = *(const float4*)&dpa[s2 * 136 + 4 * l];
            c0 = fmaf(pvv, dv.x, c0); c1 = fmaf(pvv, dv.y, c1);
            c2 = fmaf(pvv, dv.z, c2); c3 = fmaf(pvv, dv.w, c3);
        }
        *(float4*)&g_score[(bh * 128 + r) * 128 + 4 * l] =
            make_float4(c0*0.25f, c1*0.25f, c2*0.25f, c3*0.25f);
        __syncwarp();
    }
}

// ---------------------------------------------------------------------------
// Kernel 2: two independent 4-warp engines per CTA (group grp handles heads
// 4grp..4grp+3); each warp owns 32 dd-rows (2 M-tiles) so B-fragments are
// amortized 2x. LN residual recomputed exactly from scrow (bit-identical).
// grid 1024, 256 thr; dynamic smem 60480 B -> 3 CTAs/SM.
// ---------------------------------------------------------------------------
__global__ __launch_bounds__(256, 3) void k2_main(
    const float* __restrict__ cost_mat,
    const float* __restrict__ mix1_w, const float* __restrict__ mix1_b,
    const float* __restrict__ Waa,
    const float* __restrict__ mix2_w, const float* __restrict__ mix2_b,
    const float* __restrict__ edge_w, const float* __restrict__ edge_b,
    const float* __restrict__ ln_g,  const float* __restrict__ ln_b,
    const float* __restrict__ v, float* __restrict__ out) {
    extern __shared__ float sm[];
    float* w1a_all  = sm;            // [8][16]
    float* w1b_all  = sm + 128;
    float* b1s_all  = sm + 256;
    float* w2s_all  = sm + 384;
    float* ews_all  = sm + 512;
    float* costrow  = sm + 640;
    float* lng      = sm + 768;
    float* lnb      = sm + 896;
    float* b2_all   = sm + 1024;     // [8]

    const int tid = threadIdx.x;
    const int grp = tid >> 7;        // group 0/1 -> heads 4grp..4grp+3
    const int gw  = (tid >> 5) & 3;  // warp within group
    const int l   = tid & 31;
    const int c   = tid & 127;       // row owned within group
    const int g   = l >> 2, tq = l & 3;
    const int rot4 = 4 * ((tq + (g >> 1)) & 3);

    float* gb       = sm + 1040 + grp * 7040;
    float* waa      = gb;            // [16][20] L2E-scaled, padded
    float* scrow    = gb + 320;      // [128]
    float* mixedrow = gb + 448;      // [128]
    float* edge     = gb + 576;      // [128]
    float* Msm      = gb + 704;      // [4]
    float* ms1r_f   = gb + 712;      // [128][16] tf32 ms1, paired-e chunks
    float* ms1T_f   = gb + 2760;     // [16][136] tf32 ms1^T, natural order
    float* aeT      = gb + 4936;     // [16][130]

    const int br = blockIdx.x;
    const int b = br >> 7, r = br & 127;

    if (tid < 128) {
        int h0 = tid >> 4, e0 = tid & 15;
        w1a_all[tid] = mix1_w[h0 * 32 + e0];
        w1b_all[tid] = mix1_w[h0 * 32 + 16 + e0];
        b1s_all[tid] = mix1_b[tid];
        w2s_all[tid] = mix2_w[tid];
        ews_all[tid] = edge_w[tid];
        costrow[tid] = cost_mat[br * 128 + tid];
        lng[tid] = ln_g[tid];
        lnb[tid] = ln_b[tid];
    }
    if (tid < 8) b2_all[tid] = mix2_b[tid];
    edge[c] = 0.f;
    __syncthreads();

    for (int hh = 0; hh < 4; ++hh) {
        const int h = grp * 4 + hh;

        // ---- P1: waa reload; ms1 row c -> tiles; scrow; mixed; tile max ----
        waa[(c >> 4) * 20 + (c & 15)]         = Waa[h * 256 + c] * L2E;
        waa[((c + 128) >> 4) * 20 + (c & 15)] = Waa[h * 256 + c + 128] * L2E;

        float sc = g_score[((b * KH + h) * KR + r) * KC + c];
        float co = costrow[c];
        scrow[c] = sc;
        float m[16];
        {
            const float4* wa4 = (const float4*)&w1a_all[h * 16];
            const float4* wb4 = (const float4*)&w1b_all[h * 16];
            const float4* bi4 = (const float4*)&b1s_all[h * 16];
#pragma unroll
            for (int j = 0; j < 4; ++j) {
                float4 a = wa4[j], bq = wb4[j], bi = bi4[j];
                m[4*j+0] = fmaxf(fmaf(sc, a.x, fmaf(co, bq.x, bi.x)), 0.f);
                m[4*j+1] = fmaxf(fmaf(sc, a.y, fmaf(co, bq.y, bi.y)), 0.f);
                m[4*j+2] = fmaxf(fmaf(sc, a.z, fmaf(co, bq.z, bi.z)), 0.f);
                m[4*j+3] = fmaxf(fmaf(sc, a.w, fmaf(co, bq.w, bi.w)), 0.f);
            }
        }
        {
            float rm = m[0];
#pragma unroll
            for (int e = 1; e < 16; ++e) rm = fmaxf(rm, m[e]);
#pragma unroll
            for (int o = 16; o; o >>= 1) rm = fmaxf(rm, __shfl_xor_sync(FULLMASK, rm, o));
            if (l == 0) Msm[gw] = rm;
        }
        // ms1r_f: paired-e rotated chunks (dd-B / t-A source)
#pragma unroll
        for (int t = 0; t < 4; ++t) {
            float4 ch;
            ch.x = __uint_as_float(tf32r(m[2*t]));
            ch.y = __uint_as_float(tf32r(m[2*t + 1]));
            ch.z = __uint_as_float(tf32r(m[2*t + 8]));
            ch.w = __uint_as_float(tf32r(m[2*t + 9]));
            *(float4*)&ms1r_f[c * 16 + 4 * ((t + (c >> 1)) & 3)] = ch;
        }
        // ms1T_f: transposed, natural column order (ae-B source)
#pragma unroll
        for (int e = 0; e < 16; ++e)
            ms1T_f[e * 136 + c] = __uint_as_float(tf32r(m[e]));
        // mixed score
        {
            float mx = b2_all[h];
            const float4* w24 = (const float4*)&w2s_all[h * 16];
#pragma unroll
            for (int j = 0; j < 4; ++j) {
                float4 ww = w24[j];
                mx = fmaf(m[4*j],   ww.x, mx); mx = fmaf(m[4*j+1], ww.y, mx);
                mx = fmaf(m[4*j+2], ww.z, mx); mx = fmaf(m[4*j+3], ww.w, mx);
            }
            mixedrow[c] = mx;
        }
        gbar(grp);   // B1

        const float Mmax = fmaxf(fmaxf(Msm[0], Msm[1]), fmaxf(Msm[2], Msm[3]));

        // ---- P2a: t-GEMM for both row-blocks (t stays in registers) ----
        uint32_t wf[8];
        wf[0] = tf32r(waa[(2*tq)   * 20 + g]);
        wf[1] = tf32r(waa[(2*tq+1) * 20 + g]);
        wf[2] = tf32r(waa[(8+2*tq) * 20 + g]);
        wf[3] = tf32r(waa[(9+2*tq) * 20 + g]);
        wf[4] = tf32r(waa[(2*tq)   * 20 + g + 8]);
        wf[5] = tf32r(waa[(2*tq+1) * 20 + g + 8]);
        wf[6] = tf32r(waa[(8+2*tq) * 20 + g + 8]);
        wf[7] = tf32r(waa[(9+2*tq) * 20 + g + 8]);

        float mub[2][2];
        uint32_t daf[2][4], dbf[2][4];
#pragma unroll
        for (int rb = 0; rb < 2; ++rb) {
            const int R = gw * 32 + rb * 16;
            float4 tA = *(const float4*)&ms1r_f[(R + g)     * 16 + rot4];
            float4 tB = *(const float4*)&ms1r_f[(R + g + 8) * 16 + rot4];
            float tc0 = 0.f, tc1 = 0.f, tc2 = 0.f, tc3 = 0.f;
            float tc4 = 0.f, tc5 = 0.f, tc6 = 0.f, tc7 = 0.f;
            uint32_t ax = __float_as_uint(tA.x), bx = __float_as_uint(tB.x);
            uint32_t ay = __float_as_uint(tA.y), by = __float_as_uint(tB.y);
            uint32_t az = __float_as_uint(tA.z), bz = __float_as_uint(tB.z);
            uint32_t aw = __float_as_uint(tA.w), bw = __float_as_uint(tB.w);
            mma8(tc0, tc1, tc2, tc3, ax, bx, ay, by, wf[0], wf[1]);
            mma8(tc0, tc1, tc2, tc3, az, bz, aw, bw, wf[2], wf[3]);
            mma8(tc4, tc5, tc6, tc7, ax, bx, ay, by, wf[4], wf[5]);
            mma8(tc4, tc5, tc6, tc7, az, bz, aw, bw, wf[6], wf[7]);
            float s_g  = fmaxf(tc0, 0.f) + fmaxf(tc1, 0.f)
                       + fmaxf(tc4, 0.f) + fmaxf(tc5, 0.f);
            float s_g8 = fmaxf(tc2, 0.f) + fmaxf(tc3, 0.f)
                       + fmaxf(tc6, 0.f) + fmaxf(tc7, 0.f);
            s_g  += __shfl_xor_sync(FULLMASK, s_g, 1);
            s_g  += __shfl_xor_sync(FULLMASK, s_g, 2);
            s_g8 += __shfl_xor_sync(FULLMASK, s_g8, 1);
            s_g8 += __shfl_xor_sync(FULLMASK, s_g8, 2);
            mub[rb][0] = Mmax * s_g;
            mub[rb][1] = Mmax * s_g8;
            daf[rb][0] = __float_as_uint(tc0); daf[rb][1] = __float_as_uint(tc2);
            daf[rb][2] = __float_as_uint(tc1); daf[rb][3] = __float_as_uint(tc3);
            dbf[rb][0] = __float_as_uint(tc4); dbf[rb][1] = __float_as_uint(tc6);
            dbf[rb][2] = __float_as_uint(tc5); dbf[rb][3] = __float_as_uint(tc7);
        }

        // ---- P2b: per j, one B-load feeds BOTH row-blocks ----
        float sg[2][2] = {{0.f, 0.f}, {0.f, 0.f}};
        float ae0[8], ae1[8];
#pragma unroll
        for (int i = 0; i < 8; ++i) { ae0[i] = 0.f; ae1[i] = 0.f; }

#pragma unroll
        for (int j = 0; j < 16; ++j) {
            float4 bv = *(const float4*)&ms1r_f[(8*j + g) * 16 + rot4];
            float2 e0v = *(const float2*)&ms1T_f[g       * 136 + j*8 + 2*tq];
            float2 e1v = *(const float2*)&ms1T_f[(8 + g) * 136 + j*8 + 2*tq];
            uint32_t bx = __float_as_uint(bv.x), by = __float_as_uint(bv.y);
            uint32_t bz = __float_as_uint(bv.z), bw = __float_as_uint(bv.w);
            uint32_t u0 = __float_as_uint(e0v.x), u1 = __float_as_uint(e0v.y);
            uint32_t u2 = __float_as_uint(e1v.x), u3 = __float_as_uint(e1v.y);
#pragma unroll
            for (int rb = 0; rb < 2; ++rb) {
                float c0 = -mub[rb][0], c1 = -mub[rb][0];
                float c2 = -mub[rb][1], c3 = -mub[rb][1];
                mma8(c0, c1, c2, c3, daf[rb][0], daf[rb][1], daf[rb][2],
                     daf[rb][3], bx, by);
                mma8(c0, c1, c2, c3, dbf[rb][0], dbf[rb][1], dbf[rb][2],
                     dbf[rb][3], bz, bw);
                float p0 = ex2(c0), p1 = ex2(c1), p2 = ex2(c2), p3 = ex2(c3);
                sg[rb][0] += p0 + p1; sg[rb][1] += p2 + p3;
                uint32_t a0 = __float_as_uint(p0);
                uint32_t a1 = __float_as_uint(p2);
                uint32_t a2 = __float_as_uint(p1);
                uint32_t a3 = __float_as_uint(p3);
                float* ae = rb ? ae1 : ae0;
                mma8(ae[0], ae[1], ae[2], ae[3], a0, a1, a2, a3, u0, u1);
                mma8(ae[4], ae[5], ae[6], ae[7], a0, a1, a2, a3, u2, u3);
            }
        }
#pragma unroll
        for (int rb = 0; rb < 2; ++rb) {
            float s0 = sg[rb][0], s1 = sg[rb][1];
            s0 += __shfl_xor_sync(FULLMASK, s0, 1);
            s0 += __shfl_xor_sync(FULLMASK, s0, 2);
            s1 += __shfl_xor_sync(FULLMASK, s1, 1);
            s1 += __shfl_xor_sync(FULLMASK, s1, 2);
            const float inv0 = 1.f / s0, inv1 = 1.f / s1;
            const int R = gw * 32 + rb * 16;
            const float* ae = rb ? ae1 : ae0;
#pragma unroll
            for (int nt = 0; nt < 2; ++nt) {
                aeT[(8*nt + 2*tq)    *130 + R + g]     = ae[nt*4]   * inv0;
                aeT[(8*nt + 2*tq + 1)*130 + R + g]     = ae[nt*4+1] * inv0;
                aeT[(8*nt + 2*tq)    *130 + R + g + 8] = ae[nt*4+2] * inv1;
                aeT[(8*nt + 2*tq + 1)*130 + R + g + 8] = ae[nt*4+3] * inv1;
            }
        }
        gbar(grp);   // B2

        // ---- P3: LayerNorm (residual recomputed exactly from scrow) ----
#pragma unroll
        for (int ei = 0; ei < 4; ++ei) {
            int e = gw * 4 + ei;
            float wa = w1a_all[h * 16 + e];
            float wb = w1b_all[h * 16 + e];
            float bi = b1s_all[h * 16 + e];
            float x[4];
#pragma unroll
            for (int ki = 0; ki < 4; ++ki) {
                int cc = l + 32 * ki;
                float ms = fmaxf(fmaf(scrow[cc], wa, fmaf(costrow[cc], wb, bi)), 0.f);
                x[ki] = aeT[e * 130 + cc] + ms;
            }
            float s1v = x[0] + x[1] + x[2] + x[3];
            float sq = x[0]*x[0] + x[1]*x[1] + x[2]*x[2] + x[3]*x[3];
#pragma unroll
            for (int o = 16; o; o >>= 1) {
                s1v += __shfl_xor_sync(FULLMASK, s1v, o);
                sq  += __shfl_xor_sync(FULLMASK, sq, o);
            }
            float mean = s1v * (1.f / 128.f);
            float var  = sq * (1.f / 128.f) - mean * mean;
            float rs = rsqrtf(var + 1e-5f);
#pragma unroll
            for (int ki = 0; ki < 4; ++ki) {
                int cc = l + 32 * ki;
                aeT[e * 130 + cc] = (x[ki] - mean) * rs * lng[cc] + lnb[cc];
            }
        }

        // ---- mixed softmax attention (same warps, before B3) ----
        {
            float m0 = mixedrow[l],      m1 = mixedrow[l + 32];
            float m2 = mixedrow[l + 64], m3 = mixedrow[l + 96];
            float mx = fmaxf(fmaxf(m0, m1), fmaxf(m2, m3));
#pragma unroll
            for (int o = 16; o; o >>= 1) mx = fmaxf(mx, __shfl_xor_sync(FULLMASK, mx, o));
            float p0 = __expf(m0 - mx), p1 = __expf(m1 - mx);
            float p2 = __expf(m2 - mx), p3 = __expf(m3 - mx);
            float ssum = p0 + p1 + p2 + p3;
#pragma unroll
            for (int o = 16; o; o >>= 1) ssum += __shfl_xor_sync(FULLMASK, ssum, o);
            float inv = 1.f / ssum;
            const float* vb = v + (b * KH + h) * KC * KDQ;
#pragma unroll
            for (int d0 = 0; d0 < 4; ++d0) {
                int dq = gw * 4 + d0;
                float a = p0 * vb[l * 16 + dq] + p1 * vb[(l + 32) * 16 + dq]
                        + p2 * vb[(l + 64) * 16 + dq] + p3 * vb[(l + 96) * 16 + dq];
#pragma unroll
                for (int o = 16; o; o >>= 1) a += __shfl_xor_sync(FULLMASK, a, o);
                if (l == 0)
                    out[(b * KR + r) * (KH * KDQ) + h * KDQ + dq] = a * inv;
            }
        }
        gbar(grp);   // B3

        // ---- edge accumulation (reads aeT only; precedes next P1 per-thread)
        {
            const float4* ew4 = (const float4*)&ews_all[h * 16];
            float acc = edge[c];
#pragma unroll
            for (int j = 0; j < 4; ++j) {
                float4 ew = ew4[j];
                acc = fmaf(aeT[(4*j)     * 130 + c], ew.x, acc);
                acc = fmaf(aeT[(4*j + 1) * 130 + c], ew.y, acc);
                acc = fmaf(aeT[(4*j + 2) * 130 + c], ew.z, acc);
                acc = fmaf(aeT[(4*j + 3) * 130 + c], ew.w, acc);
            }
            edge[c] = acc;
        }
    }

    __syncthreads();
    if (tid < 128) {
        const float* e0 = sm + 1040 + 576;
        const float* e1 = sm + 1040 + 7040 + 576;
        out[KB * KR * KH * KDQ + br * 128 + tid] = e0[tid] + e1[tid] + edge_b[0];
    }
}

extern "C" void kernel_launch(void* const* d_in, const int* in_sizes, int n_in,
                              void* d_out, int out_size) {
    const float* q    = (const float*)d_in[0];
    const float* k_s  = (const float*)d_in[1];
    const float* k_a  = (const float*)d_in[2];
    const float* v    = (const float*)d_in[3];
    const float* cost = (const float*)d_in[4];
    const float* m1w  = (const float*)d_in[5];
    const float* m1b  = (const float*)d_in[6];
    const float* waa  = (const float*)d_in[7];
    const float* m2w  = (const float*)d_in[8];
    const float* m2b  = (const float*)d_in[9];
    const float* ew   = (const float*)d_in[10];
    const float* eb   = (const float*)d_in[11];
    const float* lng  = (const float*)d_in[12];
    const float* lnb  = (const float*)d_in[13];
    float* out = (float*)d_out;

    cudaFuncSetAttribute(k1_score, cudaFuncAttributeMaxDynamicSharedMemorySize, 98816);
    cudaFuncSetAttribute(k2_main,  cudaFuncAttributeMaxDynamicSharedMemorySize, 60480);

    k1_score<<<KB * KH * 4, 256, 98816>>>(q, k_s, k_a);
    k2_main<<<KB * KR, 256, 60480>>>(cost, m1w, m1b, waa, m2w, m2b, ew, eb,
                                     lng, lnb, v, out);
}

// round 15
// speedup vs baseline: 4.5011x; 1.0510x over previous
#include <cuda_runtime.h>
#include <cstdint>

#define FULLMASK 0xffffffffu
#define KB 8
#define KH 8
#define KR 128
#define KC 128
#define KDQ 16
#define L2E 1.4426950408889634f

__device__ float g_score[KB * KH * KR * KC];

__device__ __forceinline__ float ex2(float x) {
    float r;
    asm("ex2.approx.f32 %0, %1;" : "=f"(r) : "f"(x));
    return r;
}
__device__ __forceinline__ uint32_t tf32r(float f) {
    uint32_t u;
    asm("cvt.rna.tf32.f32 %0, %1;" : "=r"(u) : "f"(f));
    return u;
}
__device__ __forceinline__ void mma8(float& c0, float& c1, float& c2, float& c3,
                                     uint32_t a0, uint32_t a1, uint32_t a2,
                                     uint32_t a3, uint32_t b0, uint32_t b1) {
    asm volatile(
        "mma.sync.aligned.m16n8k8.row.col.f32.tf32.tf32.f32 "
        "{%0,%1,%2,%3}, {%4,%5,%6,%7}, {%8,%9}, {%0,%1,%2,%3};"
        : "+f"(c0), "+f"(c1), "+f"(c2), "+f"(c3)
        : "r"(a0), "r"(a1), "r"(a2), "r"(a3), "r"(b0), "r"(b1));
}
__device__ __forceinline__ void gbar(int grp) {
    asm volatile("bar.sync %0, 128;" :: "r"(grp + 1) : "memory");
}

// ---------------------------------------------------------------------------
// Kernel 1 (unchanged, proven): grid 256, 256 thr, smem 98816
// ---------------------------------------------------------------------------
__global__ __launch_bounds__(256) void k1_score(const float* __restrict__ q,
                                                const float* __restrict__ ks,
                                                const float* __restrict__ ka) {
    extern __shared__ float sm[];
    float* ksT  = sm;
    float* kaT  = sm + 2112;
    float* qrow = sm + 4224;
    float* pbuf = sm + 6272;
    float* dpa  = sm + 7296;

    const int bh      = blockIdx.x >> 2;
    const int quarter = blockIdx.x & 3;
    const int tid = threadIdx.x;
    const float* qb  = q  + bh * 2048;
    const float* ksb = ks + bh * 2048;
    const float* kab = ka + bh * 2048;

    for (int i = tid; i < 2048; i += 256) {
        int srow = i >> 4, e = i & 15;
        ksT[e * 132 + srow] = ksb[i];
        kaT[e * 132 + srow] = kab[i];
        qrow[i] = qb[i];
    }
    __syncthreads();

    const int w = tid >> 5, l = tid & 31;

    for (int k = 0; k < 16; ++k) {
        int r = w * 16 + k;
        float qr[16];
#pragma unroll
        for (int j = 0; j < 4; ++j) {
            float4 v4 = *(const float4*)&qrow[r * 16 + 4 * j];
            qr[4*j] = v4.x; qr[4*j+1] = v4.y; qr[4*j+2] = v4.z; qr[4*j+3] = v4.w;
        }
        float a0 = 0.f, a1 = 0.f, a2 = 0.f, a3 = 0.f;
#pragma unroll
        for (int e = 0; e < 16; ++e) {
            float4 kk = *(const float4*)&kaT[e * 132 + 4 * l];
            a0 = fmaf(qr[e], kk.x, a0); a1 = fmaf(qr[e], kk.y, a1);
            a2 = fmaf(qr[e], kk.z, a2); a3 = fmaf(qr[e], kk.w, a3);
        }
        float4 o;
        o.x = fmaxf(a0 * 0.25f, 0.f); o.y = fmaxf(a1 * 0.25f, 0.f);
        o.z = fmaxf(a2 * 0.25f, 0.f); o.w = fmaxf(a3 * 0.25f, 0.f);
        *(float4*)&dpa[r * 136 + 4 * l] = o;
    }
    __syncthreads();

    for (int k = 0; k < 4; ++k) {
        int r = quarter * 32 + w * 4 + k;
        float qr[16];
#pragma unroll
        for (int j = 0; j < 4; ++j) {
            float4 v4 = *(const float4*)&qrow[r * 16 + 4 * j];
            qr[4*j] = v4.x; qr[4*j+1] = v4.y; qr[4*j+2] = v4.z; qr[4*j+3] = v4.w;
        }
        float a0 = 0.f, a1 = 0.f, a2 = 0.f, a3 = 0.f;
#pragma unroll
        for (int e = 0; e < 16; ++e) {
            float4 kk = *(const float4*)&ksT[e * 132 + 4 * l];
            a0 = fmaf(qr[e], kk.x, a0); a1 = fmaf(qr[e], kk.y, a1);
            a2 = fmaf(qr[e], kk.z, a2); a3 = fmaf(qr[e], kk.w, a3);
        }
        float x0 = a0 * 0.25f, x1 = a1 * 0.25f, x2 = a2 * 0.25f, x3 = a3 * 0.25f;
        a0 = x0 * normcdff(x0); a1 = x1 * normcdff(x1);
        a2 = x2 * normcdff(x2); a3 = x3 * normcdff(x3);
        float mx = fmaxf(fmaxf(a0, a1), fmaxf(a2, a3));
#pragma unroll
        for (int o = 16; o; o >>= 1) mx = fmaxf(mx, __shfl_xor_sync(FULLMASK, mx, o));
        float p0 = __expf(a0 - mx), p1 = __expf(a1 - mx);
        float p2 = __expf(a2 - mx), p3 = __expf(a3 - mx);
        float ssum = p0 + p1 + p2 + p3;
#pragma unroll
        for (int o = 16; o; o >>= 1) ssum += __shfl_xor_sync(FULLMASK, ssum, o);
        float inv = 1.f / ssum;
        *(float4*)&pbuf[w * 128 + 4 * l] = make_float4(p0*inv, p1*inv, p2*inv, p3*inv);
        __syncwarp();
        float c0 = 0.f, c1 = 0.f, c2 = 0.f, c3 = 0.f;
#pragma unroll 4
        for (int s2 = 0; s2 < 128; ++s2) {
            float pvv = pbuf[w * 128 + s2];
            float4 dv = *(const float4*)&dpa[s2 * 136 + 4 * l];
            c0 = fmaf(pvv, dv.x, c0); c1 = fmaf(pvv, dv.y, c1);
            c2 = fmaf(pvv, dv.z, c2); c3 = fmaf(pvv, dv.w, c3);
        }
        *(float4*)&g_score[(bh * 128 + r) * 128 + 4 * l] =
            make_float4(c0*0.25f, c1*0.25f, c2*0.25f, c3*0.25f);
        __syncwarp();
    }
}

// ---------------------------------------------------------------------------
// Kernel 2: edge fused into LN (no post-LN aeT traffic, no edge phase);
// 2 barriers/head via double-buffered scrow/mixedrow.
// grid 1024, 256 thr; dynamic smem 65536 B -> 3 CTAs/SM.
// ---------------------------------------------------------------------------
__global__ __launch_bounds__(256, 3) void k2_main(
    const float* __restrict__ cost_mat,
    const float* __restrict__ mix1_w, const float* __restrict__ mix1_b,
    const float* __restrict__ Waa,
    const float* __restrict__ mix2_w, const float* __restrict__ mix2_b,
    const float* __restrict__ edge_w, const float* __restrict__ edge_b,
    const float* __restrict__ ln_g,  const float* __restrict__ ln_b,
    const float* __restrict__ v, float* __restrict__ out) {
    extern __shared__ float sm[];
    float* w1a_all  = sm;            // [8][16]
    float* w1b_all  = sm + 128;
    float* b1s_all  = sm + 256;
    float* w2s_all  = sm + 384;
    float* ews_all  = sm + 512;
    float* costrow  = sm + 640;
    float* lng      = sm + 768;
    float* lnb      = sm + 896;
    float* b2_all   = sm + 1024;     // [8], pad to 16

    const int tid = threadIdx.x;
    const int grp = tid >> 7;        // group 0/1 -> heads 4grp..4grp+3
    const int gw  = (tid >> 5) & 3;  // warp within group
    const int l   = tid & 31;
    const int c   = tid & 127;       // row owned within group
    const int g   = l >> 2, tq = l & 3;
    const int rot4 = 4 * ((tq + (g >> 1)) & 3);

    float* gb       = sm + 1040 + grp * 7672;
    float* waa      = gb;            // [16][20] L2E-scaled, padded
    float* scrow2   = gb + 320;      // [2][128] double-buffered
    float* mixed2   = gb + 576;      // [2][128] double-buffered
    float* Msm      = gb + 832;      // [4], pad 8
    float* edgepart = gb + 840;      // [4][132] per-warp edge partials
    float* ms1r_f   = gb + 1368;     // [128][16] tf32 ms1, paired-e chunks
    float* ms1T_f   = gb + 3416;     // [16][136] tf32 ms1^T, natural order
    float* aeT      = gb + 5592;     // [16][130] pre-LN transpose buffer

    const int br = blockIdx.x;
    const int b = br >> 7, r = br & 127;

    if (tid < 128) {
        int h0 = tid >> 4, e0 = tid & 15;
        w1a_all[tid] = mix1_w[h0 * 32 + e0];
        w1b_all[tid] = mix1_w[h0 * 32 + 16 + e0];
        b1s_all[tid] = mix1_b[tid];
        w2s_all[tid] = mix2_w[tid];
        ews_all[tid] = edge_w[tid];
        costrow[tid] = cost_mat[br * 128 + tid];
        lng[tid] = ln_g[tid];
        lnb[tid] = ln_b[tid];
    }
    if (tid < 8) b2_all[tid] = mix2_b[tid];
    for (int i = c; i < 528; i += 128) edgepart[i] = 0.f;
    __syncthreads();

    for (int hh = 0; hh < 4; ++hh) {
        const int h = grp * 4 + hh;
        float* scrow    = scrow2 + (hh & 1) * 128;
        float* mixedrow = mixed2 + (hh & 1) * 128;

        // ---- P1: waa reload; ms1 row c -> tiles; scrow; mixed; tile max ----
        waa[(c >> 4) * 20 + (c & 15)]         = Waa[h * 256 + c] * L2E;
        waa[((c + 128) >> 4) * 20 + (c & 15)] = Waa[h * 256 + c + 128] * L2E;

        float sc = g_score[((b * KH + h) * KR + r) * KC + c];
        float co = costrow[c];
        scrow[c] = sc;
        float m[16];
        {
            const float4* wa4 = (const float4*)&w1a_all[h * 16];
            const float4* wb4 = (const float4*)&w1b_all[h * 16];
            const float4* bi4 = (const float4*)&b1s_all[h * 16];
#pragma unroll
            for (int j = 0; j < 4; ++j) {
                float4 a = wa4[j], bq = wb4[j], bi = bi4[j];
                m[4*j+0] = fmaxf(fmaf(sc, a.x, fmaf(co, bq.x, bi.x)), 0.f);
                m[4*j+1] = fmaxf(fmaf(sc, a.y, fmaf(co, bq.y, bi.y)), 0.f);
                m[4*j+2] = fmaxf(fmaf(sc, a.z, fmaf(co, bq.z, bi.z)), 0.f);
                m[4*j+3] = fmaxf(fmaf(sc, a.w, fmaf(co, bq.w, bi.w)), 0.f);
            }
        }
        {
            float rm = m[0];
#pragma unroll
            for (int e = 1; e < 16; ++e) rm = fmaxf(rm, m[e]);
#pragma unroll
            for (int o = 16; o; o >>= 1) rm = fmaxf(rm, __shfl_xor_sync(FULLMASK, rm, o));
            if (l == 0) Msm[gw] = rm;
        }
#pragma unroll
        for (int t = 0; t < 4; ++t) {
            float4 ch;
            ch.x = __uint_as_float(tf32r(m[2*t]));
            ch.y = __uint_as_float(tf32r(m[2*t + 1]));
            ch.z = __uint_as_float(tf32r(m[2*t + 8]));
            ch.w = __uint_as_float(tf32r(m[2*t + 9]));
            *(float4*)&ms1r_f[c * 16 + 4 * ((t + (c >> 1)) & 3)] = ch;
        }
#pragma unroll
        for (int e = 0; e < 16; ++e)
            ms1T_f[e * 136 + c] = __uint_as_float(tf32r(m[e]));
        {
            float mx = b2_all[h];
            const float4* w24 = (const float4*)&w2s_all[h * 16];
#pragma unroll
            for (int j = 0; j < 4; ++j) {
                float4 ww = w24[j];
                mx = fmaf(m[4*j],   ww.x, mx); mx = fmaf(m[4*j+1], ww.y, mx);
                mx = fmaf(m[4*j+2], ww.z, mx); mx = fmaf(m[4*j+3], ww.w, mx);
            }
            mixedrow[c] = mx;
        }
        gbar(grp);   // B1

        const float Mmax = fmaxf(fmaxf(Msm[0], Msm[1]), fmaxf(Msm[2], Msm[3]));

        // ---- P2a: t-GEMM for both row-blocks (t stays in registers) ----
        uint32_t wf[8];
        wf[0] = tf32r(waa[(2*tq)   * 20 + g]);
        wf[1] = tf32r(waa[(2*tq+1) * 20 + g]);
        wf[2] = tf32r(waa[(8+2*tq) * 20 + g]);
        wf[3] = tf32r(waa[(9+2*tq) * 20 + g]);
        wf[4] = tf32r(waa[(2*tq)   * 20 + g + 8]);
        wf[5] = tf32r(waa[(2*tq+1) * 20 + g + 8]);
        wf[6] = tf32r(waa[(8+2*tq) * 20 + g + 8]);
        wf[7] = tf32r(waa[(9+2*tq) * 20 + g + 8]);

        float mub[2][2];
        uint32_t daf[2][4], dbf[2][4];
#pragma unroll
        for (int rb = 0; rb < 2; ++rb) {
            const int R = gw * 32 + rb * 16;
            float4 tA = *(const float4*)&ms1r_f[(R + g)     * 16 + rot4];
            float4 tB = *(const float4*)&ms1r_f[(R + g + 8) * 16 + rot4];
            float tc0 = 0.f, tc1 = 0.f, tc2 = 0.f, tc3 = 0.f;
            float tc4 = 0.f, tc5 = 0.f, tc6 = 0.f, tc7 = 0.f;
            uint32_t ax = __float_as_uint(tA.x), bx = __float_as_uint(tB.x);
            uint32_t ay = __float_as_uint(tA.y), by = __float_as_uint(tB.y);
            uint32_t az = __float_as_uint(tA.z), bz = __float_as_uint(tB.z);
            uint32_t aw = __float_as_uint(tA.w), bw = __float_as_uint(tB.w);
            mma8(tc0, tc1, tc2, tc3, ax, bx, ay, by, wf[0], wf[1]);
            mma8(tc0, tc1, tc2, tc3, az, bz, aw, bw, wf[2], wf[3]);
            mma8(tc4, tc5, tc6, tc7, ax, bx, ay, by, wf[4], wf[5]);
            mma8(tc4, tc5, tc6, tc7, az, bz, aw, bw, wf[6], wf[7]);
            float s_g  = fmaxf(tc0, 0.f) + fmaxf(tc1, 0.f)
                       + fmaxf(tc4, 0.f) + fmaxf(tc5, 0.f);
            float s_g8 = fmaxf(tc2, 0.f) + fmaxf(tc3, 0.f)
                       + fmaxf(tc6, 0.f) + fmaxf(tc7, 0.f);
            s_g  += __shfl_xor_sync(FULLMASK, s_g, 1);
            s_g  += __shfl_xor_sync(FULLMASK, s_g, 2);
            s_g8 += __shfl_xor_sync(FULLMASK, s_g8, 1);
            s_g8 += __shfl_xor_sync(FULLMASK, s_g8, 2);
            mub[rb][0] = Mmax * s_g;
            mub[rb][1] = Mmax * s_g8;
            daf[rb][0] = __float_as_uint(tc0); daf[rb][1] = __float_as_uint(tc2);
            daf[rb][2] = __float_as_uint(tc1); daf[rb][3] = __float_as_uint(tc3);
            dbf[rb][0] = __float_as_uint(tc4); dbf[rb][1] = __float_as_uint(tc6);
            dbf[rb][2] = __float_as_uint(tc5); dbf[rb][3] = __float_as_uint(tc7);
        }

        // ---- P2b: per j, one B-load feeds BOTH row-blocks ----
        float sg[2][2] = {{0.f, 0.f}, {0.f, 0.f}};
        float ae0[8], ae1[8];
#pragma unroll
        for (int i = 0; i < 8; ++i) { ae0[i] = 0.f; ae1[i] = 0.f; }

#pragma unroll
        for (int j = 0; j < 16; ++j) {
            float4 bv = *(const float4*)&ms1r_f[(8*j + g) * 16 + rot4];
            float2 e0v = *(const float2*)&ms1T_f[g       * 136 + j*8 + 2*tq];
            float2 e1v = *(const float2*)&ms1T_f[(8 + g) * 136 + j*8 + 2*tq];
            uint32_t bx = __float_as_uint(bv.x), by = __float_as_uint(bv.y);
            uint32_t bz = __float_as_uint(bv.z), bw = __float_as_uint(bv.w);
            uint32_t u0 = __float_as_uint(e0v.x), u1 = __float_as_uint(e0v.y);
            uint32_t u2 = __float_as_uint(e1v.x), u3 = __float_as_uint(e1v.y);
#pragma unroll
            for (int rb = 0; rb < 2; ++rb) {
                float c0 = -mub[rb][0], c1 = -mub[rb][0];
                float c2 = -mub[rb][1], c3 = -mub[rb][1];
                mma8(c0, c1, c2, c3, daf[rb][0], daf[rb][1], daf[rb][2],
                     daf[rb][3], bx, by);
                mma8(c0, c1, c2, c3, dbf[rb][0], dbf[rb][1], dbf[rb][2],
                     dbf[rb][3], bz, bw);
                float p0 = ex2(c0), p1 = ex2(c1), p2 = ex2(c2), p3 = ex2(c3);
                sg[rb][0] += p0 + p1; sg[rb][1] += p2 + p3;
                uint32_t a0 = __float_as_uint(p0);
                uint32_t a1 = __float_as_uint(p2);
                uint32_t a2 = __float_as_uint(p1);
                uint32_t a3 = __float_as_uint(p3);
                float* ae = rb ? ae1 : ae0;
                mma8(ae[0], ae[1], ae[2], ae[3], a0, a1, a2, a3, u0, u1);
                mma8(ae[4], ae[5], ae[6], ae[7], a0, a1, a2, a3, u2, u3);
            }
        }
#pragma unroll
        for (int rb = 0; rb < 2; ++rb) {
            float s0 = sg[rb][0], s1 = sg[rb][1];
            s0 += __shfl_xor_sync(FULLMASK, s0, 1);
            s0 += __shfl_xor_sync(FULLMASK, s0, 2);
            s1 += __shfl_xor_sync(FULLMASK, s1, 1);
            s1 += __shfl_xor_sync(FULLMASK, s1, 2);
            const float inv0 = 1.f / s0, inv1 = 1.f / s1;
            const int R = gw * 32 + rb * 16;
            const float* ae = rb ? ae1 : ae0;
#pragma unroll
            for (int nt = 0; nt < 2; ++nt) {
                aeT[(8*nt + 2*tq)    *130 + R + g]     = ae[nt*4]   * inv0;
                aeT[(8*nt + 2*tq + 1)*130 + R + g]     = ae[nt*4+1] * inv0;
                aeT[(8*nt + 2*tq)    *130 + R + g + 8] = ae[nt*4+2] * inv1;
                aeT[(8*nt + 2*tq + 1)*130 + R + g + 8] = ae[nt*4+3] * inv1;
            }
        }
        gbar(grp);   // B2

        // ---- P3: LayerNorm with edge fused (no post-LN stores) ----
        {
            float eacc[4] = {0.f, 0.f, 0.f, 0.f};
#pragma unroll
            for (int ei = 0; ei < 4; ++ei) {
                int e = gw * 4 + ei;
                float wa = w1a_all[h * 16 + e];
                float wb = w1b_all[h * 16 + e];
                float bi = b1s_all[h * 16 + e];
                float ewv = ews_all[h * 16 + e];
                float x[4];
#pragma unroll
                for (int ki = 0; ki < 4; ++ki) {
                    int cc = l + 32 * ki;
                    float ms = fmaxf(fmaf(scrow[cc], wa,
                                     fmaf(costrow[cc], wb, bi)), 0.f);
                    x[ki] = aeT[e * 130 + cc] + ms;
                }
                float s1v = x[0] + x[1] + x[2] + x[3];
                float sq = x[0]*x[0] + x[1]*x[1] + x[2]*x[2] + x[3]*x[3];
#pragma unroll
                for (int o = 16; o; o >>= 1) {
                    s1v += __shfl_xor_sync(FULLMASK, s1v, o);
                    sq  += __shfl_xor_sync(FULLMASK, sq, o);
                }
                float mean = s1v * (1.f / 128.f);
                float var  = sq * (1.f / 128.f) - mean * mean;
                float rs = rsqrtf(var + 1e-5f);
#pragma unroll
                for (int ki = 0; ki < 4; ++ki) {
                    int cc = l + 32 * ki;
                    float val = (x[ki] - mean) * rs * lng[cc] + lnb[cc];
                    eacc[ki] = fmaf(val, ewv, eacc[ki]);
                }
            }
#pragma unroll
            for (int ki = 0; ki < 4; ++ki)
                edgepart[gw * 132 + l + 32 * ki] += eacc[ki];
        }

        // ---- mixed softmax attention (no barrier needed before this) ----
        {
            float m0 = mixedrow[l],      m1 = mixedrow[l + 32];
            float m2 = mixedrow[l + 64], m3 = mixedrow[l + 96];
            float mx = fmaxf(fmaxf(m0, m1), fmaxf(m2, m3));
#pragma unroll
            for (int o = 16; o; o >>= 1) mx = fmaxf(mx, __shfl_xor_sync(FULLMASK, mx, o));
            float p0 = __expf(m0 - mx), p1 = __expf(m1 - mx);
            float p2 = __expf(m2 - mx), p3 = __expf(m3 - mx);
            float ssum = p0 + p1 + p2 + p3;
#pragma unroll
            for (int o = 16; o; o >>= 1) ssum += __shfl_xor_sync(FULLMASK, ssum, o);
            float inv = 1.f / ssum;
            const float* vb = v + (b * KH + h) * KC * KDQ;
#pragma unroll
            for (int d0 = 0; d0 < 4; ++d0) {
                int dq = gw * 4 + d0;
                float a = p0 * vb[l * 16 + dq] + p1 * vb[(l + 32) * 16 + dq]
                        + p2 * vb[(l + 64) * 16 + dq] + p3 * vb[(l + 96) * 16 + dq];
#pragma unroll
                for (int o = 16; o; o >>= 1) a += __shfl_xor_sync(FULLMASK, a, o);
                if (l == 0)
                    out[(b * KR + r) * (KH * KDQ) + h * KDQ + dq] = a * inv;
            }
        }
        // no end-of-head barrier: scrow/mixedrow double-buffered; aeT next
        // written after next B1; tiles next written in next P1 are only read
        // pre-B2 of this head (all warps past B2 already).
    }

    __syncthreads();
    if (tid < 128) {
        float acc = edge_b[0];
        const float* p0 = sm + 1040 + 840;
        const float* p1 = sm + 1040 + 7672 + 840;
#pragma unroll
        for (int gwi = 0; gwi < 4; ++gwi)
            acc += p0[gwi * 132 + tid] + p1[gwi * 132 + tid];
        out[KB * KR * KH * KDQ + br * 128 + tid] = acc;
    }
}

extern "C" void kernel_launch(void* const* d_in, const int* in_sizes, int n_in,
                              void* d_out, int out_size) {
    const float* q    = (const float*)d_in[0];
    const float* k_s  = (const float*)d_in[1];
    const float* k_a  = (const float*)d_in[2];
    const float* v    = (const float*)d_in[3];
    const float* cost = (const float*)d_in[4];
    const float* m1w  = (const float*)d_in[5];
    const float* m1b  = (const float*)d_in[6];
    const float* waa  = (const float*)d_in[7];
    const float* m2w  = (const float*)d_in[8];
    const float* m2b  = (const float*)d_in[9];
    const float* ew   = (const float*)d_in[10];
    const float* eb   = (const float*)d_in[11];
    const float* lng  = (const float*)d_in[12];
    const float* lnb  = (const float*)d_in[13];
    float* out = (float*)d_out;

    cudaFuncSetAttribute(k1_score, cudaFuncAttributeMaxDynamicSharedMemorySize, 98816);
    cudaFuncSetAttribute(k2_main,  cudaFuncAttributeMaxDynamicSharedMemorySize, 65536);

    k1_score<<<KB * KH * 4, 256, 98816>>>(q, k_s, k_a);
    k2_main<<<KB * KR, 256, 65536>>>(cost, m1w, m1b, waa, m2w, m2b, ew, eb,
                                     lng, lnb, v, out);
}

// round 16
// speedup vs baseline: 4.8795x; 1.0841x over previous
#include <cuda_runtime.h>
#include <cstdint>

#define FULLMASK 0xffffffffu
#define KB 8
#define KH 8
#define KR 128
#define KC 128
#define KDQ 16
#define L2E 1.4426950408889634f

__device__ float g_score[KB * KH * KR * KC];

__device__ __forceinline__ float ex2(float x) {
    float r;
    asm("ex2.approx.f32 %0, %1;" : "=f"(r) : "f"(x));
    return r;
}
__device__ __forceinline__ uint32_t tf32r(float f) {
    uint32_t u;
    asm("cvt.rna.tf32.f32 %0, %1;" : "=r"(u) : "f"(f));
    return u;
}
__device__ __forceinline__ void mma8(float& c0, float& c1, float& c2, float& c3,
                                     uint32_t a0, uint32_t a1, uint32_t a2,
                                     uint32_t a3, uint32_t b0, uint32_t b1) {
    asm volatile(
        "mma.sync.aligned.m16n8k8.row.col.f32.tf32.tf32.f32 "
        "{%0,%1,%2,%3}, {%4,%5,%6,%7}, {%8,%9}, {%0,%1,%2,%3};"
        : "+f"(c0), "+f"(c1), "+f"(c2), "+f"(c3)
        : "r"(a0), "r"(a1), "r"(a2), "r"(a3), "r"(b0), "r"(b1));
}
__device__ __forceinline__ void gbar(int grp) {
    asm volatile("bar.sync %0, 128;" :: "r"(grp + 1) : "memory");
}

// ---------------------------------------------------------------------------
// Kernel 1: restructured phase B — 4 softmax rows first, then ONE shared
// score loop with 16 accumulators (dpa loaded once, not 4x).
// grid 256, 256 thr, smem 111104 B (2 CTAs/SM).
// ---------------------------------------------------------------------------
__global__ __launch_bounds__(256) void k1_score(const float* __restrict__ q,
                                                const float* __restrict__ ks,
                                                const float* __restrict__ ka) {
    extern __shared__ float sm[];
    float* ksT   = sm;            // [16][132]
    float* kaT   = sm + 2112;     // [16][132]
    float* qrow  = sm + 4224;     // [128*16]
    float* pbuf4 = sm + 6272;     // [8][4][128]
    float* dpa   = sm + 10368;    // [128][136]

    const int bh      = blockIdx.x >> 2;
    const int quarter = blockIdx.x & 3;
    const int tid = threadIdx.x;
    const float* qb  = q  + bh * 2048;
    const float* ksb = ks + bh * 2048;
    const float* kab = ka + bh * 2048;

    for (int i = tid; i < 2048; i += 256) {
        int srow = i >> 4, e = i & 15;
        ksT[e * 132 + srow] = ksb[i];
        kaT[e * 132 + srow] = kab[i];
        qrow[i] = qb[i];
    }
    __syncthreads();

    const int w = tid >> 5, l = tid & 31;

    // Phase A: full dpa[r][c] = relu(dot(q[r], ka[c]) * 0.25)
    for (int k = 0; k < 16; ++k) {
        int r = w * 16 + k;
        float qr[16];
#pragma unroll
        for (int j = 0; j < 4; ++j) {
            float4 v4 = *(const float4*)&qrow[r * 16 + 4 * j];
            qr[4*j] = v4.x; qr[4*j+1] = v4.y; qr[4*j+2] = v4.z; qr[4*j+3] = v4.w;
        }
        float a0 = 0.f, a1 = 0.f, a2 = 0.f, a3 = 0.f;
#pragma unroll
        for (int e = 0; e < 16; ++e) {
            float4 kk = *(const float4*)&kaT[e * 132 + 4 * l];
            a0 = fmaf(qr[e], kk.x, a0); a1 = fmaf(qr[e], kk.y, a1);
            a2 = fmaf(qr[e], kk.z, a2); a3 = fmaf(qr[e], kk.w, a3);
        }
        float4 o;
        o.x = fmaxf(a0 * 0.25f, 0.f); o.y = fmaxf(a1 * 0.25f, 0.f);
        o.z = fmaxf(a2 * 0.25f, 0.f); o.w = fmaxf(a3 * 0.25f, 0.f);
        *(float4*)&dpa[r * 136 + 4 * l] = o;
    }
    __syncthreads();

    // Phase B1: 4 dps rows -> gelu -> softmax -> pbuf4
    for (int k = 0; k < 4; ++k) {
        int r = quarter * 32 + w * 4 + k;
        float qr[16];
#pragma unroll
        for (int j = 0; j < 4; ++j) {
            float4 v4 = *(const float4*)&qrow[r * 16 + 4 * j];
            qr[4*j] = v4.x; qr[4*j+1] = v4.y; qr[4*j+2] = v4.z; qr[4*j+3] = v4.w;
        }
        float a0 = 0.f, a1 = 0.f, a2 = 0.f, a3 = 0.f;
#pragma unroll
        for (int e = 0; e < 16; ++e) {
            float4 kk = *(const float4*)&ksT[e * 132 + 4 * l];
            a0 = fmaf(qr[e], kk.x, a0); a1 = fmaf(qr[e], kk.y, a1);
            a2 = fmaf(qr[e], kk.z, a2); a3 = fmaf(qr[e], kk.w, a3);
        }
        float x0 = a0 * 0.25f, x1 = a1 * 0.25f, x2 = a2 * 0.25f, x3 = a3 * 0.25f;
        a0 = x0 * normcdff(x0); a1 = x1 * normcdff(x1);
        a2 = x2 * normcdff(x2); a3 = x3 * normcdff(x3);
        float mx = fmaxf(fmaxf(a0, a1), fmaxf(a2, a3));
#pragma unroll
        for (int o = 16; o; o >>= 1) mx = fmaxf(mx, __shfl_xor_sync(FULLMASK, mx, o));
        float p0 = __expf(a0 - mx), p1 = __expf(a1 - mx);
        float p2 = __expf(a2 - mx), p3 = __expf(a3 - mx);
        float ssum = p0 + p1 + p2 + p3;
#pragma unroll
        for (int o = 16; o; o >>= 1) ssum += __shfl_xor_sync(FULLMASK, ssum, o);
        float inv = 1.f / ssum;
        *(float4*)&pbuf4[w * 512 + k * 128 + 4 * l] =
            make_float4(p0*inv, p1*inv, p2*inv, p3*inv);
    }
    __syncwarp();

    // Phase B2: single score loop, 16 accumulators, dpa loaded once
    float acc[16];
#pragma unroll
    for (int i = 0; i < 16; ++i) acc[i] = 0.f;
    const float* pb = &pbuf4[w * 512];
#pragma unroll 2
    for (int s = 0; s < 128; ++s) {
        float4 dv = *(const float4*)&dpa[s * 136 + 4 * l];
        float pk0 = pb[s], pk1 = pb[128 + s];
        float pk2 = pb[256 + s], pk3 = pb[384 + s];
        acc[0]  = fmaf(pk0, dv.x, acc[0]);  acc[1]  = fmaf(pk0, dv.y, acc[1]);
        acc[2]  = fmaf(pk0, dv.z, acc[2]);  acc[3]  = fmaf(pk0, dv.w, acc[3]);
        acc[4]  = fmaf(pk1, dv.x, acc[4]);  acc[5]  = fmaf(pk1, dv.y, acc[5]);
        acc[6]  = fmaf(pk1, dv.z, acc[6]);  acc[7]  = fmaf(pk1, dv.w, acc[7]);
        acc[8]  = fmaf(pk2, dv.x, acc[8]);  acc[9]  = fmaf(pk2, dv.y, acc[9]);
        acc[10] = fmaf(pk2, dv.z, acc[10]); acc[11] = fmaf(pk2, dv.w, acc[11]);
        acc[12] = fmaf(pk3, dv.x, acc[12]); acc[13] = fmaf(pk3, dv.y, acc[13]);
        acc[14] = fmaf(pk3, dv.z, acc[14]); acc[15] = fmaf(pk3, dv.w, acc[15]);
    }
#pragma unroll
    for (int k = 0; k < 4; ++k) {
        int r = quarter * 32 + w * 4 + k;
        *(float4*)&g_score[(bh * 128 + r) * 128 + 4 * l] =
            make_float4(acc[4*k] * 0.25f, acc[4*k+1] * 0.25f,
                        acc[4*k+2] * 0.25f, acc[4*k+3] * 0.25f);
    }
}

// ---------------------------------------------------------------------------
// Kernel 2: same as round 15 (best), with waa pre-rounded to tf32 at store.
// grid 1024, 256 thr; dynamic smem 65536 B -> 3 CTAs/SM.
// ---------------------------------------------------------------------------
__global__ __launch_bounds__(256, 3) void k2_main(
    const float* __restrict__ cost_mat,
    const float* __restrict__ mix1_w, const float* __restrict__ mix1_b,
    const float* __restrict__ Waa,
    const float* __restrict__ mix2_w, const float* __restrict__ mix2_b,
    const float* __restrict__ edge_w, const float* __restrict__ edge_b,
    const float* __restrict__ ln_g,  const float* __restrict__ ln_b,
    const float* __restrict__ v, float* __restrict__ out) {
    extern __shared__ float sm[];
    float* w1a_all  = sm;            // [8][16]
    float* w1b_all  = sm + 128;
    float* b1s_all  = sm + 256;
    float* w2s_all  = sm + 384;
    float* ews_all  = sm + 512;
    float* costrow  = sm + 640;
    float* lng      = sm + 768;
    float* lnb      = sm + 896;
    float* b2_all   = sm + 1024;     // [8], pad to 16

    const int tid = threadIdx.x;
    const int grp = tid >> 7;        // group 0/1 -> heads 4grp..4grp+3
    const int gw  = (tid >> 5) & 3;  // warp within group
    const int l   = tid & 31;
    const int c   = tid & 127;       // row owned within group
    const int g   = l >> 2, tq = l & 3;
    const int rot4 = 4 * ((tq + (g >> 1)) & 3);

    float* gb       = sm + 1040 + grp * 7672;
    float* waa      = gb;            // [16][20] tf32(Waa*L2E), padded
    float* scrow2   = gb + 320;      // [2][128] double-buffered
    float* mixed2   = gb + 576;      // [2][128] double-buffered
    float* Msm      = gb + 832;      // [4], pad 8
    float* edgepart = gb + 840;      // [4][132] per-warp edge partials
    float* ms1r_f   = gb + 1368;     // [128][16] tf32 ms1, paired-e chunks
    float* ms1T_f   = gb + 3416;     // [16][136] tf32 ms1^T, natural order
    float* aeT      = gb + 5592;     // [16][130] pre-LN transpose buffer

    const int br = blockIdx.x;
    const int b = br >> 7, r = br & 127;

    if (tid < 128) {
        int h0 = tid >> 4, e0 = tid & 15;
        w1a_all[tid] = mix1_w[h0 * 32 + e0];
        w1b_all[tid] = mix1_w[h0 * 32 + 16 + e0];
        b1s_all[tid] = mix1_b[tid];
        w2s_all[tid] = mix2_w[tid];
        ews_all[tid] = edge_w[tid];
        costrow[tid] = cost_mat[br * 128 + tid];
        lng[tid] = ln_g[tid];
        lnb[tid] = ln_b[tid];
    }
    if (tid < 8) b2_all[tid] = mix2_b[tid];
    for (int i = c; i < 528; i += 128) edgepart[i] = 0.f;
    __syncthreads();

    for (int hh = 0; hh < 4; ++hh) {
        const int h = grp * 4 + hh;
        float* scrow    = scrow2 + (hh & 1) * 128;
        float* mixedrow = mixed2 + (hh & 1) * 128;

        // ---- P1: waa reload (pre-tf32); ms1 row c -> tiles; mixed; max ----
        waa[(c >> 4) * 20 + (c & 15)] =
            __uint_as_float(tf32r(Waa[h * 256 + c] * L2E));
        waa[((c + 128) >> 4) * 20 + (c & 15)] =
            __uint_as_float(tf32r(Waa[h * 256 + c + 128] * L2E));

        float sc = g_score[((b * KH + h) * KR + r) * KC + c];
        float co = costrow[c];
        scrow[c] = sc;
        float m[16];
        {
            const float4* wa4 = (const float4*)&w1a_all[h * 16];
            const float4* wb4 = (const float4*)&w1b_all[h * 16];
            const float4* bi4 = (const float4*)&b1s_all[h * 16];
#pragma unroll
            for (int j = 0; j < 4; ++j) {
                float4 a = wa4[j], bq = wb4[j], bi = bi4[j];
                m[4*j+0] = fmaxf(fmaf(sc, a.x, fmaf(co, bq.x, bi.x)), 0.f);
                m[4*j+1] = fmaxf(fmaf(sc, a.y, fmaf(co, bq.y, bi.y)), 0.f);
                m[4*j+2] = fmaxf(fmaf(sc, a.z, fmaf(co, bq.z, bi.z)), 0.f);
                m[4*j+3] = fmaxf(fmaf(sc, a.w, fmaf(co, bq.w, bi.w)), 0.f);
            }
        }
        {
            float rm = m[0];
#pragma unroll
            for (int e = 1; e < 16; ++e) rm = fmaxf(rm, m[e]);
#pragma unroll
            for (int o = 16; o; o >>= 1) rm = fmaxf(rm, __shfl_xor_sync(FULLMASK, rm, o));
            if (l == 0) Msm[gw] = rm;
        }
#pragma unroll
        for (int t = 0; t < 4; ++t) {
            float4 ch;
            ch.x = __uint_as_float(tf32r(m[2*t]));
            ch.y = __uint_as_float(tf32r(m[2*t + 1]));
            ch.z = __uint_as_float(tf32r(m[2*t + 8]));
            ch.w = __uint_as_float(tf32r(m[2*t + 9]));
            *(float4*)&ms1r_f[c * 16 + 4 * ((t + (c >> 1)) & 3)] = ch;
        }
#pragma unroll
        for (int e = 0; e < 16; ++e)
            ms1T_f[e * 136 + c] = __uint_as_float(tf32r(m[e]));
        {
            float mx = b2_all[h];
            const float4* w24 = (const float4*)&w2s_all[h * 16];
#pragma unroll
            for (int j = 0; j < 4; ++j) {
                float4 ww = w24[j];
                mx = fmaf(m[4*j],   ww.x, mx); mx = fmaf(m[4*j+1], ww.y, mx);
                mx = fmaf(m[4*j+2], ww.z, mx); mx = fmaf(m[4*j+3], ww.w, mx);
            }
            mixedrow[c] = mx;
        }
        gbar(grp);   // B1

        const float Mmax = fmaxf(fmaxf(Msm[0], Msm[1]), fmaxf(Msm[2], Msm[3]));

        // ---- P2a: t-GEMM for both row-blocks (t stays in registers) ----
        uint32_t wf[8];
        wf[0] = __float_as_uint(waa[(2*tq)   * 20 + g]);
        wf[1] = __float_as_uint(waa[(2*tq+1) * 20 + g]);
        wf[2] = __float_as_uint(waa[(8+2*tq) * 20 + g]);
        wf[3] = __float_as_uint(waa[(9+2*tq) * 20 + g]);
        wf[4] = __float_as_uint(waa[(2*tq)   * 20 + g + 8]);
        wf[5] = __float_as_uint(waa[(2*tq+1) * 20 + g + 8]);
        wf[6] = __float_as_uint(waa[(8+2*tq) * 20 + g + 8]);
        wf[7] = __float_as_uint(waa[(9+2*tq) * 20 + g + 8]);

        float mub[2][2];
        uint32_t daf[2][4], dbf[2][4];
#pragma unroll
        for (int rb = 0; rb < 2; ++rb) {
            const int R = gw * 32 + rb * 16;
            float4 tA = *(const float4*)&ms1r_f[(R + g)     * 16 + rot4];
            float4 tB = *(const float4*)&ms1r_f[(R + g + 8) * 16 + rot4];
            float tc0 = 0.f, tc1 = 0.f, tc2 = 0.f, tc3 = 0.f;
            float tc4 = 0.f, tc5 = 0.f, tc6 = 0.f, tc7 = 0.f;
            uint32_t ax = __float_as_uint(tA.x), bx = __float_as_uint(tB.x);
            uint32_t ay = __float_as_uint(tA.y), by = __float_as_uint(tB.y);
            uint32_t az = __float_as_uint(tA.z), bz = __float_as_uint(tB.z);
            uint32_t aw = __float_as_uint(tA.w), bw = __float_as_uint(tB.w);
            mma8(tc0, tc1, tc2, tc3, ax, bx, ay, by, wf[0], wf[1]);
            mma8(tc0, tc1, tc2, tc3, az, bz, aw, bw, wf[2], wf[3]);
            mma8(tc4, tc5, tc6, tc7, ax, bx, ay, by, wf[4], wf[5]);
            mma8(tc4, tc5, tc6, tc7, az, bz, aw, bw, wf[6], wf[7]);
            float s_g  = fmaxf(tc0, 0.f) + fmaxf(tc1, 0.f)
                       + fmaxf(tc4, 0.f) + fmaxf(tc5, 0.f);
            float s_g8 = fmaxf(tc2, 0.f) + fmaxf(tc3, 0.f)
                       + fmaxf(tc6, 0.f) + fmaxf(tc7, 0.f);
            s_g  += __shfl_xor_sync(FULLMASK, s_g, 1);
            s_g  += __shfl_xor_sync(FULLMASK, s_g, 2);
            s_g8 += __shfl_xor_sync(FULLMASK, s_g8, 1);
            s_g8 += __shfl_xor_sync(FULLMASK, s_g8, 2);
            mub[rb][0] = Mmax * s_g;
            mub[rb][1] = Mmax * s_g8;
            daf[rb][0] = __float_as_uint(tc0); daf[rb][1] = __float_as_uint(tc2);
            daf[rb][2] = __float_as_uint(tc1); daf[rb][3] = __float_as_uint(tc3);
            dbf[rb][0] = __float_as_uint(tc4); dbf[rb][1] = __float_as_uint(tc6);
            dbf[rb][2] = __float_as_uint(tc5); dbf[rb][3] = __float_as_uint(tc7);
        }

        // ---- P2b: per j, one B-load feeds BOTH row-blocks ----
        float sg[2][2] = {{0.f, 0.f}, {0.f, 0.f}};
        float ae0[8], ae1[8];
#pragma unroll
        for (int i = 0; i < 8; ++i) { ae0[i] = 0.f; ae1[i] = 0.f; }

#pragma unroll
        for (int j = 0; j < 16; ++j) {
            float4 bv = *(const float4*)&ms1r_f[(8*j + g) * 16 + rot4];
            float2 e0v = *(const float2*)&ms1T_f[g       * 136 + j*8 + 2*tq];
            float2 e1v = *(const float2*)&ms1T_f[(8 + g) * 136 + j*8 + 2*tq];
            uint32_t bx = __float_as_uint(bv.x), by = __float_as_uint(bv.y);
            uint32_t bz = __float_as_uint(bv.z), bw = __float_as_uint(bv.w);
            uint32_t u0 = __float_as_uint(e0v.x), u1 = __float_as_uint(e0v.y);
            uint32_t u2 = __float_as_uint(e1v.x), u3 = __float_as_uint(e1v.y);
#pragma unroll
            for (int rb = 0; rb < 2; ++rb) {
                float c0 = -mub[rb][0], c1 = -mub[rb][0];
                float c2 = -mub[rb][1], c3 = -mub[rb][1];
                mma8(c0, c1, c2, c3, daf[rb][0], daf[rb][1], daf[rb][2],
                     daf[rb][3], bx, by);
                mma8(c0, c1, c2, c3, dbf[rb][0], dbf[rb][1], dbf[rb][2],
                     dbf[rb][3], bz, bw);
                float p0 = ex2(c0), p1 = ex2(c1), p2 = ex2(c2), p3 = ex2(c3);
                sg[rb][0] += p0 + p1; sg[rb][1] += p2 + p3;
                uint32_t a0 = __float_as_uint(p0);
                uint32_t a1 = __float_as_uint(p2);
                uint32_t a2 = __float_as_uint(p1);
                uint32_t a3 = __float_as_uint(p3);
                float* ae = rb ? ae1 : ae0;
                mma8(ae[0], ae[1], ae[2], ae[3], a0, a1, a2, a3, u0, u1);
                mma8(ae[4], ae[5], ae[6], ae[7], a0, a1, a2, a3, u2, u3);
            }
        }
#pragma unroll
        for (int rb = 0; rb < 2; ++rb) {
            float s0 = sg[rb][0], s1 = sg[rb][1];
            s0 += __shfl_xor_sync(FULLMASK, s0, 1);
            s0 += __shfl_xor_sync(FULLMASK, s0, 2);
            s1 += __shfl_xor_sync(FULLMASK, s1, 1);
            s1 += __shfl_xor_sync(FULLMASK, s1, 2);
            const float inv0 = 1.f / s0, inv1 = 1.f / s1;
            const int R = gw * 32 + rb * 16;
            const float* ae = rb ? ae1 : ae0;
#pragma unroll
            for (int nt = 0; nt < 2; ++nt) {
                aeT[(8*nt + 2*tq)    *130 + R + g]     = ae[nt*4]   * inv0;
                aeT[(8*nt + 2*tq + 1)*130 + R + g]     = ae[nt*4+1] * inv0;
                aeT[(8*nt + 2*tq)    *130 + R + g + 8] = ae[nt*4+2] * inv1;
                aeT[(8*nt + 2*tq + 1)*130 + R + g + 8] = ae[nt*4+3] * inv1;
            }
        }
        gbar(grp);   // B2

        // ---- P3: LayerNorm with edge fused (no post-LN stores) ----
        {
            float eacc[4] = {0.f, 0.f, 0.f, 0.f};
#pragma unroll
            for (int ei = 0; ei < 4; ++ei) {
                int e = gw * 4 + ei;
                float wa = w1a_all[h * 16 + e];
                float wb = w1b_all[h * 16 + e];
                float bi = b1s_all[h * 16 + e];
                float ewv = ews_all[h * 16 + e];
                float x[4];
#pragma unroll
                for (int ki = 0; ki < 4; ++ki) {
                    int cc = l + 32 * ki;
                    float ms = fmaxf(fmaf(scrow[cc], wa,
                                     fmaf(costrow[cc], wb, bi)), 0.f);
                    x[ki] = aeT[e * 130 + cc] + ms;
                }
                float s1v = x[0] + x[1] + x[2] + x[3];
                float sq = x[0]*x[0] + x[1]*x[1] + x[2]*x[2] + x[3]*x[3];
#pragma unroll
                for (int o = 16; o; o >>= 1) {
                    s1v += __shfl_xor_sync(FULLMASK, s1v, o);
                    sq  += __shfl_xor_sync(FULLMASK, sq, o);
                }
                float mean = s1v * (1.f / 128.f);
                float var  = sq * (1.f / 128.f) - mean * mean;
                float rs = rsqrtf(var + 1e-5f);
#pragma unroll
                for (int ki = 0; ki < 4; ++ki) {
                    int cc = l + 32 * ki;
                    float val = (x[ki] - mean) * rs * lng[cc] + lnb[cc];
                    eacc[ki] = fmaf(val, ewv, eacc[ki]);
                }
            }
#pragma unroll
            for (int ki = 0; ki < 4; ++ki)
                edgepart[gw * 132 + l + 32 * ki] += eacc[ki];
        }

        // ---- mixed softmax attention ----
        {
            float m0 = mixedrow[l],      m1 = mixedrow[l + 32];
            float m2 = mixedrow[l + 64], m3 = mixedrow[l + 96];
            float mx = fmaxf(fmaxf(m0, m1), fmaxf(m2, m3));
#pragma unroll
            for (int o = 16; o; o >>= 1) mx = fmaxf(mx, __shfl_xor_sync(FULLMASK, mx, o));
            float p0 = __expf(m0 - mx), p1 = __expf(m1 - mx);
            float p2 = __expf(m2 - mx), p3 = __expf(m3 - mx);
            float ssum = p0 + p1 + p2 + p3;
#pragma unroll
            for (int o = 16; o; o >>= 1) ssum += __shfl_xor_sync(FULLMASK, ssum, o);
            float inv = 1.f / ssum;
            const float* vb = v + (b * KH + h) * KC * KDQ;
#pragma unroll
            for (int d0 = 0; d0 < 4; ++d0) {
                int dq = gw * 4 + d0;
                float a = p0 * vb[l * 16 + dq] + p1 * vb[(l + 32) * 16 + dq]
                        + p2 * vb[(l + 64) * 16 + dq] + p3 * vb[(l + 96) * 16 + dq];
#pragma unroll
                for (int o = 16; o; o >>= 1) a += __shfl_xor_sync(FULLMASK, a, o);
                if (l == 0)
                    out[(b * KR + r) * (KH * KDQ) + h * KDQ + dq] = a * inv;
            }
        }
        // no end-of-head barrier (double-buffered scrow/mixedrow)
    }

    __syncthreads();
    if (tid < 128) {
        float acc = edge_b[0];
        const float* p0 = sm + 1040 + 840;
        const float* p1 = sm + 1040 + 7672 + 840;
#pragma unroll
        for (int gwi = 0; gwi < 4; ++gwi)
            acc += p0[gwi * 132 + tid] + p1[gwi * 132 + tid];
        out[KB * KR * KH * KDQ + br * 128 + tid] = acc;
    }
}

extern "C" void kernel_launch(void* const* d_in, const int* in_sizes, int n_in,
                              void* d_out, int out_size) {
    const float* q    = (const float*)d_in[0];
    const float* k_s  = (const float*)d_in[1];
    const float* k_a  = (const float*)d_in[2];
    const float* v    = (const float*)d_in[3];
    const float* cost = (const float*)d_in[4];
    const float* m1w  = (const float*)d_in[5];
    const float* m1b  = (const float*)d_in[6];
    const float* waa  = (const float*)d_in[7];
    const float* m2w  = (const float*)d_in[8];
    const float* m2b  = (const float*)d_in[9];
    const float* ew   = (const float*)d_in[10];
    const float* eb   = (const float*)d_in[11];
    const float* lng  = (const float*)d_in[12];
    const float* lnb  = (const float*)d_in[13];
    float* out = (float*)d_out;

    cudaFuncSetAttribute(k1_score, cudaFuncAttributeMaxDynamicSharedMemorySize, 111104);
    cudaFuncSetAttribute(k2_main,  cudaFuncAttributeMaxDynamicSharedMemorySize, 65536);

    k1_score<<<KB * KH * 4, 256, 111104>>>(q, k_s, k_a);
    k2_main<<<KB * KR, 256, 65536>>>(cost, m1w, m1b, waa, m2w, m2b, ew, eb,
                                     lng, lnb, v, out);
}